// round 12
// baseline (speedup 1.0000x reference)
#include <cuda_runtime.h>
#include <cuda_fp16.h>
#include <cstdint>
#include <math.h>

// Problem constants
#define NB 16
#define NL 2048
#define ND 1024
#define NE 64

// ---------------- scratch (device globals; no runtime allocation) ----------------
__device__ __half g_selh[(size_t)NB * NL * ND]; // sigmoid(x @ Ws^T + bs)
__device__ float  g_z   [(size_t)NB * NE * NL]; // attention logits (fp32)
__device__ __half g_pa  [(size_t)NB * NE * ND]; // normalized A_fw @ x
__device__ __half g_pb  [(size_t)NB * NE * ND];
__device__ __half g_ca  [(size_t)NB * NE * ND]; // class_a
__device__ __half g_cb  [(size_t)NB * NE * ND]; // class_b
__device__ float  g_afw [NB * NE];
__device__ float  g_bfw [NB * NE];
__device__ float  g_abw [NB * NL];
__device__ float  g_bbw [NB * NL];
__device__ __half g_xh  [(size_t)NB * NL * ND]; // x  (fp16)
__device__ __half g_wh  [(size_t)4 * ND * ND];  // Wk,Wa,Wb,Ws (fp16)
__device__ __half g_qh  [(size_t)NE * ND];      // q_emb (fp16)
__device__ __half g_qwh [(size_t)NE * ND];      // q_emb @ Wk (fp16)
__device__ float  g_qbv [NE];                   // q_emb . bk

// pads (in halves)
#define PADH  72    // [m/n][k] rows, BK=64 halves
#define PADNH 136   // [k][n] rows, 128 n-halves

// ============================================================================
// helpers
// ============================================================================
__device__ __forceinline__ uint32_t smem_u32(const void* p) {
    uint32_t a;
    asm("{ .reg .u64 t; cvta.to.shared.u64 t, %1; cvt.u32.u64 %0, t; }"
        : "=r"(a) : "l"(p));
    return a;
}

__device__ __forceinline__ void cp_async16(uint32_t dst, const void* src) {
    asm volatile("cp.async.cg.shared.global [%0], [%1], 16;" :: "r"(dst), "l"(src));
}

__device__ __forceinline__ void mma_f16(float* d, const uint32_t* a, const uint32_t* b) {
    asm volatile(
        "mma.sync.aligned.m16n8k16.row.col.f32.f16.f16.f32 "
        "{%0,%1,%2,%3}, {%4,%5,%6,%7}, {%8,%9}, {%0,%1,%2,%3};\n"
        : "+f"(d[0]), "+f"(d[1]), "+f"(d[2]), "+f"(d[3])
        : "r"(a[0]), "r"(a[1]), "r"(a[2]), "r"(a[3]), "r"(b[0]), "r"(b[1]));
}

__device__ __forceinline__ void ldmx4(uint32_t& r0, uint32_t& r1, uint32_t& r2,
                                      uint32_t& r3, uint32_t addr) {
    asm volatile("ldmatrix.sync.aligned.m8n8.x4.shared.b16 {%0,%1,%2,%3}, [%4];"
                 : "=r"(r0), "=r"(r1), "=r"(r2), "=r"(r3) : "r"(addr));
}

// dual 16-bit load for [k][n] smem layouts: {B[k][n], B[k+1][n]}
__device__ __forceinline__ uint32_t ldpair(const __half* base, int k, int n, int strideH) {
    uint16_t lo = *(const uint16_t*)(base + (size_t)k * strideH + n);
    uint16_t hi = *(const uint16_t*)(base + (size_t)(k + 1) * strideH + n);
    return (uint32_t)lo | ((uint32_t)hi << 16);
}

// ============================================================================
// Kernel 0: fp32 -> fp16 conversion prepass
// ============================================================================
__global__ __launch_bounds__(256) void k_cvt_h(const float* __restrict__ src,
                                               __half* __restrict__ dst, int n4)
{
    int i = blockIdx.x * 256 + threadIdx.x;
    if (i >= n4) return;
    float4 v = ((const float4*)src)[i];
    __half2 h0 = __floats2half2_rn(v.x, v.y);
    __half2 h1 = __floats2half2_rn(v.z, v.w);
    ((uint2*)dst)[i] = make_uint2(*(uint32_t*)&h0, *(uint32_t*)&h1);
}

__global__ __launch_bounds__(256) void k_cvt4_h(
    const float* __restrict__ w0, const float* __restrict__ w1,
    const float* __restrict__ w2, const float* __restrict__ w3)
{
    const float* srcs[4] = { w0, w1, w2, w3 };
    const float* src = srcs[blockIdx.y];
    __half* dst = g_wh + (size_t)blockIdx.y * ND * ND;
    int i = blockIdx.x * 256 + threadIdx.x;
    float4 v = ((const float4*)src)[i];
    __half2 h0 = __floats2half2_rn(v.x, v.y);
    __half2 h1 = __floats2half2_rn(v.z, v.w);
    ((uint2*)dst)[i] = make_uint2(*(uint32_t*)&h0, *(uint32_t*)&h1);
}

// ============================================================================
// Kernel A: selector GEMM + sigmoid.  g_selh = sigmoid(x @ Ws^T + bs)
// fp16 mma + ldmatrix. CTA 128x128, 8 warps (2x4), warp tile 64x32, BK=64,
// 3-stage ring, 110.6 KB smem => 2 CTAs/SM.
// ============================================================================
#define SG_STG_H ((128 + 128) * PADH)
#define SG_SMEM (3 * SG_STG_H * 2)      // 110,592 B

__global__ __launch_bounds__(256, 2) void k_selgemm(const float* __restrict__ bs)
{
    extern __shared__ __half smh[];

    const int n0 = blockIdx.x * 128;
    const int m0 = blockIdx.y * 128;
    const __half* Wt = g_wh + (size_t)3 * ND * ND;

    const int tid = threadIdx.x;
    const int wid = tid >> 5, lane = tid & 31;
    const int wm = wid >> 2, wn = wid & 3;     // 2 x 4
    const int g = lane >> 2, tg = lane & 3;
    const int lrow = (lane & 7) + ((lane >> 3) & 1) * 8;  // ldmatrix row in 16
    const int lcol = (lane >> 4) * 8;                     // ldmatrix col: 0 / 8

    const uint32_t sb = smem_u32(smh);

    float acc[4][4][4];
    #pragma unroll
    for (int mt = 0; mt < 4; mt++)
        #pragma unroll
        for (int nt = 0; nt < 4; nt++)
            #pragma unroll
            for (int r = 0; r < 4; r++) acc[mt][nt][r] = 0.f;

    const int ldRow = tid >> 3;          // 0..31
    const int ldSeg = tid & 7;

    auto load_chunk = [&](int kc, int st) {
        const uint32_t s0 = sb + (uint32_t)(st * SG_STG_H) * 2u;
        const uint32_t bB = s0 + (uint32_t)(128 * PADH) * 2u;
        const __half* xs = g_xh + (size_t)m0 * 1024 + kc * 64;
        const __half* ws = Wt   + (size_t)n0 * 1024 + kc * 64;
        #pragma unroll
        for (int s = 0; s < 4; ++s) {
            int row = ldRow + s * 32;
            cp_async16(s0 + (uint32_t)(row * (PADH * 2) + ldSeg * 16),
                       xs + (size_t)row * 1024 + ldSeg * 8);
        }
        #pragma unroll
        for (int s = 0; s < 4; ++s) {
            int row = ldRow + s * 32;
            cp_async16(bB + (uint32_t)(row * (PADH * 2) + ldSeg * 16),
                       ws + (size_t)row * 1024 + ldSeg * 8);
        }
        asm volatile("cp.async.commit_group;" ::: "memory");
    };

    load_chunk(0, 0);
    load_chunk(1, 1);

    for (int it = 0; it < 16; ++it) {
        const int st = it % 3;
        if (it < 15) {
            asm volatile("cp.async.wait_group 1;" ::: "memory");
        } else {
            asm volatile("cp.async.wait_group 0;" ::: "memory");
        }
        __syncthreads();

        const uint32_t As_u = sb + (uint32_t)(st * SG_STG_H) * 2u;
        const uint32_t Bs_u = As_u + (uint32_t)(128 * PADH) * 2u;

        #pragma unroll
        for (int ks = 0; ks < 4; ++ks) {
            const int kb = ks * 16;
            uint32_t afr[4][4];
            #pragma unroll
            for (int mt = 0; mt < 4; mt++)
                ldmx4(afr[mt][0], afr[mt][1], afr[mt][2], afr[mt][3],
                      As_u + (uint32_t)((wm * 64 + mt * 16 + lrow) * PADH + kb + lcol) * 2u);
            uint32_t bq[2][4];   // p<2: {b[2p][0], b[2p+1][0], b[2p][1], b[2p+1][1]}
            #pragma unroll
            for (int p = 0; p < 2; p++)
                ldmx4(bq[p][0], bq[p][1], bq[p][2], bq[p][3],
                      Bs_u + (uint32_t)((wn * 32 + p * 16 + lrow) * PADH + kb + lcol) * 2u);
            #pragma unroll
            for (int mt = 0; mt < 4; mt++)
                #pragma unroll
                for (int p = 0; p < 2; p++) {
                    uint32_t b0[2] = { bq[p][0], bq[p][2] };
                    uint32_t b1[2] = { bq[p][1], bq[p][3] };
                    mma_f16(acc[mt][2 * p],     afr[mt], b0);
                    mma_f16(acc[mt][2 * p + 1], afr[mt], b1);
                }
        }

        if (it + 2 < 16) load_chunk(it + 2, (it + 2) % 3);
    }

    const int mBase = m0 + wm * 64;
    const int nBase = n0 + wn * 32;
    #pragma unroll
    for (int mt = 0; mt < 4; mt++) {
        #pragma unroll
        for (int nt = 0; nt < 4; nt++) {
            const int r0 = mBase + mt * 16 + g;
            const int c  = nBase + nt * 8 + 2 * tg;
            float2 bv = *(const float2*)(bs + c);
            float s00 = 1.f / (1.f + expf(-(acc[mt][nt][0] + bv.x)));
            float s01 = 1.f / (1.f + expf(-(acc[mt][nt][1] + bv.y)));
            float s10 = 1.f / (1.f + expf(-(acc[mt][nt][2] + bv.x)));
            float s11 = 1.f / (1.f + expf(-(acc[mt][nt][3] + bv.y)));
            *(__half2*)(g_selh + (size_t)r0 * 1024 + c)       = __floats2half2_rn(s00, s01);
            *(__half2*)(g_selh + (size_t)(r0 + 8) * 1024 + c) = __floats2half2_rn(s10, s11);
        }
    }
}

// ============================================================================
// Kernel B: class projections  g_c{a,b} = P @ W{a,b}^T + S*b{a,b} + b_emb[idx]
// Same ldmatrix 128x128 geometry. grid (8, 8, 2).
// ============================================================================
__global__ __launch_bounds__(256, 2) void k_cproj(
    const int* __restrict__ n_idx, const float* __restrict__ b_emb,
    const float* __restrict__ ba, const float* __restrict__ bb)
{
    extern __shared__ __half smh[];

    const int n0 = blockIdx.x * 128;
    const int m0 = blockIdx.y * 128;
    const int side = blockIdx.z;
    const __half* P   = side ? g_pb  : g_pa;
    const float* sums = side ? g_bfw : g_afw;
    const float* bias = side ? bb    : ba;
    __half*      out  = side ? g_cb  : g_ca;
    const __half* Wt  = g_wh + (size_t)(side ? 2 : 1) * ND * ND;

    const int tid = threadIdx.x;
    const int wid = tid >> 5, lane = tid & 31;
    const int wm = wid >> 2, wn = wid & 3;
    const int g = lane >> 2, tg = lane & 3;
    const int lrow = (lane & 7) + ((lane >> 3) & 1) * 8;
    const int lcol = (lane >> 4) * 8;

    const uint32_t sb = smem_u32(smh);

    float acc[4][4][4];
    #pragma unroll
    for (int mt = 0; mt < 4; mt++)
        #pragma unroll
        for (int nt = 0; nt < 4; nt++)
            #pragma unroll
            for (int r = 0; r < 4; r++) acc[mt][nt][r] = 0.f;

    const int ldRow = tid >> 3;
    const int ldSeg = tid & 7;

    auto load_chunk = [&](int kc, int st) {
        const uint32_t s0 = sb + (uint32_t)(st * SG_STG_H) * 2u;
        const uint32_t bB = s0 + (uint32_t)(128 * PADH) * 2u;
        const __half* xs = P  + (size_t)m0 * 1024 + kc * 64;
        const __half* ws = Wt + (size_t)n0 * 1024 + kc * 64;
        #pragma unroll
        for (int s = 0; s < 4; ++s) {
            int row = ldRow + s * 32;
            cp_async16(s0 + (uint32_t)(row * (PADH * 2) + ldSeg * 16),
                       xs + (size_t)row * 1024 + ldSeg * 8);
        }
        #pragma unroll
        for (int s = 0; s < 4; ++s) {
            int row = ldRow + s * 32;
            cp_async16(bB + (uint32_t)(row * (PADH * 2) + ldSeg * 16),
                       ws + (size_t)row * 1024 + ldSeg * 8);
        }
        asm volatile("cp.async.commit_group;" ::: "memory");
    };

    load_chunk(0, 0);
    load_chunk(1, 1);

    for (int it = 0; it < 16; ++it) {
        const int st = it % 3;
        if (it < 15) {
            asm volatile("cp.async.wait_group 1;" ::: "memory");
        } else {
            asm volatile("cp.async.wait_group 0;" ::: "memory");
        }
        __syncthreads();

        const uint32_t As_u = sb + (uint32_t)(st * SG_STG_H) * 2u;
        const uint32_t Bs_u = As_u + (uint32_t)(128 * PADH) * 2u;

        #pragma unroll
        for (int ks = 0; ks < 4; ++ks) {
            const int kb = ks * 16;
            uint32_t afr[4][4];
            #pragma unroll
            for (int mt = 0; mt < 4; mt++)
                ldmx4(afr[mt][0], afr[mt][1], afr[mt][2], afr[mt][3],
                      As_u + (uint32_t)((wm * 64 + mt * 16 + lrow) * PADH + kb + lcol) * 2u);
            uint32_t bq[2][4];
            #pragma unroll
            for (int p = 0; p < 2; p++)
                ldmx4(bq[p][0], bq[p][1], bq[p][2], bq[p][3],
                      Bs_u + (uint32_t)((wn * 32 + p * 16 + lrow) * PADH + kb + lcol) * 2u);
            #pragma unroll
            for (int mt = 0; mt < 4; mt++)
                #pragma unroll
                for (int p = 0; p < 2; p++) {
                    uint32_t b0[2] = { bq[p][0], bq[p][2] };
                    uint32_t b1[2] = { bq[p][1], bq[p][3] };
                    mma_f16(acc[mt][2 * p],     afr[mt], b0);
                    mma_f16(acc[mt][2 * p + 1], afr[mt], b1);
                }
        }

        if (it + 2 < 16) load_chunk(it + 2, (it + 2) % 3);
    }

    const int mBase = m0 + wm * 64;
    const int nBase = n0 + wn * 32;
    #pragma unroll
    for (int mt = 0; mt < 4; mt++) {
        const int r0 = mBase + mt * 16 + g;
        const int b  = r0 >> 6;
        const int e0 = r0 & 63;
        float s0v = sums[b * 64 + e0];
        float s1v = sums[b * 64 + e0 + 8];
        float S0 = s0v / (s0v + 1e-9f);
        float S1 = s1v / (s1v + 1e-9f);
        const float* br0 = b_emb + (size_t)n_idx[b * 64 + e0] * 1024;
        const float* br1 = b_emb + (size_t)n_idx[b * 64 + e0 + 8] * 1024;
        #pragma unroll
        for (int nt = 0; nt < 4; nt++) {
            const int c = nBase + nt * 8 + 2 * tg;
            float2 bv = *(const float2*)(bias + c);
            float2 e0v = *(const float2*)(br0 + c);
            float2 e1v = *(const float2*)(br1 + c);
            *(__half2*)(out + (size_t)r0 * 1024 + c) = __floats2half2_rn(
                acc[mt][nt][0] + S0 * bv.x + e0v.x,
                acc[mt][nt][1] + S0 * bv.y + e0v.y);
            *(__half2*)(out + (size_t)(r0 + 8) * 1024 + c) = __floats2half2_rn(
                acc[mt][nt][2] + S1 * bv.x + e1v.x,
                acc[mt][nt][3] + S1 * bv.y + e1v.y);
        }
    }
}

// ============================================================================
// Kernel C: qw = q_emb @ Wk  (M=64(e), N=1024(d), K=1024(j)). B=[k][n]. grid(8).
// ============================================================================
#define QW_STG_H (64 * PADH + 64 * PADNH)
#define QW_SMEM (2 * QW_STG_H * 2)

__global__ __launch_bounds__(256) void k_qw()
{
    extern __shared__ __half smh[];
    const int n0 = blockIdx.x * 128;

    const int tid = threadIdx.x;
    const int wid = tid >> 5, lane = tid & 31;
    const int wm = wid >> 2, wn = wid & 3;
    const int g = lane >> 2, tg = lane & 3;

    const uint32_t sb = smem_u32(smh);

    float acc[2][4][4];
    #pragma unroll
    for (int mt = 0; mt < 2; mt++)
        #pragma unroll
        for (int nt = 0; nt < 4; nt++)
            #pragma unroll
            for (int r = 0; r < 4; r++) acc[mt][nt][r] = 0.f;

    const int aRow = tid >> 3;
    const int aSeg = tid & 7;

    auto load_chunk = [&](int kc, int st) {
        const uint32_t s0 = sb + (uint32_t)(st * QW_STG_H) * 2u;
        const uint32_t bB = s0 + (uint32_t)(64 * PADH) * 2u;
        cp_async16(s0 + (uint32_t)(aRow * (PADH * 2) + aSeg * 16),
                   g_qh + (size_t)aRow * 1024 + kc * 64 + aSeg * 8);
        cp_async16(s0 + (uint32_t)((aRow + 32) * (PADH * 2) + aSeg * 16),
                   g_qh + (size_t)(aRow + 32) * 1024 + kc * 64 + aSeg * 8);
        #pragma unroll
        for (int s = 0; s < 4; ++s) {
            int slot = tid + s * 256;
            int row = slot >> 4, seg = slot & 15;
            cp_async16(bB + (uint32_t)(row * (PADNH * 2) + seg * 16),
                       g_wh + (size_t)(kc * 64 + row) * 1024 + n0 + seg * 8);
        }
        asm volatile("cp.async.commit_group;" ::: "memory");
    };

    load_chunk(0, 0);

    for (int it = 0; it < 16; ++it) {
        const int buf = it & 1;
        if (it + 1 < 16) {
            load_chunk(it + 1, buf ^ 1);
            asm volatile("cp.async.wait_group 1;" ::: "memory");
        } else {
            asm volatile("cp.async.wait_group 0;" ::: "memory");
        }
        __syncthreads();

        const __half* As = smh + buf * QW_STG_H;
        const __half* Bs = As + 64 * PADH;

        #pragma unroll
        for (int ks = 0; ks < 4; ++ks) {
            const int kb = ks * 16;
            uint32_t afr[2][4];
            #pragma unroll
            for (int mt = 0; mt < 2; mt++) {
                const __half* ap = As + (wm * 32 + mt * 16 + g) * PADH + kb + 2 * tg;
                afr[mt][0] = *(const uint32_t*)ap;
                afr[mt][1] = *(const uint32_t*)(ap + 8 * PADH);
                afr[mt][2] = *(const uint32_t*)(ap + 8);
                afr[mt][3] = *(const uint32_t*)(ap + 8 * PADH + 8);
            }
            uint32_t bfr[4][2];
            #pragma unroll
            for (int nt = 0; nt < 4; nt++) {
                const int n = wn * 32 + nt * 8 + g;
                bfr[nt][0] = ldpair(Bs, kb + 2 * tg, n, PADNH);
                bfr[nt][1] = ldpair(Bs, kb + 2 * tg + 8, n, PADNH);
            }
            #pragma unroll
            for (int mt = 0; mt < 2; mt++)
                #pragma unroll
                for (int nt = 0; nt < 4; nt++)
                    mma_f16(acc[mt][nt], afr[mt], bfr[nt]);
        }
        __syncthreads();
    }

    #pragma unroll
    for (int mt = 0; mt < 2; mt++) {
        const int e0 = wm * 32 + mt * 16 + g;
        #pragma unroll
        for (int nt = 0; nt < 4; nt++) {
            const int c = n0 + wn * 32 + nt * 8 + 2 * tg;
            *(__half2*)(g_qwh + (size_t)e0 * 1024 + c) =
                __floats2half2_rn(acc[mt][nt][0], acc[mt][nt][1]);
            *(__half2*)(g_qwh + (size_t)(e0 + 8) * 1024 + c) =
                __floats2half2_rn(acc[mt][nt][2], acc[mt][nt][3]);
        }
    }
}

// Kernel C2: qb[e] = q_emb[e] . bk
__global__ void k_qb(const float* __restrict__ q_emb, const float* __restrict__ bk)
{
    int e = threadIdx.x;
    if (e >= 64) return;
    float s = 0.f;
    const float* qr = q_emb + (size_t)e * 1024;
    for (int d = 0; d < 1024; ++d) s += qr[d] * bk[d];
    g_qbv[e] = s;
}

// ============================================================================
// Kernel D: z[b,e,l] = (qwh[idx[b,e]] . xh[b,l] + qb[idx]) / 32
// M=64(e), N=128(l), K=1024(d). A=[m][k], B=x[n=l][k=d] native. BK=64.
// ============================================================================
#define Z_STG_H ((64 + 128) * PADH)
#define Z_SMEM (2 * Z_STG_H * 2)

__global__ __launch_bounds__(256) void k_zgemm(const int* __restrict__ n_idx)
{
    extern __shared__ __half smh[];
    const int b  = blockIdx.y;
    const int l0 = blockIdx.x * 128;
    const int tid = threadIdx.x;
    const int wid = tid >> 5, lane = tid & 31;
    const int wm = wid >> 2, wn = wid & 3;
    const int g = lane >> 2, tg = lane & 3;

    const uint32_t sb = smem_u32(smh);

    float acc[2][4][4];
    #pragma unroll
    for (int mt = 0; mt < 2; mt++)
        #pragma unroll
        for (int nt = 0; nt < 4; nt++)
            #pragma unroll
            for (int r = 0; r < 4; r++) acc[mt][nt][r] = 0.f;

    const int aRow = tid >> 3;
    const int aSeg = tid & 7;
    const __half* aSrc0 = g_qwh + (size_t)n_idx[b * 64 + aRow] * 1024;
    const __half* aSrc1 = g_qwh + (size_t)n_idx[b * 64 + aRow + 32] * 1024;

    auto load_chunk = [&](int kc, int st) {
        const uint32_t s0 = sb + (uint32_t)(st * Z_STG_H) * 2u;
        const uint32_t bB = s0 + (uint32_t)(64 * PADH) * 2u;
        cp_async16(s0 + (uint32_t)(aRow * (PADH * 2) + aSeg * 16), aSrc0 + kc * 64 + aSeg * 8);
        cp_async16(s0 + (uint32_t)((aRow + 32) * (PADH * 2) + aSeg * 16), aSrc1 + kc * 64 + aSeg * 8);
        const __half* xs = g_xh + ((size_t)b * 2048 + l0) * 1024 + kc * 64;
        #pragma unroll
        for (int s = 0; s < 4; ++s) {
            int row = aRow + s * 32;
            cp_async16(bB + (uint32_t)(row * (PADH * 2) + aSeg * 16),
                       xs + (size_t)row * 1024 + aSeg * 8);
        }
        asm volatile("cp.async.commit_group;" ::: "memory");
    };

    load_chunk(0, 0);

    for (int it = 0; it < 16; ++it) {
        const int buf = it & 1;
        if (it + 1 < 16) {
            load_chunk(it + 1, buf ^ 1);
            asm volatile("cp.async.wait_group 1;" ::: "memory");
        } else {
            asm volatile("cp.async.wait_group 0;" ::: "memory");
        }
        __syncthreads();

        const __half* As = smh + buf * Z_STG_H;
        const __half* Bs = As + 64 * PADH;

        #pragma unroll
        for (int ks = 0; ks < 4; ++ks) {
            const int kb = ks * 16;
            uint32_t afr[2][4];
            #pragma unroll
            for (int mt = 0; mt < 2; mt++) {
                const __half* ap = As + (wm * 32 + mt * 16 + g) * PADH + kb + 2 * tg;
                afr[mt][0] = *(const uint32_t*)ap;
                afr[mt][1] = *(const uint32_t*)(ap + 8 * PADH);
                afr[mt][2] = *(const uint32_t*)(ap + 8);
                afr[mt][3] = *(const uint32_t*)(ap + 8 * PADH + 8);
            }
            uint32_t bfr[4][2];
            #pragma unroll
            for (int nt = 0; nt < 4; nt++) {
                const __half* bp = Bs + (wn * 32 + nt * 8 + g) * PADH + kb + 2 * tg;
                bfr[nt][0] = *(const uint32_t*)bp;
                bfr[nt][1] = *(const uint32_t*)(bp + 8);
            }
            #pragma unroll
            for (int mt = 0; mt < 2; mt++)
                #pragma unroll
                for (int nt = 0; nt < 4; nt++)
                    mma_f16(acc[mt][nt], afr[mt], bfr[nt]);
        }
        __syncthreads();
    }

    #pragma unroll
    for (int mt = 0; mt < 2; mt++) {
        #pragma unroll
        for (int nt = 0; nt < 4; nt++) {
            const int e = wm * 32 + mt * 16 + g;
            const float qb0 = g_qbv[n_idx[b * 64 + e]];
            const float qb1 = g_qbv[n_idx[b * 64 + e + 8]];
            const int l = l0 + wn * 32 + nt * 8 + 2 * tg;
            float* zr0 = g_z + ((size_t)b * 64 + e) * 2048 + l;
            float* zr1 = g_z + ((size_t)b * 64 + e + 8) * 2048 + l;
            *(float2*)zr0 = make_float2((acc[mt][nt][0] + qb0) * 0.03125f,
                                        (acc[mt][nt][1] + qb0) * 0.03125f);
            *(float2*)zr1 = make_float2((acc[mt][nt][2] + qb1) * 0.03125f,
                                        (acc[mt][nt][3] + qb1) * 0.03125f);
        }
    }
}

// ============================================================================
// Kernel 3/4: reduction sums
// ============================================================================
__global__ __launch_bounds__(256) void k_fwsums(const int* __restrict__ mask)
{
    const int be = blockIdx.x;
    const int b = be >> 6;
    const float* zr = g_z + (size_t)be * 2048;
    const int* mrow = mask + b * 2048;

    float sa = 0.f, sb = 0.f;
    for (int l = threadIdx.x; l < 2048; l += 256) {
        float v = zr[l];
        if (mrow[l] != 0) { sa += fmaxf(v, 0.f); sb += fmaxf(-v, 0.f); }
    }
    #pragma unroll
    for (int off = 16; off > 0; off >>= 1) {
        sa += __shfl_down_sync(0xffffffffu, sa, off);
        sb += __shfl_down_sync(0xffffffffu, sb, off);
    }
    __shared__ float ra[8], rb[8];
    int wrp = threadIdx.x >> 5, lane = threadIdx.x & 31;
    if (lane == 0) { ra[wrp] = sa; rb[wrp] = sb; }
    __syncthreads();
    if (threadIdx.x == 0) {
        float ta = 0.f, tb = 0.f;
        #pragma unroll
        for (int i = 0; i < 8; i++) { ta += ra[i]; tb += rb[i]; }
        g_afw[be] = ta; g_bfw[be] = tb;
    }
}

__global__ __launch_bounds__(256) void k_bwsums()
{
    const int idx = blockIdx.x * 256 + threadIdx.x;
    const int b = idx >> 11;
    const float* zp = g_z + (size_t)b * 64 * 2048 + (idx & 2047);
    float sa = 0.f, sb = 0.f;
    #pragma unroll 8
    for (int e = 0; e < 64; e++) {
        float v = zp[(size_t)e * 2048];
        sa += fmaxf(v, 0.f);
        sb += fmaxf(-v, 0.f);
    }
    g_abw[idx] = sa;
    g_bbw[idx] = sb;
}

// ============================================================================
// Kernel E: merged P GEMM. g_p{a,b}[b,e,d] = (A_{a,b} @ x)*inv   (fp16)
// M=64(e), N=128(d), K=2048(l), BK=64. A built from z; B = xh [k][n] dual-16.
// ============================================================================
#define PG_STG_H (2 * 64 * PADH + 64 * PADNH)
#define PG_SMEM (2 * PG_STG_H * 2)

__global__ __launch_bounds__(256) void k_pgemm2(const int* __restrict__ mask)
{
    extern __shared__ __half smh[];
    const int b  = blockIdx.y;
    const int n0 = blockIdx.x * 128;

    const int tid = threadIdx.x;
    const int wid = tid >> 5, lane = tid & 31;
    const int wm = wid >> 2, wn = wid & 3;
    const int g = lane >> 2, tg = lane & 3;

    const uint32_t sb = smem_u32(smh);

    float accA[2][4][4], accB[2][4][4];
    #pragma unroll
    for (int mt = 0; mt < 2; mt++)
        #pragma unroll
        for (int nt = 0; nt < 4; nt++)
            #pragma unroll
            for (int r = 0; r < 4; r++) { accA[mt][nt][r] = 0.f; accB[mt][nt][r] = 0.f; }

    const int aE = tid >> 2;
    const int aC = (tid & 3) * 16;
    const float* zrow = g_z + ((size_t)b * 64 + aE) * 2048;
    const int* mrow = mask + b * 2048;

    auto load_chunk = [&](int kc, int st) {
        __half* Aa = smh + st * PG_STG_H;
        __half* Ab = Aa + 64 * PADH;
        const uint32_t bB = sb + (uint32_t)(st * PG_STG_H + 2 * 64 * PADH) * 2u;
        const int kk = kc * 64;
        __half ha[16], hb[16];
        #pragma unroll
        for (int q = 0; q < 4; ++q) {
            float4 v = *(const float4*)(zrow + kk + aC + q * 4);
            int4 m = *(const int4*)(mrow + kk + aC + q * 4);
            float vv[4] = { v.x, v.y, v.z, v.w };
            int   mm[4] = { m.x, m.y, m.z, m.w };
            #pragma unroll
            for (int j = 0; j < 4; ++j) {
                ha[q * 4 + j] = __float2half_rn(mm[j] ? fmaxf(vv[j], 0.f) : 0.f);
                hb[q * 4 + j] = __float2half_rn(mm[j] ? fmaxf(-vv[j], 0.f) : 0.f);
            }
        }
        *(uint4*)(Aa + aE * PADH + aC)     = *(uint4*)ha;
        *(uint4*)(Aa + aE * PADH + aC + 8) = *(uint4*)(ha + 8);
        *(uint4*)(Ab + aE * PADH + aC)     = *(uint4*)hb;
        *(uint4*)(Ab + aE * PADH + aC + 8) = *(uint4*)(hb + 8);
        const __half* xs = g_xh + ((size_t)b * 2048 + kk) * 1024 + n0;
        #pragma unroll
        for (int s = 0; s < 4; ++s) {
            int slot = tid + s * 256;
            int row = slot >> 4, seg = slot & 15;
            cp_async16(bB + (uint32_t)(row * (PADNH * 2) + seg * 16),
                       xs + (size_t)row * 1024 + seg * 8);
        }
        asm volatile("cp.async.commit_group;" ::: "memory");
    };

    load_chunk(0, 0);

    for (int it = 0; it < 32; ++it) {
        const int buf = it & 1;
        if (it + 1 < 32) {
            load_chunk(it + 1, buf ^ 1);
            asm volatile("cp.async.wait_group 1;" ::: "memory");
        } else {
            asm volatile("cp.async.wait_group 0;" ::: "memory");
        }
        __syncthreads();

        const __half* Aa = smh + buf * PG_STG_H;
        const __half* Ab = Aa + 64 * PADH;
        const __half* Bs = Ab + 64 * PADH;

        #pragma unroll
        for (int ks = 0; ks < 4; ++ks) {
            const int kb = ks * 16;
            uint32_t afa[2][4], afb[2][4];
            #pragma unroll
            for (int mt = 0; mt < 2; mt++) {
                const __half* pa = Aa + (wm * 32 + mt * 16 + g) * PADH + kb + 2 * tg;
                const __half* pb = Ab + (wm * 32 + mt * 16 + g) * PADH + kb + 2 * tg;
                afa[mt][0] = *(const uint32_t*)pa;
                afa[mt][1] = *(const uint32_t*)(pa + 8 * PADH);
                afa[mt][2] = *(const uint32_t*)(pa + 8);
                afa[mt][3] = *(const uint32_t*)(pa + 8 * PADH + 8);
                afb[mt][0] = *(const uint32_t*)pb;
                afb[mt][1] = *(const uint32_t*)(pb + 8 * PADH);
                afb[mt][2] = *(const uint32_t*)(pb + 8);
                afb[mt][3] = *(const uint32_t*)(pb + 8 * PADH + 8);
            }
            uint32_t bfr[4][2];
            #pragma unroll
            for (int nt = 0; nt < 4; nt++) {
                const int n = wn * 32 + nt * 8 + g;
                bfr[nt][0] = ldpair(Bs, kb + 2 * tg, n, PADNH);
                bfr[nt][1] = ldpair(Bs, kb + 2 * tg + 8, n, PADNH);
            }
            #pragma unroll
            for (int mt = 0; mt < 2; mt++)
                #pragma unroll
                for (int nt = 0; nt < 4; nt++) {
                    mma_f16(accA[mt][nt], afa[mt], bfr[nt]);
                    mma_f16(accB[mt][nt], afb[mt], bfr[nt]);
                }
        }
        __syncthreads();
    }

    #pragma unroll
    for (int mt = 0; mt < 2; mt++) {
        const int e0 = wm * 32 + mt * 16 + g;
        const float ia0 = 1.f / (g_afw[b * 64 + e0] + 1e-9f);
        const float ia1 = 1.f / (g_afw[b * 64 + e0 + 8] + 1e-9f);
        const float ib0 = 1.f / (g_bfw[b * 64 + e0] + 1e-9f);
        const float ib1 = 1.f / (g_bfw[b * 64 + e0 + 8] + 1e-9f);
        #pragma unroll
        for (int nt = 0; nt < 4; nt++) {
            const int d = n0 + wn * 32 + nt * 8 + 2 * tg;
            *(__half2*)(g_pa + ((size_t)b * 64 + e0) * 1024 + d) =
                __floats2half2_rn(accA[mt][nt][0] * ia0, accA[mt][nt][1] * ia0);
            *(__half2*)(g_pa + ((size_t)b * 64 + e0 + 8) * 1024 + d) =
                __floats2half2_rn(accA[mt][nt][2] * ia1, accA[mt][nt][3] * ia1);
            *(__half2*)(g_pb + ((size_t)b * 64 + e0) * 1024 + d) =
                __floats2half2_rn(accB[mt][nt][0] * ib0, accB[mt][nt][1] * ib0);
            *(__half2*)(g_pb + ((size_t)b * 64 + e0 + 8) * 1024 + d) =
                __floats2half2_rn(accB[mt][nt][2] * ib1, accB[mt][nt][3] * ib1);
        }
    }
}

// ============================================================================
// Kernel 6: final mix (fp16 mma). M=64(l), N=128(d), K=64(e). Single shot.
// ============================================================================
#define FN_SMEM ((2 * 64 * PADH + 2 * 64 * PADNH) * 2)

__global__ __launch_bounds__(256) void k_final(float* __restrict__ out)
{
    extern __shared__ __half smh[];
    __half* Aa = smh;
    __half* Ab = Aa + 64 * PADH;
    __half* Ba = Ab + 64 * PADH;
    __half* Bb = Ba + 64 * PADNH;

    const int b  = blockIdx.z;
    const int l0 = blockIdx.y * 64;
    const int d0 = blockIdx.x * 128;
    const int tid = threadIdx.x;
    const int wid = tid >> 5, lane = tid & 31;
    const int wm = wid >> 2, wn = wid & 3;
    const int g = lane >> 2, tg = lane & 3;

    {
        const int e  = tid & 63;
        const int lc = (tid >> 6) * 16;
        const float* zp = g_z + ((size_t)b * 64 + e) * 2048 + l0 + lc;
        #pragma unroll
        for (int j = 0; j < 4; ++j) {
            float4 v = *(const float4*)(zp + j * 4);
            float vv[4] = { v.x, v.y, v.z, v.w };
            #pragma unroll
            for (int t = 0; t < 4; ++t) {
                int l = lc + j * 4 + t;
                Aa[l * PADH + e] = __float2half_rn(fmaxf(vv[t], 0.f));
                Ab[l * PADH + e] = __float2half_rn(fmaxf(-vv[t], 0.f));
            }
        }
    }
    {
        const uint32_t baU = smem_u32(Ba);
        const uint32_t bbU = smem_u32(Bb);
        const __half* caP = g_ca + ((size_t)b * 64) * 1024 + d0;
        const __half* cbP = g_cb + ((size_t)b * 64) * 1024 + d0;
        #pragma unroll
        for (int s = 0; s < 4; ++s) {
            int slot = tid + s * 256;
            int row = slot >> 4, seg = slot & 15;
            uint32_t doff = (uint32_t)(row * (PADNH * 2) + seg * 16);
            cp_async16(baU + doff, caP + (size_t)row * 1024 + seg * 8);
            cp_async16(bbU + doff, cbP + (size_t)row * 1024 + seg * 8);
        }
        asm volatile("cp.async.commit_group;" ::: "memory");
        asm volatile("cp.async.wait_group 0;" ::: "memory");
    }
    __syncthreads();

    float aca[2][4][4], acb[2][4][4];
    #pragma unroll
    for (int mt = 0; mt < 2; mt++)
        #pragma unroll
        for (int nt = 0; nt < 4; nt++)
            #pragma unroll
            for (int r = 0; r < 4; r++) { aca[mt][nt][r] = 0.f; acb[mt][nt][r] = 0.f; }

    #pragma unroll
    for (int ks = 0; ks < 4; ++ks) {
        const int kb = ks * 16;
        uint32_t afa[2][4], afb[2][4];
        #pragma unroll
        for (int mt = 0; mt < 2; mt++) {
            const __half* pa = Aa + (wm * 32 + mt * 16 + g) * PADH + kb + 2 * tg;
            const __half* pb = Ab + (wm * 32 + mt * 16 + g) * PADH + kb + 2 * tg;
            afa[mt][0] = *(const uint32_t*)pa;
            afa[mt][1] = *(const uint32_t*)(pa + 8 * PADH);
            afa[mt][2] = *(const uint32_t*)(pa + 8);
            afa[mt][3] = *(const uint32_t*)(pa + 8 * PADH + 8);
            afb[mt][0] = *(const uint32_t*)pb;
            afb[mt][1] = *(const uint32_t*)(pb + 8 * PADH);
            afb[mt][2] = *(const uint32_t*)(pb + 8);
            afb[mt][3] = *(const uint32_t*)(pb + 8 * PADH + 8);
        }
        uint32_t bfa[4][2], bfb[4][2];
        #pragma unroll
        for (int nt = 0; nt < 4; nt++) {
            const int n = wn * 32 + nt * 8 + g;
            bfa[nt][0] = ldpair(Ba, kb + 2 * tg, n, PADNH);
            bfa[nt][1] = ldpair(Ba, kb + 2 * tg + 8, n, PADNH);
            bfb[nt][0] = ldpair(Bb, kb + 2 * tg, n, PADNH);
            bfb[nt][1] = ldpair(Bb, kb + 2 * tg + 8, n, PADNH);
        }
        #pragma unroll
        for (int mt = 0; mt < 2; mt++)
            #pragma unroll
            for (int nt = 0; nt < 4; nt++) {
                mma_f16(aca[mt][nt], afa[mt], bfa[nt]);
                mma_f16(acb[mt][nt], afb[mt], bfb[nt]);
            }
    }

    #pragma unroll
    for (int mt = 0; mt < 2; mt++) {
        const int l0r = l0 + wm * 32 + mt * 16 + g;
        const float ia0 = 1.f / (g_abw[b * 2048 + l0r] + 1e-9f);
        const float ib0 = 1.f / (g_bbw[b * 2048 + l0r] + 1e-9f);
        const float ia1 = 1.f / (g_abw[b * 2048 + l0r + 8] + 1e-9f);
        const float ib1 = 1.f / (g_bbw[b * 2048 + l0r + 8] + 1e-9f);
        #pragma unroll
        for (int nt = 0; nt < 4; nt++) {
            const int d = d0 + wn * 32 + nt * 8 + 2 * tg;
            float2 sg0 = __half22float2(*(const __half2*)(g_selh + ((size_t)b * 2048 + l0r) * 1024 + d));
            float2 sg1 = __half22float2(*(const __half2*)(g_selh + ((size_t)b * 2048 + l0r + 8) * 1024 + d));
            float2 o0 = make_float2(
                sg0.x * (aca[mt][nt][0] * ia0) + (1.f - sg0.x) * (acb[mt][nt][0] * ib0),
                sg0.y * (aca[mt][nt][1] * ia0) + (1.f - sg0.y) * (acb[mt][nt][1] * ib0));
            float2 o1 = make_float2(
                sg1.x * (aca[mt][nt][2] * ia1) + (1.f - sg1.x) * (acb[mt][nt][2] * ib1),
                sg1.y * (aca[mt][nt][3] * ia1) + (1.f - sg1.y) * (acb[mt][nt][3] * ib1));
            *(float2*)(out + ((size_t)b * 2048 + l0r) * 1024 + d)     = o0;
            *(float2*)(out + ((size_t)b * 2048 + l0r + 8) * 1024 + d) = o1;
        }
    }
}

// ============================================================================
extern "C" void kernel_launch(void* const* d_in, const int* in_sizes, int n_in,
                              void* d_out, int out_size)
{
    const float* x     = (const float*)d_in[0];
    const int*   n_idx = (const int*)  d_in[1];
    const int*   mask  = (const int*)  d_in[2];
    const float* q_emb = (const float*)d_in[3];
    const float* b_emb = (const float*)d_in[4];
    const float* Wk    = (const float*)d_in[5];
    const float* bk    = (const float*)d_in[6];
    const float* Wa    = (const float*)d_in[7];
    const float* ba    = (const float*)d_in[8];
    const float* Wb    = (const float*)d_in[9];
    const float* bb    = (const float*)d_in[10];
    const float* Ws    = (const float*)d_in[11];
    const float* bs    = (const float*)d_in[12];
    float* out = (float*)d_out;

    __half *xh_p, *qh_p;
    cudaGetSymbolAddress((void**)&xh_p, g_xh);
    cudaGetSymbolAddress((void**)&qh_p, g_qh);

    cudaFuncSetAttribute(k_selgemm, cudaFuncAttributeMaxDynamicSharedMemorySize, SG_SMEM);
    cudaFuncSetAttribute(k_cproj,   cudaFuncAttributeMaxDynamicSharedMemorySize, SG_SMEM);
    cudaFuncSetAttribute(k_qw,      cudaFuncAttributeMaxDynamicSharedMemorySize, QW_SMEM);
    cudaFuncSetAttribute(k_zgemm,   cudaFuncAttributeMaxDynamicSharedMemorySize, Z_SMEM);
    cudaFuncSetAttribute(k_pgemm2,  cudaFuncAttributeMaxDynamicSharedMemorySize, PG_SMEM);
    cudaFuncSetAttribute(k_final,   cudaFuncAttributeMaxDynamicSharedMemorySize, FN_SMEM);

    // prepass; selgemm at the launch slot ncu profiles
    k_cvt_h <<<(NB * NL * ND / 4 + 255) / 256, 256>>>(x, xh_p, NB * NL * ND / 4);
    k_cvt4_h<<<dim3(ND * ND / 4 / 256, 4),     256>>>(Wk, Wa, Wb, Ws);
    k_cvt_h <<<(NE * ND / 4 + 255) / 256,      256>>>(q_emb, qh_p, NE * ND / 4);

    k_selgemm<<<dim3(8, 256),    256, SG_SMEM>>>(bs);
    k_qw     <<<8,               256, QW_SMEM>>>();
    k_qb     <<<1,               64>>>(q_emb, bk);
    k_zgemm  <<<dim3(16, 16),    256, Z_SMEM>>>(n_idx);
    k_fwsums <<<NB * NE,         256>>>(mask);
    k_bwsums <<<(NB * NL) / 256, 256>>>();
    k_pgemm2 <<<dim3(8, 16),     256, PG_SMEM>>>(mask);
    k_cproj  <<<dim3(8, 8, 2),   256, SG_SMEM>>>(n_idx, b_emb, ba, bb);
    k_final  <<<dim3(8, 32, 16), 256, FN_SMEM>>>(out);
}

// round 13
// speedup vs baseline: 1.0601x; 1.0601x over previous
#include <cuda_runtime.h>
#include <cuda_fp16.h>
#include <cstdint>
#include <math.h>

// Problem constants
#define NB 16
#define NL 2048
#define ND 1024
#define NE 64

// ---------------- scratch (device globals; no runtime allocation) ----------------
__device__ __half g_selh[(size_t)NB * NL * ND]; // sigmoid(x @ Ws^T + bs)
__device__ float  g_z   [(size_t)NB * NE * NL]; // attention logits (fp32)
__device__ __half g_pa  [(size_t)NB * NE * ND]; // normalized A_fw @ x
__device__ __half g_pb  [(size_t)NB * NE * ND];
__device__ __half g_ca  [(size_t)NB * NE * ND]; // class_a
__device__ __half g_cb  [(size_t)NB * NE * ND]; // class_b
__device__ float  g_afw [NB * NE];
__device__ float  g_bfw [NB * NE];
__device__ float  g_abw [NB * NL];
__device__ float  g_bbw [NB * NL];
__device__ __half g_xh  [(size_t)NB * NL * ND]; // x  (fp16)
__device__ __half g_wh  [(size_t)4 * ND * ND];  // Wk,Wa,Wb,Ws (fp16)
__device__ __half g_qh  [(size_t)NE * ND];      // q_emb (fp16)
__device__ __half g_qwh [(size_t)NE * ND];      // q_emb @ Wk (fp16)
__device__ float  g_qbv [NE];                   // q_emb . bk

// pads (in halves)
#define PADH  72    // [m/n][k] rows, BK=64 halves
#define PADNH 136   // [k][n] rows, 128 n-halves

// ============================================================================
// helpers
// ============================================================================
__device__ __forceinline__ uint32_t smem_u32(const void* p) {
    uint32_t a;
    asm("{ .reg .u64 t; cvta.to.shared.u64 t, %1; cvt.u32.u64 %0, t; }"
        : "=r"(a) : "l"(p));
    return a;
}

__device__ __forceinline__ void cp_async16(uint32_t dst, const void* src) {
    asm volatile("cp.async.cg.shared.global [%0], [%1], 16;" :: "r"(dst), "l"(src));
}

__device__ __forceinline__ void mma_f16(float* d, const uint32_t* a, const uint32_t* b) {
    asm volatile(
        "mma.sync.aligned.m16n8k16.row.col.f32.f16.f16.f32 "
        "{%0,%1,%2,%3}, {%4,%5,%6,%7}, {%8,%9}, {%0,%1,%2,%3};\n"
        : "+f"(d[0]), "+f"(d[1]), "+f"(d[2]), "+f"(d[3])
        : "r"(a[0]), "r"(a[1]), "r"(a[2]), "r"(a[3]), "r"(b[0]), "r"(b[1]));
}

// dual 16-bit load for [k][n] smem layouts: {B[k][n], B[k+1][n]}
__device__ __forceinline__ uint32_t ldpair(const __half* base, int k, int n, int strideH) {
    uint16_t lo = *(const uint16_t*)(base + (size_t)k * strideH + n);
    uint16_t hi = *(const uint16_t*)(base + (size_t)(k + 1) * strideH + n);
    return (uint32_t)lo | ((uint32_t)hi << 16);
}

// ============================================================================
// Kernel 0: fp32 -> fp16 conversion prepass
// ============================================================================
__global__ __launch_bounds__(256) void k_cvt_h(const float* __restrict__ src,
                                               __half* __restrict__ dst, int n4)
{
    int i = blockIdx.x * 256 + threadIdx.x;
    if (i >= n4) return;
    float4 v = ((const float4*)src)[i];
    __half2 h0 = __floats2half2_rn(v.x, v.y);
    __half2 h1 = __floats2half2_rn(v.z, v.w);
    ((uint2*)dst)[i] = make_uint2(*(uint32_t*)&h0, *(uint32_t*)&h1);
}

__global__ __launch_bounds__(256) void k_cvt4_h(
    const float* __restrict__ w0, const float* __restrict__ w1,
    const float* __restrict__ w2, const float* __restrict__ w3)
{
    const float* srcs[4] = { w0, w1, w2, w3 };
    const float* src = srcs[blockIdx.y];
    __half* dst = g_wh + (size_t)blockIdx.y * ND * ND;
    int i = blockIdx.x * 256 + threadIdx.x;
    float4 v = ((const float4*)src)[i];
    __half2 h0 = __floats2half2_rn(v.x, v.y);
    __half2 h1 = __floats2half2_rn(v.z, v.w);
    ((uint2*)dst)[i] = make_uint2(*(uint32_t*)&h0, *(uint32_t*)&h1);
}

// ============================================================================
// Kernel A: selector GEMM + sigmoid.  g_selh = sigmoid(x @ Ws^T + bs)
// fp16 mma. CTA 128x128, 8 warps (2x4), warp tile 64x32, BK=64 halves,
// 3-stage ring, 110.6 KB smem => 2 CTAs/SM (R11-proven config).
// ============================================================================
#define SG_STG_H ((128 + 128) * PADH)
#define SG_SMEM (3 * SG_STG_H * 2)      // 110,592 B

__global__ __launch_bounds__(256, 2) void k_selgemm(const float* __restrict__ bs)
{
    extern __shared__ __half smh[];

    const int n0 = blockIdx.x * 128;
    const int m0 = blockIdx.y * 128;
    const __half* Wt = g_wh + (size_t)3 * ND * ND;

    const int tid = threadIdx.x;
    const int wid = tid >> 5, lane = tid & 31;
    const int wm = wid >> 2, wn = wid & 3;     // 2 x 4
    const int g = lane >> 2, tg = lane & 3;

    const uint32_t sb = smem_u32(smh);

    float acc[4][4][4];
    #pragma unroll
    for (int mt = 0; mt < 4; mt++)
        #pragma unroll
        for (int nt = 0; nt < 4; nt++)
            #pragma unroll
            for (int r = 0; r < 4; r++) acc[mt][nt][r] = 0.f;

    const int ldRow = tid >> 3;          // 0..31
    const int ldSeg = tid & 7;

    auto load_chunk = [&](int kc, int st) {
        const uint32_t s0 = sb + (uint32_t)(st * SG_STG_H) * 2u;
        const uint32_t bB = s0 + (uint32_t)(128 * PADH) * 2u;
        const __half* xs = g_xh + (size_t)m0 * 1024 + kc * 64;
        const __half* ws = Wt   + (size_t)n0 * 1024 + kc * 64;
        #pragma unroll
        for (int s = 0; s < 4; ++s) {
            int row = ldRow + s * 32;
            cp_async16(s0 + (uint32_t)(row * (PADH * 2) + ldSeg * 16),
                       xs + (size_t)row * 1024 + ldSeg * 8);
        }
        #pragma unroll
        for (int s = 0; s < 4; ++s) {
            int row = ldRow + s * 32;
            cp_async16(bB + (uint32_t)(row * (PADH * 2) + ldSeg * 16),
                       ws + (size_t)row * 1024 + ldSeg * 8);
        }
        asm volatile("cp.async.commit_group;" ::: "memory");
    };

    load_chunk(0, 0);
    load_chunk(1, 1);

    for (int it = 0; it < 16; ++it) {
        const int st = it % 3;
        if (it < 15) {
            asm volatile("cp.async.wait_group 1;" ::: "memory");
        } else {
            asm volatile("cp.async.wait_group 0;" ::: "memory");
        }
        __syncthreads();

        const __half* As = smh + st * SG_STG_H;
        const __half* Bs = As + 128 * PADH;

        #pragma unroll
        for (int ks = 0; ks < 4; ++ks) {
            const int kb = ks * 16;
            uint32_t afr[4][4];
            #pragma unroll
            for (int mt = 0; mt < 4; mt++) {
                const __half* ap = As + (wm * 64 + mt * 16 + g) * PADH + kb + 2 * tg;
                afr[mt][0] = *(const uint32_t*)ap;
                afr[mt][1] = *(const uint32_t*)(ap + 8 * PADH);
                afr[mt][2] = *(const uint32_t*)(ap + 8);
                afr[mt][3] = *(const uint32_t*)(ap + 8 * PADH + 8);
            }
            uint32_t bfr[4][2];
            #pragma unroll
            for (int nt = 0; nt < 4; nt++) {
                const __half* bp = Bs + (wn * 32 + nt * 8 + g) * PADH + kb + 2 * tg;
                bfr[nt][0] = *(const uint32_t*)bp;
                bfr[nt][1] = *(const uint32_t*)(bp + 8);
            }
            #pragma unroll
            for (int mt = 0; mt < 4; mt++)
                #pragma unroll
                for (int nt = 0; nt < 4; nt++)
                    mma_f16(acc[mt][nt], afr[mt], bfr[nt]);
        }

        if (it + 2 < 16) load_chunk(it + 2, (it + 2) % 3);
    }

    const int mBase = m0 + wm * 64;
    const int nBase = n0 + wn * 32;
    #pragma unroll
    for (int mt = 0; mt < 4; mt++) {
        #pragma unroll
        for (int nt = 0; nt < 4; nt++) {
            const int r0 = mBase + mt * 16 + g;
            const int c  = nBase + nt * 8 + 2 * tg;
            float2 bv = *(const float2*)(bs + c);
            float s00 = 1.f / (1.f + expf(-(acc[mt][nt][0] + bv.x)));
            float s01 = 1.f / (1.f + expf(-(acc[mt][nt][1] + bv.y)));
            float s10 = 1.f / (1.f + expf(-(acc[mt][nt][2] + bv.x)));
            float s11 = 1.f / (1.f + expf(-(acc[mt][nt][3] + bv.y)));
            *(__half2*)(g_selh + (size_t)r0 * 1024 + c)       = __floats2half2_rn(s00, s01);
            *(__half2*)(g_selh + (size_t)(r0 + 8) * 1024 + c) = __floats2half2_rn(s10, s11);
        }
    }
}

// ============================================================================
// Kernel B: class projections  g_c{a,b} = P @ W{a,b}^T + S*b{a,b} + b_emb[idx]
// Same 128x128 geometry (R11). grid (8, 8, 2).
// ============================================================================
__global__ __launch_bounds__(256, 2) void k_cproj(
    const int* __restrict__ n_idx, const float* __restrict__ b_emb,
    const float* __restrict__ ba, const float* __restrict__ bb)
{
    extern __shared__ __half smh[];

    const int n0 = blockIdx.x * 128;
    const int m0 = blockIdx.y * 128;
    const int side = blockIdx.z;
    const __half* P   = side ? g_pb  : g_pa;
    const float* sums = side ? g_bfw : g_afw;
    const float* bias = side ? bb    : ba;
    __half*      out  = side ? g_cb  : g_ca;
    const __half* Wt  = g_wh + (size_t)(side ? 2 : 1) * ND * ND;

    const int tid = threadIdx.x;
    const int wid = tid >> 5, lane = tid & 31;
    const int wm = wid >> 2, wn = wid & 3;
    const int g = lane >> 2, tg = lane & 3;

    float acc[4][4][4];
    #pragma unroll
    for (int mt = 0; mt < 4; mt++)
        #pragma unroll
        for (int nt = 0; nt < 4; nt++)
            #pragma unroll
            for (int r = 0; r < 4; r++) acc[mt][nt][r] = 0.f;

    const uint32_t sb = smem_u32(smh);
    const int ldRow = tid >> 3;
    const int ldSeg = tid & 7;

    auto load_chunk = [&](int kc, int st) {
        const uint32_t s0 = sb + (uint32_t)(st * SG_STG_H) * 2u;
        const uint32_t bB = s0 + (uint32_t)(128 * PADH) * 2u;
        const __half* xs = P  + (size_t)m0 * 1024 + kc * 64;
        const __half* ws = Wt + (size_t)n0 * 1024 + kc * 64;
        #pragma unroll
        for (int s = 0; s < 4; ++s) {
            int row = ldRow + s * 32;
            cp_async16(s0 + (uint32_t)(row * (PADH * 2) + ldSeg * 16),
                       xs + (size_t)row * 1024 + ldSeg * 8);
        }
        #pragma unroll
        for (int s = 0; s < 4; ++s) {
            int row = ldRow + s * 32;
            cp_async16(bB + (uint32_t)(row * (PADH * 2) + ldSeg * 16),
                       ws + (size_t)row * 1024 + ldSeg * 8);
        }
        asm volatile("cp.async.commit_group;" ::: "memory");
    };

    load_chunk(0, 0);
    load_chunk(1, 1);

    for (int it = 0; it < 16; ++it) {
        const int st = it % 3;
        if (it < 15) {
            asm volatile("cp.async.wait_group 1;" ::: "memory");
        } else {
            asm volatile("cp.async.wait_group 0;" ::: "memory");
        }
        __syncthreads();

        const __half* As = smh + st * SG_STG_H;
        const __half* Bs = As + 128 * PADH;

        #pragma unroll
        for (int ks = 0; ks < 4; ++ks) {
            const int kb = ks * 16;
            uint32_t afr[4][4];
            #pragma unroll
            for (int mt = 0; mt < 4; mt++) {
                const __half* ap = As + (wm * 64 + mt * 16 + g) * PADH + kb + 2 * tg;
                afr[mt][0] = *(const uint32_t*)ap;
                afr[mt][1] = *(const uint32_t*)(ap + 8 * PADH);
                afr[mt][2] = *(const uint32_t*)(ap + 8);
                afr[mt][3] = *(const uint32_t*)(ap + 8 * PADH + 8);
            }
            uint32_t bfr[4][2];
            #pragma unroll
            for (int nt = 0; nt < 4; nt++) {
                const __half* bp = Bs + (wn * 32 + nt * 8 + g) * PADH + kb + 2 * tg;
                bfr[nt][0] = *(const uint32_t*)bp;
                bfr[nt][1] = *(const uint32_t*)(bp + 8);
            }
            #pragma unroll
            for (int mt = 0; mt < 4; mt++)
                #pragma unroll
                for (int nt = 0; nt < 4; nt++)
                    mma_f16(acc[mt][nt], afr[mt], bfr[nt]);
        }

        if (it + 2 < 16) load_chunk(it + 2, (it + 2) % 3);
    }

    const int mBase = m0 + wm * 64;
    const int nBase = n0 + wn * 32;
    #pragma unroll
    for (int mt = 0; mt < 4; mt++) {
        const int r0 = mBase + mt * 16 + g;
        const int b  = r0 >> 6;
        const int e0 = r0 & 63;
        float s0v = sums[b * 64 + e0];
        float s1v = sums[b * 64 + e0 + 8];
        float S0 = s0v / (s0v + 1e-9f);
        float S1 = s1v / (s1v + 1e-9f);
        const float* br0 = b_emb + (size_t)n_idx[b * 64 + e0] * 1024;
        const float* br1 = b_emb + (size_t)n_idx[b * 64 + e0 + 8] * 1024;
        #pragma unroll
        for (int nt = 0; nt < 4; nt++) {
            const int c = nBase + nt * 8 + 2 * tg;
            float2 bv = *(const float2*)(bias + c);
            float2 e0v = *(const float2*)(br0 + c);
            float2 e1v = *(const float2*)(br1 + c);
            *(__half2*)(out + (size_t)r0 * 1024 + c) = __floats2half2_rn(
                acc[mt][nt][0] + S0 * bv.x + e0v.x,
                acc[mt][nt][1] + S0 * bv.y + e0v.y);
            *(__half2*)(out + (size_t)(r0 + 8) * 1024 + c) = __floats2half2_rn(
                acc[mt][nt][2] + S1 * bv.x + e1v.x,
                acc[mt][nt][3] + S1 * bv.y + e1v.y);
        }
    }
}

// ============================================================================
// Kernel C: qw = q_emb @ Wk  (M=64(e), N=1024(d), K=1024(j)). B=[k][n]. grid(8).
// ============================================================================
#define QW_STG_H (64 * PADH + 64 * PADNH)
#define QW_SMEM (2 * QW_STG_H * 2)

__global__ __launch_bounds__(256) void k_qw()
{
    extern __shared__ __half smh[];
    const int n0 = blockIdx.x * 128;

    const int tid = threadIdx.x;
    const int wid = tid >> 5, lane = tid & 31;
    const int wm = wid >> 2, wn = wid & 3;
    const int g = lane >> 2, tg = lane & 3;

    const uint32_t sb = smem_u32(smh);

    float acc[2][4][4];
    #pragma unroll
    for (int mt = 0; mt < 2; mt++)
        #pragma unroll
        for (int nt = 0; nt < 4; nt++)
            #pragma unroll
            for (int r = 0; r < 4; r++) acc[mt][nt][r] = 0.f;

    const int aRow = tid >> 3;
    const int aSeg = tid & 7;

    auto load_chunk = [&](int kc, int st) {
        const uint32_t s0 = sb + (uint32_t)(st * QW_STG_H) * 2u;
        const uint32_t bB = s0 + (uint32_t)(64 * PADH) * 2u;
        cp_async16(s0 + (uint32_t)(aRow * (PADH * 2) + aSeg * 16),
                   g_qh + (size_t)aRow * 1024 + kc * 64 + aSeg * 8);
        cp_async16(s0 + (uint32_t)((aRow + 32) * (PADH * 2) + aSeg * 16),
                   g_qh + (size_t)(aRow + 32) * 1024 + kc * 64 + aSeg * 8);
        #pragma unroll
        for (int s = 0; s < 4; ++s) {
            int slot = tid + s * 256;
            int row = slot >> 4, seg = slot & 15;
            cp_async16(bB + (uint32_t)(row * (PADNH * 2) + seg * 16),
                       g_wh + (size_t)(kc * 64 + row) * 1024 + n0 + seg * 8);
        }
        asm volatile("cp.async.commit_group;" ::: "memory");
    };

    load_chunk(0, 0);

    for (int it = 0; it < 16; ++it) {
        const int buf = it & 1;
        if (it + 1 < 16) {
            load_chunk(it + 1, buf ^ 1);
            asm volatile("cp.async.wait_group 1;" ::: "memory");
        } else {
            asm volatile("cp.async.wait_group 0;" ::: "memory");
        }
        __syncthreads();

        const __half* As = smh + buf * QW_STG_H;
        const __half* Bs = As + 64 * PADH;

        #pragma unroll
        for (int ks = 0; ks < 4; ++ks) {
            const int kb = ks * 16;
            uint32_t afr[2][4];
            #pragma unroll
            for (int mt = 0; mt < 2; mt++) {
                const __half* ap = As + (wm * 32 + mt * 16 + g) * PADH + kb + 2 * tg;
                afr[mt][0] = *(const uint32_t*)ap;
                afr[mt][1] = *(const uint32_t*)(ap + 8 * PADH);
                afr[mt][2] = *(const uint32_t*)(ap + 8);
                afr[mt][3] = *(const uint32_t*)(ap + 8 * PADH + 8);
            }
            uint32_t bfr[4][2];
            #pragma unroll
            for (int nt = 0; nt < 4; nt++) {
                const int n = wn * 32 + nt * 8 + g;
                bfr[nt][0] = ldpair(Bs, kb + 2 * tg, n, PADNH);
                bfr[nt][1] = ldpair(Bs, kb + 2 * tg + 8, n, PADNH);
            }
            #pragma unroll
            for (int mt = 0; mt < 2; mt++)
                #pragma unroll
                for (int nt = 0; nt < 4; nt++)
                    mma_f16(acc[mt][nt], afr[mt], bfr[nt]);
        }
        __syncthreads();
    }

    #pragma unroll
    for (int mt = 0; mt < 2; mt++) {
        const int e0 = wm * 32 + mt * 16 + g;
        #pragma unroll
        for (int nt = 0; nt < 4; nt++) {
            const int c = n0 + wn * 32 + nt * 8 + 2 * tg;
            *(__half2*)(g_qwh + (size_t)e0 * 1024 + c) =
                __floats2half2_rn(acc[mt][nt][0], acc[mt][nt][1]);
            *(__half2*)(g_qwh + (size_t)(e0 + 8) * 1024 + c) =
                __floats2half2_rn(acc[mt][nt][2], acc[mt][nt][3]);
        }
    }
}

// Kernel C2: qb[e] = q_emb[e] . bk
__global__ void k_qb(const float* __restrict__ q_emb, const float* __restrict__ bk)
{
    int e = threadIdx.x;
    if (e >= 64) return;
    float s = 0.f;
    const float* qr = q_emb + (size_t)e * 1024;
    for (int d = 0; d < 1024; ++d) s += qr[d] * bk[d];
    g_qbv[e] = s;
}

// ============================================================================
// Kernel D: z[b,e,l] = (qwh[idx[b,e]] . xh[b,l] + qb[idx]) / 32
// M=64(e), N=128(l), K=1024(d). A=[m][k], B=x[n=l][k=d] native. BK=64.
// ============================================================================
#define Z_STG_H ((64 + 128) * PADH)
#define Z_SMEM (2 * Z_STG_H * 2)

__global__ __launch_bounds__(256) void k_zgemm(const int* __restrict__ n_idx)
{
    extern __shared__ __half smh[];
    const int b  = blockIdx.y;
    const int l0 = blockIdx.x * 128;
    const int tid = threadIdx.x;
    const int wid = tid >> 5, lane = tid & 31;
    const int wm = wid >> 2, wn = wid & 3;
    const int g = lane >> 2, tg = lane & 3;

    const uint32_t sb = smem_u32(smh);

    float acc[2][4][4];
    #pragma unroll
    for (int mt = 0; mt < 2; mt++)
        #pragma unroll
        for (int nt = 0; nt < 4; nt++)
            #pragma unroll
            for (int r = 0; r < 4; r++) acc[mt][nt][r] = 0.f;

    const int aRow = tid >> 3;
    const int aSeg = tid & 7;
    const __half* aSrc0 = g_qwh + (size_t)n_idx[b * 64 + aRow] * 1024;
    const __half* aSrc1 = g_qwh + (size_t)n_idx[b * 64 + aRow + 32] * 1024;

    auto load_chunk = [&](int kc, int st) {
        const uint32_t s0 = sb + (uint32_t)(st * Z_STG_H) * 2u;
        const uint32_t bB = s0 + (uint32_t)(64 * PADH) * 2u;
        cp_async16(s0 + (uint32_t)(aRow * (PADH * 2) + aSeg * 16), aSrc0 + kc * 64 + aSeg * 8);
        cp_async16(s0 + (uint32_t)((aRow + 32) * (PADH * 2) + aSeg * 16), aSrc1 + kc * 64 + aSeg * 8);
        const __half* xs = g_xh + ((size_t)b * 2048 + l0) * 1024 + kc * 64;
        #pragma unroll
        for (int s = 0; s < 4; ++s) {
            int row = aRow + s * 32;
            cp_async16(bB + (uint32_t)(row * (PADH * 2) + aSeg * 16),
                       xs + (size_t)row * 1024 + aSeg * 8);
        }
        asm volatile("cp.async.commit_group;" ::: "memory");
    };

    load_chunk(0, 0);

    for (int it = 0; it < 16; ++it) {
        const int buf = it & 1;
        if (it + 1 < 16) {
            load_chunk(it + 1, buf ^ 1);
            asm volatile("cp.async.wait_group 1;" ::: "memory");
        } else {
            asm volatile("cp.async.wait_group 0;" ::: "memory");
        }
        __syncthreads();

        const __half* As = smh + buf * Z_STG_H;
        const __half* Bs = As + 64 * PADH;

        #pragma unroll
        for (int ks = 0; ks < 4; ++ks) {
            const int kb = ks * 16;
            uint32_t afr[2][4];
            #pragma unroll
            for (int mt = 0; mt < 2; mt++) {
                const __half* ap = As + (wm * 32 + mt * 16 + g) * PADH + kb + 2 * tg;
                afr[mt][0] = *(const uint32_t*)ap;
                afr[mt][1] = *(const uint32_t*)(ap + 8 * PADH);
                afr[mt][2] = *(const uint32_t*)(ap + 8);
                afr[mt][3] = *(const uint32_t*)(ap + 8 * PADH + 8);
            }
            uint32_t bfr[4][2];
            #pragma unroll
            for (int nt = 0; nt < 4; nt++) {
                const __half* bp = Bs + (wn * 32 + nt * 8 + g) * PADH + kb + 2 * tg;
                bfr[nt][0] = *(const uint32_t*)bp;
                bfr[nt][1] = *(const uint32_t*)(bp + 8);
            }
            #pragma unroll
            for (int mt = 0; mt < 2; mt++)
                #pragma unroll
                for (int nt = 0; nt < 4; nt++)
                    mma_f16(acc[mt][nt], afr[mt], bfr[nt]);
        }
        __syncthreads();
    }

    #pragma unroll
    for (int mt = 0; mt < 2; mt++) {
        #pragma unroll
        for (int nt = 0; nt < 4; nt++) {
            const int e = wm * 32 + mt * 16 + g;
            const float qb0 = g_qbv[n_idx[b * 64 + e]];
            const float qb1 = g_qbv[n_idx[b * 64 + e + 8]];
            const int l = l0 + wn * 32 + nt * 8 + 2 * tg;
            float* zr0 = g_z + ((size_t)b * 64 + e) * 2048 + l;
            float* zr1 = g_z + ((size_t)b * 64 + e + 8) * 2048 + l;
            *(float2*)zr0 = make_float2((acc[mt][nt][0] + qb0) * 0.03125f,
                                        (acc[mt][nt][1] + qb0) * 0.03125f);
            *(float2*)zr1 = make_float2((acc[mt][nt][2] + qb1) * 0.03125f,
                                        (acc[mt][nt][3] + qb1) * 0.03125f);
        }
    }
}

// ============================================================================
// Kernel 3/4: reduction sums
// ============================================================================
__global__ __launch_bounds__(256) void k_fwsums(const int* __restrict__ mask)
{
    const int be = blockIdx.x;
    const int b = be >> 6;
    const float* zr = g_z + (size_t)be * 2048;
    const int* mrow = mask + b * 2048;

    float sa = 0.f, sb = 0.f;
    for (int l = threadIdx.x; l < 2048; l += 256) {
        float v = zr[l];
        if (mrow[l] != 0) { sa += fmaxf(v, 0.f); sb += fmaxf(-v, 0.f); }
    }
    #pragma unroll
    for (int off = 16; off > 0; off >>= 1) {
        sa += __shfl_down_sync(0xffffffffu, sa, off);
        sb += __shfl_down_sync(0xffffffffu, sb, off);
    }
    __shared__ float ra[8], rb[8];
    int wrp = threadIdx.x >> 5, lane = threadIdx.x & 31;
    if (lane == 0) { ra[wrp] = sa; rb[wrp] = sb; }
    __syncthreads();
    if (threadIdx.x == 0) {
        float ta = 0.f, tb = 0.f;
        #pragma unroll
        for (int i = 0; i < 8; i++) { ta += ra[i]; tb += rb[i]; }
        g_afw[be] = ta; g_bfw[be] = tb;
    }
}

__global__ __launch_bounds__(256) void k_bwsums()
{
    const int idx = blockIdx.x * 256 + threadIdx.x;
    const int b = idx >> 11;
    const float* zp = g_z + (size_t)b * 64 * 2048 + (idx & 2047);
    float sa = 0.f, sb = 0.f;
    #pragma unroll 8
    for (int e = 0; e < 64; e++) {
        float v = zp[(size_t)e * 2048];
        sa += fmaxf(v, 0.f);
        sb += fmaxf(-v, 0.f);
    }
    g_abw[idx] = sa;
    g_bbw[idx] = sb;
}

// ============================================================================
// Kernel E: merged P GEMM. g_p{a,b}[b,e,d] = (A_{a,b} @ x)*inv   (fp16)
// M=64(e), N=128(d), K=2048(l), BK=64. A built from z; B = xh [k][n] dual-16.
// ============================================================================
#define PG_STG_H (2 * 64 * PADH + 64 * PADNH)
#define PG_SMEM (2 * PG_STG_H * 2)

__global__ __launch_bounds__(256) void k_pgemm2(const int* __restrict__ mask)
{
    extern __shared__ __half smh[];
    const int b  = blockIdx.y;
    const int n0 = blockIdx.x * 128;

    const int tid = threadIdx.x;
    const int wid = tid >> 5, lane = tid & 31;
    const int wm = wid >> 2, wn = wid & 3;
    const int g = lane >> 2, tg = lane & 3;

    const uint32_t sb = smem_u32(smh);

    float accA[2][4][4], accB[2][4][4];
    #pragma unroll
    for (int mt = 0; mt < 2; mt++)
        #pragma unroll
        for (int nt = 0; nt < 4; nt++)
            #pragma unroll
            for (int r = 0; r < 4; r++) { accA[mt][nt][r] = 0.f; accB[mt][nt][r] = 0.f; }

    const int aE = tid >> 2;
    const int aC = (tid & 3) * 16;
    const float* zrow = g_z + ((size_t)b * 64 + aE) * 2048;
    const int* mrow = mask + b * 2048;

    auto load_chunk = [&](int kc, int st) {
        __half* Aa = smh + st * PG_STG_H;
        __half* Ab = Aa + 64 * PADH;
        const uint32_t bB = sb + (uint32_t)(st * PG_STG_H + 2 * 64 * PADH) * 2u;
        const int kk = kc * 64;
        __half ha[16], hb[16];
        #pragma unroll
        for (int q = 0; q < 4; ++q) {
            float4 v = *(const float4*)(zrow + kk + aC + q * 4);
            int4 m = *(const int4*)(mrow + kk + aC + q * 4);
            float vv[4] = { v.x, v.y, v.z, v.w };
            int   mm[4] = { m.x, m.y, m.z, m.w };
            #pragma unroll
            for (int j = 0; j < 4; ++j) {
                ha[q * 4 + j] = __float2half_rn(mm[j] ? fmaxf(vv[j], 0.f) : 0.f);
                hb[q * 4 + j] = __float2half_rn(mm[j] ? fmaxf(-vv[j], 0.f) : 0.f);
            }
        }
        *(uint4*)(Aa + aE * PADH + aC)     = *(uint4*)ha;
        *(uint4*)(Aa + aE * PADH + aC + 8) = *(uint4*)(ha + 8);
        *(uint4*)(Ab + aE * PADH + aC)     = *(uint4*)hb;
        *(uint4*)(Ab + aE * PADH + aC + 8) = *(uint4*)(hb + 8);
        const __half* xs = g_xh + ((size_t)b * 2048 + kk) * 1024 + n0;
        #pragma unroll
        for (int s = 0; s < 4; ++s) {
            int slot = tid + s * 256;
            int row = slot >> 4, seg = slot & 15;
            cp_async16(bB + (uint32_t)(row * (PADNH * 2) + seg * 16),
                       xs + (size_t)row * 1024 + seg * 8);
        }
        asm volatile("cp.async.commit_group;" ::: "memory");
    };

    load_chunk(0, 0);

    for (int it = 0; it < 32; ++it) {
        const int buf = it & 1;
        if (it + 1 < 32) {
            load_chunk(it + 1, buf ^ 1);
            asm volatile("cp.async.wait_group 1;" ::: "memory");
        } else {
            asm volatile("cp.async.wait_group 0;" ::: "memory");
        }
        __syncthreads();

        const __half* Aa = smh + buf * PG_STG_H;
        const __half* Ab = Aa + 64 * PADH;
        const __half* Bs = Ab + 64 * PADH;

        #pragma unroll
        for (int ks = 0; ks < 4; ++ks) {
            const int kb = ks * 16;
            uint32_t afa[2][4], afb[2][4];
            #pragma unroll
            for (int mt = 0; mt < 2; mt++) {
                const __half* pa = Aa + (wm * 32 + mt * 16 + g) * PADH + kb + 2 * tg;
                const __half* pb = Ab + (wm * 32 + mt * 16 + g) * PADH + kb + 2 * tg;
                afa[mt][0] = *(const uint32_t*)pa;
                afa[mt][1] = *(const uint32_t*)(pa + 8 * PADH);
                afa[mt][2] = *(const uint32_t*)(pa + 8);
                afa[mt][3] = *(const uint32_t*)(pa + 8 * PADH + 8);
                afb[mt][0] = *(const uint32_t*)pb;
                afb[mt][1] = *(const uint32_t*)(pb + 8 * PADH);
                afb[mt][2] = *(const uint32_t*)(pb + 8);
                afb[mt][3] = *(const uint32_t*)(pb + 8 * PADH + 8);
            }
            uint32_t bfr[4][2];
            #pragma unroll
            for (int nt = 0; nt < 4; nt++) {
                const int n = wn * 32 + nt * 8 + g;
                bfr[nt][0] = ldpair(Bs, kb + 2 * tg, n, PADNH);
                bfr[nt][1] = ldpair(Bs, kb + 2 * tg + 8, n, PADNH);
            }
            #pragma unroll
            for (int mt = 0; mt < 2; mt++)
                #pragma unroll
                for (int nt = 0; nt < 4; nt++) {
                    mma_f16(accA[mt][nt], afa[mt], bfr[nt]);
                    mma_f16(accB[mt][nt], afb[mt], bfr[nt]);
                }
        }
        __syncthreads();
    }

    #pragma unroll
    for (int mt = 0; mt < 2; mt++) {
        const int e0 = wm * 32 + mt * 16 + g;
        const float ia0 = 1.f / (g_afw[b * 64 + e0] + 1e-9f);
        const float ia1 = 1.f / (g_afw[b * 64 + e0 + 8] + 1e-9f);
        const float ib0 = 1.f / (g_bfw[b * 64 + e0] + 1e-9f);
        const float ib1 = 1.f / (g_bfw[b * 64 + e0 + 8] + 1e-9f);
        #pragma unroll
        for (int nt = 0; nt < 4; nt++) {
            const int d = n0 + wn * 32 + nt * 8 + 2 * tg;
            *(__half2*)(g_pa + ((size_t)b * 64 + e0) * 1024 + d) =
                __floats2half2_rn(accA[mt][nt][0] * ia0, accA[mt][nt][1] * ia0);
            *(__half2*)(g_pa + ((size_t)b * 64 + e0 + 8) * 1024 + d) =
                __floats2half2_rn(accA[mt][nt][2] * ia1, accA[mt][nt][3] * ia1);
            *(__half2*)(g_pb + ((size_t)b * 64 + e0) * 1024 + d) =
                __floats2half2_rn(accB[mt][nt][0] * ib0, accB[mt][nt][1] * ib0);
            *(__half2*)(g_pb + ((size_t)b * 64 + e0 + 8) * 1024 + d) =
                __floats2half2_rn(accB[mt][nt][2] * ib1, accB[mt][nt][3] * ib1);
        }
    }
}

// ============================================================================
// Kernel 6: final mix (fp16 mma). M=64(l), N=128(d), K=64(e). Single shot.
// ============================================================================
#define FN_SMEM ((2 * 64 * PADH + 2 * 64 * PADNH) * 2)

__global__ __launch_bounds__(256) void k_final(float* __restrict__ out)
{
    extern __shared__ __half smh[];
    __half* Aa = smh;
    __half* Ab = Aa + 64 * PADH;
    __half* Ba = Ab + 64 * PADH;
    __half* Bb = Ba + 64 * PADNH;

    const int b  = blockIdx.z;
    const int l0 = blockIdx.y * 64;
    const int d0 = blockIdx.x * 128;
    const int tid = threadIdx.x;
    const int wid = tid >> 5, lane = tid & 31;
    const int wm = wid >> 2, wn = wid & 3;
    const int g = lane >> 2, tg = lane & 3;

    {
        const int e  = tid & 63;
        const int lc = (tid >> 6) * 16;
        const float* zp = g_z + ((size_t)b * 64 + e) * 2048 + l0 + lc;
        #pragma unroll
        for (int j = 0; j < 4; ++j) {
            float4 v = *(const float4*)(zp + j * 4);
            float vv[4] = { v.x, v.y, v.z, v.w };
            #pragma unroll
            for (int t = 0; t < 4; ++t) {
                int l = lc + j * 4 + t;
                Aa[l * PADH + e] = __float2half_rn(fmaxf(vv[t], 0.f));
                Ab[l * PADH + e] = __float2half_rn(fmaxf(-vv[t], 0.f));
            }
        }
    }
    {
        const uint32_t baU = smem_u32(Ba);
        const uint32_t bbU = smem_u32(Bb);
        const __half* caP = g_ca + ((size_t)b * 64) * 1024 + d0;
        const __half* cbP = g_cb + ((size_t)b * 64) * 1024 + d0;
        #pragma unroll
        for (int s = 0; s < 4; ++s) {
            int slot = tid + s * 256;
            int row = slot >> 4, seg = slot & 15;
            uint32_t doff = (uint32_t)(row * (PADNH * 2) + seg * 16);
            cp_async16(baU + doff, caP + (size_t)row * 1024 + seg * 8);
            cp_async16(bbU + doff, cbP + (size_t)row * 1024 + seg * 8);
        }
        asm volatile("cp.async.commit_group;" ::: "memory");
        asm volatile("cp.async.wait_group 0;" ::: "memory");
    }
    __syncthreads();

    float aca[2][4][4], acb[2][4][4];
    #pragma unroll
    for (int mt = 0; mt < 2; mt++)
        #pragma unroll
        for (int nt = 0; nt < 4; nt++)
            #pragma unroll
            for (int r = 0; r < 4; r++) { aca[mt][nt][r] = 0.f; acb[mt][nt][r] = 0.f; }

    #pragma unroll
    for (int ks = 0; ks < 4; ++ks) {
        const int kb = ks * 16;
        uint32_t afa[2][4], afb[2][4];
        #pragma unroll
        for (int mt = 0; mt < 2; mt++) {
            const __half* pa = Aa + (wm * 32 + mt * 16 + g) * PADH + kb + 2 * tg;
            const __half* pb = Ab + (wm * 32 + mt * 16 + g) * PADH + kb + 2 * tg;
            afa[mt][0] = *(const uint32_t*)pa;
            afa[mt][1] = *(const uint32_t*)(pa + 8 * PADH);
            afa[mt][2] = *(const uint32_t*)(pa + 8);
            afa[mt][3] = *(const uint32_t*)(pa + 8 * PADH + 8);
            afb[mt][0] = *(const uint32_t*)pb;
            afb[mt][1] = *(const uint32_t*)(pb + 8 * PADH);
            afb[mt][2] = *(const uint32_t*)(pb + 8);
            afb[mt][3] = *(const uint32_t*)(pb + 8 * PADH + 8);
        }
        uint32_t bfa[4][2], bfb[4][2];
        #pragma unroll
        for (int nt = 0; nt < 4; nt++) {
            const int n = wn * 32 + nt * 8 + g;
            bfa[nt][0] = ldpair(Ba, kb + 2 * tg, n, PADNH);
            bfa[nt][1] = ldpair(Ba, kb + 2 * tg + 8, n, PADNH);
            bfb[nt][0] = ldpair(Bb, kb + 2 * tg, n, PADNH);
            bfb[nt][1] = ldpair(Bb, kb + 2 * tg + 8, n, PADNH);
        }
        #pragma unroll
        for (int mt = 0; mt < 2; mt++)
            #pragma unroll
            for (int nt = 0; nt < 4; nt++) {
                mma_f16(aca[mt][nt], afa[mt], bfa[nt]);
                mma_f16(acb[mt][nt], afb[mt], bfb[nt]);
            }
    }

    #pragma unroll
    for (int mt = 0; mt < 2; mt++) {
        const int l0r = l0 + wm * 32 + mt * 16 + g;
        const float ia0 = 1.f / (g_abw[b * 2048 + l0r] + 1e-9f);
        const float ib0 = 1.f / (g_bbw[b * 2048 + l0r] + 1e-9f);
        const float ia1 = 1.f / (g_abw[b * 2048 + l0r + 8] + 1e-9f);
        const float ib1 = 1.f / (g_bbw[b * 2048 + l0r + 8] + 1e-9f);
        #pragma unroll
        for (int nt = 0; nt < 4; nt++) {
            const int d = d0 + wn * 32 + nt * 8 + 2 * tg;
            float2 sg0 = __half22float2(*(const __half2*)(g_selh + ((size_t)b * 2048 + l0r) * 1024 + d));
            float2 sg1 = __half22float2(*(const __half2*)(g_selh + ((size_t)b * 2048 + l0r + 8) * 1024 + d));
            float2 o0 = make_float2(
                sg0.x * (aca[mt][nt][0] * ia0) + (1.f - sg0.x) * (acb[mt][nt][0] * ib0),
                sg0.y * (aca[mt][nt][1] * ia0) + (1.f - sg0.y) * (acb[mt][nt][1] * ib0));
            float2 o1 = make_float2(
                sg1.x * (aca[mt][nt][2] * ia1) + (1.f - sg1.x) * (acb[mt][nt][2] * ib1),
                sg1.y * (aca[mt][nt][3] * ia1) + (1.f - sg1.y) * (acb[mt][nt][3] * ib1));
            *(float2*)(out + ((size_t)b * 2048 + l0r) * 1024 + d)     = o0;
            *(float2*)(out + ((size_t)b * 2048 + l0r + 8) * 1024 + d) = o1;
        }
    }
}

// ============================================================================
extern "C" void kernel_launch(void* const* d_in, const int* in_sizes, int n_in,
                              void* d_out, int out_size)
{
    const float* x     = (const float*)d_in[0];
    const int*   n_idx = (const int*)  d_in[1];
    const int*   mask  = (const int*)  d_in[2];
    const float* q_emb = (const float*)d_in[3];
    const float* b_emb = (const float*)d_in[4];
    const float* Wk    = (const float*)d_in[5];
    const float* bk    = (const float*)d_in[6];
    const float* Wa    = (const float*)d_in[7];
    const float* ba    = (const float*)d_in[8];
    const float* Wb    = (const float*)d_in[9];
    const float* bb    = (const float*)d_in[10];
    const float* Ws    = (const float*)d_in[11];
    const float* bs    = (const float*)d_in[12];
    float* out = (float*)d_out;

    __half *xh_p, *qh_p;
    cudaGetSymbolAddress((void**)&xh_p, g_xh);
    cudaGetSymbolAddress((void**)&qh_p, g_qh);

    cudaFuncSetAttribute(k_selgemm, cudaFuncAttributeMaxDynamicSharedMemorySize, SG_SMEM);
    cudaFuncSetAttribute(k_cproj,   cudaFuncAttributeMaxDynamicSharedMemorySize, SG_SMEM);
    cudaFuncSetAttribute(k_qw,      cudaFuncAttributeMaxDynamicSharedMemorySize, QW_SMEM);
    cudaFuncSetAttribute(k_zgemm,   cudaFuncAttributeMaxDynamicSharedMemorySize, Z_SMEM);
    cudaFuncSetAttribute(k_pgemm2,  cudaFuncAttributeMaxDynamicSharedMemorySize, PG_SMEM);
    cudaFuncSetAttribute(k_final,   cudaFuncAttributeMaxDynamicSharedMemorySize, FN_SMEM);

    // side stream + events (created once; per-call GPU work is identical)
    static cudaStream_t s2 = nullptr;
    static cudaEvent_t evFork = nullptr, evSel = nullptr;
    if (s2 == nullptr) {
        cudaStreamCreateWithFlags(&s2, cudaStreamNonBlocking);
        cudaEventCreateWithFlags(&evFork, cudaEventDisableTiming);
        cudaEventCreateWithFlags(&evSel, cudaEventDisableTiming);
    }

    // prepass on main (capture) stream
    k_cvt_h <<<(NB * NL * ND / 4 + 255) / 256, 256>>>(x, xh_p, NB * NL * ND / 4);
    k_cvt4_h<<<dim3(ND * ND / 4 / 256, 4),     256>>>(Wk, Wa, Wb, Ws);
    k_cvt_h <<<(NE * ND / 4 + 255) / 256,      256>>>(q_emb, qh_p, NE * ND / 4);

    // fork: selgemm (depends only on xh, wh) runs on side stream,
    // concurrent with the z-chain on the main stream.
    cudaEventRecord(evFork, 0);
    cudaStreamWaitEvent(s2, evFork, 0);
    k_selgemm<<<dim3(8, 256), 256, SG_SMEM, s2>>>(bs);
    cudaEventRecord(evSel, s2);

    // z-chain on main stream
    k_qw     <<<8,               256, QW_SMEM>>>();
    k_qb     <<<1,               64>>>(q_emb, bk);
    k_zgemm  <<<dim3(16, 16),    256, Z_SMEM>>>(n_idx);
    k_fwsums <<<NB * NE,         256>>>(mask);
    k_bwsums <<<(NB * NL) / 256, 256>>>();
    k_pgemm2 <<<dim3(8, 16),     256, PG_SMEM>>>(mask);
    k_cproj  <<<dim3(8, 8, 2),   256, SG_SMEM>>>(n_idx, b_emb, ba, bb);

    // join: final needs selh + ca/cb + z + bw sums
    cudaStreamWaitEvent(0, evSel, 0);
    k_final  <<<dim3(8, 32, 16), 256, FN_SMEM>>>(out);
}

// round 14
// speedup vs baseline: 1.0709x; 1.0103x over previous
#include <cuda_runtime.h>
#include <cuda_fp16.h>
#include <cstdint>
#include <math.h>

// Problem constants
#define NB 16
#define NL 2048
#define ND 1024
#define NE 64

// ---------------- scratch (device globals; no runtime allocation) ----------------
__device__ __half g_selh[(size_t)NB * NL * ND]; // sigmoid(x @ Ws^T + bs)
__device__ float  g_z   [(size_t)NB * NE * NL]; // attention logits (fp32)
__device__ __half g_pa  [(size_t)NB * NE * ND]; // normalized A_fw @ x
__device__ __half g_pb  [(size_t)NB * NE * ND];
__device__ float  g_ppa0[(size_t)NB * NE * ND]; // split-K partials (fp32)
__device__ float  g_ppa1[(size_t)NB * NE * ND];
__device__ float  g_ppb0[(size_t)NB * NE * ND];
__device__ float  g_ppb1[(size_t)NB * NE * ND];
__device__ __half g_ca  [(size_t)NB * NE * ND]; // class_a
__device__ __half g_cb  [(size_t)NB * NE * ND]; // class_b
__device__ float  g_afw [NB * NE];
__device__ float  g_bfw [NB * NE];
__device__ float  g_abw [NB * NL];
__device__ float  g_bbw [NB * NL];
__device__ __half g_xh  [(size_t)NB * NL * ND]; // x  (fp16)
__device__ __half g_wh  [(size_t)4 * ND * ND];  // Wk,Wa,Wb,Ws (fp16)
__device__ __half g_qh  [(size_t)NE * ND];      // q_emb (fp16)
__device__ __half g_qwh [(size_t)NE * ND];      // q_emb @ Wk (fp16)
__device__ float  g_qbv [NE];                   // q_emb . bk

// pads (in halves)
#define PADH  72    // [m/n][k] rows, BK=64 halves
#define PADNH 136   // [k][n] rows, 128 n-halves

// ============================================================================
// helpers
// ============================================================================
__device__ __forceinline__ uint32_t smem_u32(const void* p) {
    uint32_t a;
    asm("{ .reg .u64 t; cvta.to.shared.u64 t, %1; cvt.u32.u64 %0, t; }"
        : "=r"(a) : "l"(p));
    return a;
}

__device__ __forceinline__ void cp_async16(uint32_t dst, const void* src) {
    asm volatile("cp.async.cg.shared.global [%0], [%1], 16;" :: "r"(dst), "l"(src));
}

__device__ __forceinline__ void mma_f16(float* d, const uint32_t* a, const uint32_t* b) {
    asm volatile(
        "mma.sync.aligned.m16n8k16.row.col.f32.f16.f16.f32 "
        "{%0,%1,%2,%3}, {%4,%5,%6,%7}, {%8,%9}, {%0,%1,%2,%3};\n"
        : "+f"(d[0]), "+f"(d[1]), "+f"(d[2]), "+f"(d[3])
        : "r"(a[0]), "r"(a[1]), "r"(a[2]), "r"(a[3]), "r"(b[0]), "r"(b[1]));
}

// dual 16-bit load for [k][n] smem layouts: {B[k][n], B[k+1][n]}
__device__ __forceinline__ uint32_t ldpair(const __half* base, int k, int n, int strideH) {
    uint16_t lo = *(const uint16_t*)(base + (size_t)k * strideH + n);
    uint16_t hi = *(const uint16_t*)(base + (size_t)(k + 1) * strideH + n);
    return (uint32_t)lo | ((uint32_t)hi << 16);
}

// ============================================================================
// Kernel 0: fp32 -> fp16 conversion prepass
// ============================================================================
__global__ __launch_bounds__(256) void k_cvt_h(const float* __restrict__ src,
                                               __half* __restrict__ dst, int n4)
{
    int i = blockIdx.x * 256 + threadIdx.x;
    if (i >= n4) return;
    float4 v = ((const float4*)src)[i];
    __half2 h0 = __floats2half2_rn(v.x, v.y);
    __half2 h1 = __floats2half2_rn(v.z, v.w);
    ((uint2*)dst)[i] = make_uint2(*(uint32_t*)&h0, *(uint32_t*)&h1);
}

__global__ __launch_bounds__(256) void k_cvt4_h(
    const float* __restrict__ w0, const float* __restrict__ w1,
    const float* __restrict__ w2, const float* __restrict__ w3)
{
    const float* srcs[4] = { w0, w1, w2, w3 };
    const float* src = srcs[blockIdx.y];
    __half* dst = g_wh + (size_t)blockIdx.y * ND * ND;
    int i = blockIdx.x * 256 + threadIdx.x;
    float4 v = ((const float4*)src)[i];
    __half2 h0 = __floats2half2_rn(v.x, v.y);
    __half2 h1 = __floats2half2_rn(v.z, v.w);
    ((uint2*)dst)[i] = make_uint2(*(uint32_t*)&h0, *(uint32_t*)&h1);
}

// ============================================================================
// Kernel A: selector GEMM + sigmoid.  g_selh = sigmoid(x @ Ws^T + bs)
// fp16 mma. CTA 128x128, 8 warps (2x4), warp tile 64x32, BK=64 halves,
// 3-stage ring, 110.6 KB smem => 2 CTAs/SM.
// ============================================================================
#define SG_STG_H ((128 + 128) * PADH)
#define SG_SMEM (3 * SG_STG_H * 2)      // 110,592 B

__global__ __launch_bounds__(256, 2) void k_selgemm(const float* __restrict__ bs)
{
    extern __shared__ __half smh[];

    const int n0 = blockIdx.x * 128;
    const int m0 = blockIdx.y * 128;
    const __half* Wt = g_wh + (size_t)3 * ND * ND;

    const int tid = threadIdx.x;
    const int wid = tid >> 5, lane = tid & 31;
    const int wm = wid >> 2, wn = wid & 3;     // 2 x 4
    const int g = lane >> 2, tg = lane & 3;

    const uint32_t sb = smem_u32(smh);

    float acc[4][4][4];
    #pragma unroll
    for (int mt = 0; mt < 4; mt++)
        #pragma unroll
        for (int nt = 0; nt < 4; nt++)
            #pragma unroll
            for (int r = 0; r < 4; r++) acc[mt][nt][r] = 0.f;

    const int ldRow = tid >> 3;          // 0..31
    const int ldSeg = tid & 7;

    auto load_chunk = [&](int kc, int st) {
        const uint32_t s0 = sb + (uint32_t)(st * SG_STG_H) * 2u;
        const uint32_t bB = s0 + (uint32_t)(128 * PADH) * 2u;
        const __half* xs = g_xh + (size_t)m0 * 1024 + kc * 64;
        const __half* ws = Wt   + (size_t)n0 * 1024 + kc * 64;
        #pragma unroll
        for (int s = 0; s < 4; ++s) {
            int row = ldRow + s * 32;
            cp_async16(s0 + (uint32_t)(row * (PADH * 2) + ldSeg * 16),
                       xs + (size_t)row * 1024 + ldSeg * 8);
        }
        #pragma unroll
        for (int s = 0; s < 4; ++s) {
            int row = ldRow + s * 32;
            cp_async16(bB + (uint32_t)(row * (PADH * 2) + ldSeg * 16),
                       ws + (size_t)row * 1024 + ldSeg * 8);
        }
        asm volatile("cp.async.commit_group;" ::: "memory");
    };

    load_chunk(0, 0);
    load_chunk(1, 1);

    for (int it = 0; it < 16; ++it) {
        const int st = it % 3;
        if (it < 15) {
            asm volatile("cp.async.wait_group 1;" ::: "memory");
        } else {
            asm volatile("cp.async.wait_group 0;" ::: "memory");
        }
        __syncthreads();

        const __half* As = smh + st * SG_STG_H;
        const __half* Bs = As + 128 * PADH;

        #pragma unroll
        for (int ks = 0; ks < 4; ++ks) {
            const int kb = ks * 16;
            uint32_t afr[4][4];
            #pragma unroll
            for (int mt = 0; mt < 4; mt++) {
                const __half* ap = As + (wm * 64 + mt * 16 + g) * PADH + kb + 2 * tg;
                afr[mt][0] = *(const uint32_t*)ap;
                afr[mt][1] = *(const uint32_t*)(ap + 8 * PADH);
                afr[mt][2] = *(const uint32_t*)(ap + 8);
                afr[mt][3] = *(const uint32_t*)(ap + 8 * PADH + 8);
            }
            uint32_t bfr[4][2];
            #pragma unroll
            for (int nt = 0; nt < 4; nt++) {
                const __half* bp = Bs + (wn * 32 + nt * 8 + g) * PADH + kb + 2 * tg;
                bfr[nt][0] = *(const uint32_t*)bp;
                bfr[nt][1] = *(const uint32_t*)(bp + 8);
            }
            #pragma unroll
            for (int mt = 0; mt < 4; mt++)
                #pragma unroll
                for (int nt = 0; nt < 4; nt++)
                    mma_f16(acc[mt][nt], afr[mt], bfr[nt]);
        }

        if (it + 2 < 16) load_chunk(it + 2, (it + 2) % 3);
    }

    const int mBase = m0 + wm * 64;
    const int nBase = n0 + wn * 32;
    #pragma unroll
    for (int mt = 0; mt < 4; mt++) {
        #pragma unroll
        for (int nt = 0; nt < 4; nt++) {
            const int r0 = mBase + mt * 16 + g;
            const int c  = nBase + nt * 8 + 2 * tg;
            float2 bv = *(const float2*)(bs + c);
            float s00 = 1.f / (1.f + expf(-(acc[mt][nt][0] + bv.x)));
            float s01 = 1.f / (1.f + expf(-(acc[mt][nt][1] + bv.y)));
            float s10 = 1.f / (1.f + expf(-(acc[mt][nt][2] + bv.x)));
            float s11 = 1.f / (1.f + expf(-(acc[mt][nt][3] + bv.y)));
            *(__half2*)(g_selh + (size_t)r0 * 1024 + c)       = __floats2half2_rn(s00, s01);
            *(__half2*)(g_selh + (size_t)(r0 + 8) * 1024 + c) = __floats2half2_rn(s10, s11);
        }
    }
}

// ============================================================================
// Kernel B: class projections  g_c{a,b} = P @ W{a,b}^T + S*b{a,b} + b_emb[idx]
// ============================================================================
__global__ __launch_bounds__(256, 2) void k_cproj(
    const int* __restrict__ n_idx, const float* __restrict__ b_emb,
    const float* __restrict__ ba, const float* __restrict__ bb)
{
    extern __shared__ __half smh[];

    const int n0 = blockIdx.x * 128;
    const int m0 = blockIdx.y * 128;
    const int side = blockIdx.z;
    const __half* P   = side ? g_pb  : g_pa;
    const float* sums = side ? g_bfw : g_afw;
    const float* bias = side ? bb    : ba;
    __half*      out  = side ? g_cb  : g_ca;
    const __half* Wt  = g_wh + (size_t)(side ? 2 : 1) * ND * ND;

    const int tid = threadIdx.x;
    const int wid = tid >> 5, lane = tid & 31;
    const int wm = wid >> 2, wn = wid & 3;
    const int g = lane >> 2, tg = lane & 3;

    float acc[4][4][4];
    #pragma unroll
    for (int mt = 0; mt < 4; mt++)
        #pragma unroll
        for (int nt = 0; nt < 4; nt++)
            #pragma unroll
            for (int r = 0; r < 4; r++) acc[mt][nt][r] = 0.f;

    const uint32_t sb = smem_u32(smh);
    const int ldRow = tid >> 3;
    const int ldSeg = tid & 7;

    auto load_chunk = [&](int kc, int st) {
        const uint32_t s0 = sb + (uint32_t)(st * SG_STG_H) * 2u;
        const uint32_t bB = s0 + (uint32_t)(128 * PADH) * 2u;
        const __half* xs = P  + (size_t)m0 * 1024 + kc * 64;
        const __half* ws = Wt + (size_t)n0 * 1024 + kc * 64;
        #pragma unroll
        for (int s = 0; s < 4; ++s) {
            int row = ldRow + s * 32;
            cp_async16(s0 + (uint32_t)(row * (PADH * 2) + ldSeg * 16),
                       xs + (size_t)row * 1024 + ldSeg * 8);
        }
        #pragma unroll
        for (int s = 0; s < 4; ++s) {
            int row = ldRow + s * 32;
            cp_async16(bB + (uint32_t)(row * (PADH * 2) + ldSeg * 16),
                       ws + (size_t)row * 1024 + ldSeg * 8);
        }
        asm volatile("cp.async.commit_group;" ::: "memory");
    };

    load_chunk(0, 0);
    load_chunk(1, 1);

    for (int it = 0; it < 16; ++it) {
        const int st = it % 3;
        if (it < 15) {
            asm volatile("cp.async.wait_group 1;" ::: "memory");
        } else {
            asm volatile("cp.async.wait_group 0;" ::: "memory");
        }
        __syncthreads();

        const __half* As = smh + st * SG_STG_H;
        const __half* Bs = As + 128 * PADH;

        #pragma unroll
        for (int ks = 0; ks < 4; ++ks) {
            const int kb = ks * 16;
            uint32_t afr[4][4];
            #pragma unroll
            for (int mt = 0; mt < 4; mt++) {
                const __half* ap = As + (wm * 64 + mt * 16 + g) * PADH + kb + 2 * tg;
                afr[mt][0] = *(const uint32_t*)ap;
                afr[mt][1] = *(const uint32_t*)(ap + 8 * PADH);
                afr[mt][2] = *(const uint32_t*)(ap + 8);
                afr[mt][3] = *(const uint32_t*)(ap + 8 * PADH + 8);
            }
            uint32_t bfr[4][2];
            #pragma unroll
            for (int nt = 0; nt < 4; nt++) {
                const __half* bp = Bs + (wn * 32 + nt * 8 + g) * PADH + kb + 2 * tg;
                bfr[nt][0] = *(const uint32_t*)bp;
                bfr[nt][1] = *(const uint32_t*)(bp + 8);
            }
            #pragma unroll
            for (int mt = 0; mt < 4; mt++)
                #pragma unroll
                for (int nt = 0; nt < 4; nt++)
                    mma_f16(acc[mt][nt], afr[mt], bfr[nt]);
        }

        if (it + 2 < 16) load_chunk(it + 2, (it + 2) % 3);
    }

    const int mBase = m0 + wm * 64;
    const int nBase = n0 + wn * 32;
    #pragma unroll
    for (int mt = 0; mt < 4; mt++) {
        const int r0 = mBase + mt * 16 + g;
        const int b  = r0 >> 6;
        const int e0 = r0 & 63;
        float s0v = sums[b * 64 + e0];
        float s1v = sums[b * 64 + e0 + 8];
        float S0 = s0v / (s0v + 1e-9f);
        float S1 = s1v / (s1v + 1e-9f);
        const float* br0 = b_emb + (size_t)n_idx[b * 64 + e0] * 1024;
        const float* br1 = b_emb + (size_t)n_idx[b * 64 + e0 + 8] * 1024;
        #pragma unroll
        for (int nt = 0; nt < 4; nt++) {
            const int c = nBase + nt * 8 + 2 * tg;
            float2 bv = *(const float2*)(bias + c);
            float2 e0v = *(const float2*)(br0 + c);
            float2 e1v = *(const float2*)(br1 + c);
            *(__half2*)(out + (size_t)r0 * 1024 + c) = __floats2half2_rn(
                acc[mt][nt][0] + S0 * bv.x + e0v.x,
                acc[mt][nt][1] + S0 * bv.y + e0v.y);
            *(__half2*)(out + (size_t)(r0 + 8) * 1024 + c) = __floats2half2_rn(
                acc[mt][nt][2] + S1 * bv.x + e1v.x,
                acc[mt][nt][3] + S1 * bv.y + e1v.y);
        }
    }
}

// ============================================================================
// Kernel C: qw = q_emb @ Wk  (M=64(e), N=1024(d), K=1024(j)). B=[k][n]. grid(8).
// ============================================================================
#define QW_STG_H (64 * PADH + 64 * PADNH)
#define QW_SMEM (2 * QW_STG_H * 2)

__global__ __launch_bounds__(256) void k_qw()
{
    extern __shared__ __half smh[];
    const int n0 = blockIdx.x * 128;

    const int tid = threadIdx.x;
    const int wid = tid >> 5, lane = tid & 31;
    const int wm = wid >> 2, wn = wid & 3;
    const int g = lane >> 2, tg = lane & 3;

    const uint32_t sb = smem_u32(smh);

    float acc[2][4][4];
    #pragma unroll
    for (int mt = 0; mt < 2; mt++)
        #pragma unroll
        for (int nt = 0; nt < 4; nt++)
            #pragma unroll
            for (int r = 0; r < 4; r++) acc[mt][nt][r] = 0.f;

    const int aRow = tid >> 3;
    const int aSeg = tid & 7;

    auto load_chunk = [&](int kc, int st) {
        const uint32_t s0 = sb + (uint32_t)(st * QW_STG_H) * 2u;
        const uint32_t bB = s0 + (uint32_t)(64 * PADH) * 2u;
        cp_async16(s0 + (uint32_t)(aRow * (PADH * 2) + aSeg * 16),
                   g_qh + (size_t)aRow * 1024 + kc * 64 + aSeg * 8);
        cp_async16(s0 + (uint32_t)((aRow + 32) * (PADH * 2) + aSeg * 16),
                   g_qh + (size_t)(aRow + 32) * 1024 + kc * 64 + aSeg * 8);
        #pragma unroll
        for (int s = 0; s < 4; ++s) {
            int slot = tid + s * 256;
            int row = slot >> 4, seg = slot & 15;
            cp_async16(bB + (uint32_t)(row * (PADNH * 2) + seg * 16),
                       g_wh + (size_t)(kc * 64 + row) * 1024 + n0 + seg * 8);
        }
        asm volatile("cp.async.commit_group;" ::: "memory");
    };

    load_chunk(0, 0);

    for (int it = 0; it < 16; ++it) {
        const int buf = it & 1;
        if (it + 1 < 16) {
            load_chunk(it + 1, buf ^ 1);
            asm volatile("cp.async.wait_group 1;" ::: "memory");
        } else {
            asm volatile("cp.async.wait_group 0;" ::: "memory");
        }
        __syncthreads();

        const __half* As = smh + buf * QW_STG_H;
        const __half* Bs = As + 64 * PADH;

        #pragma unroll
        for (int ks = 0; ks < 4; ++ks) {
            const int kb = ks * 16;
            uint32_t afr[2][4];
            #pragma unroll
            for (int mt = 0; mt < 2; mt++) {
                const __half* ap = As + (wm * 32 + mt * 16 + g) * PADH + kb + 2 * tg;
                afr[mt][0] = *(const uint32_t*)ap;
                afr[mt][1] = *(const uint32_t*)(ap + 8 * PADH);
                afr[mt][2] = *(const uint32_t*)(ap + 8);
                afr[mt][3] = *(const uint32_t*)(ap + 8 * PADH + 8);
            }
            uint32_t bfr[4][2];
            #pragma unroll
            for (int nt = 0; nt < 4; nt++) {
                const int n = wn * 32 + nt * 8 + g;
                bfr[nt][0] = ldpair(Bs, kb + 2 * tg, n, PADNH);
                bfr[nt][1] = ldpair(Bs, kb + 2 * tg + 8, n, PADNH);
            }
            #pragma unroll
            for (int mt = 0; mt < 2; mt++)
                #pragma unroll
                for (int nt = 0; nt < 4; nt++)
                    mma_f16(acc[mt][nt], afr[mt], bfr[nt]);
        }
        __syncthreads();
    }

    #pragma unroll
    for (int mt = 0; mt < 2; mt++) {
        const int e0 = wm * 32 + mt * 16 + g;
        #pragma unroll
        for (int nt = 0; nt < 4; nt++) {
            const int c = n0 + wn * 32 + nt * 8 + 2 * tg;
            *(__half2*)(g_qwh + (size_t)e0 * 1024 + c) =
                __floats2half2_rn(acc[mt][nt][0], acc[mt][nt][1]);
            *(__half2*)(g_qwh + (size_t)(e0 + 8) * 1024 + c) =
                __floats2half2_rn(acc[mt][nt][2], acc[mt][nt][3]);
        }
    }
}

// Kernel C2: qb[e] = q_emb[e] . bk
__global__ void k_qb(const float* __restrict__ q_emb, const float* __restrict__ bk)
{
    int e = threadIdx.x;
    if (e >= 64) return;
    float s = 0.f;
    const float* qr = q_emb + (size_t)e * 1024;
    for (int d = 0; d < 1024; ++d) s += qr[d] * bk[d];
    g_qbv[e] = s;
}

// ============================================================================
// Kernel D: z[b,e,l] = (qwh[idx[b,e]] . xh[b,l] + qb[idx]) / 32
// ============================================================================
#define Z_STG_H ((64 + 128) * PADH)
#define Z_SMEM (2 * Z_STG_H * 2)

__global__ __launch_bounds__(256) void k_zgemm(const int* __restrict__ n_idx)
{
    extern __shared__ __half smh[];
    const int b  = blockIdx.y;
    const int l0 = blockIdx.x * 128;
    const int tid = threadIdx.x;
    const int wid = tid >> 5, lane = tid & 31;
    const int wm = wid >> 2, wn = wid & 3;
    const int g = lane >> 2, tg = lane & 3;

    const uint32_t sb = smem_u32(smh);

    float acc[2][4][4];
    #pragma unroll
    for (int mt = 0; mt < 2; mt++)
        #pragma unroll
        for (int nt = 0; nt < 4; nt++)
            #pragma unroll
            for (int r = 0; r < 4; r++) acc[mt][nt][r] = 0.f;

    const int aRow = tid >> 3;
    const int aSeg = tid & 7;
    const __half* aSrc0 = g_qwh + (size_t)n_idx[b * 64 + aRow] * 1024;
    const __half* aSrc1 = g_qwh + (size_t)n_idx[b * 64 + aRow + 32] * 1024;

    auto load_chunk = [&](int kc, int st) {
        const uint32_t s0 = sb + (uint32_t)(st * Z_STG_H) * 2u;
        const uint32_t bB = s0 + (uint32_t)(64 * PADH) * 2u;
        cp_async16(s0 + (uint32_t)(aRow * (PADH * 2) + aSeg * 16), aSrc0 + kc * 64 + aSeg * 8);
        cp_async16(s0 + (uint32_t)((aRow + 32) * (PADH * 2) + aSeg * 16), aSrc1 + kc * 64 + aSeg * 8);
        const __half* xs = g_xh + ((size_t)b * 2048 + l0) * 1024 + kc * 64;
        #pragma unroll
        for (int s = 0; s < 4; ++s) {
            int row = aRow + s * 32;
            cp_async16(bB + (uint32_t)(row * (PADH * 2) + aSeg * 16),
                       xs + (size_t)row * 1024 + aSeg * 8);
        }
        asm volatile("cp.async.commit_group;" ::: "memory");
    };

    load_chunk(0, 0);

    for (int it = 0; it < 16; ++it) {
        const int buf = it & 1;
        if (it + 1 < 16) {
            load_chunk(it + 1, buf ^ 1);
            asm volatile("cp.async.wait_group 1;" ::: "memory");
        } else {
            asm volatile("cp.async.wait_group 0;" ::: "memory");
        }
        __syncthreads();

        const __half* As = smh + buf * Z_STG_H;
        const __half* Bs = As + 64 * PADH;

        #pragma unroll
        for (int ks = 0; ks < 4; ++ks) {
            const int kb = ks * 16;
            uint32_t afr[2][4];
            #pragma unroll
            for (int mt = 0; mt < 2; mt++) {
                const __half* ap = As + (wm * 32 + mt * 16 + g) * PADH + kb + 2 * tg;
                afr[mt][0] = *(const uint32_t*)ap;
                afr[mt][1] = *(const uint32_t*)(ap + 8 * PADH);
                afr[mt][2] = *(const uint32_t*)(ap + 8);
                afr[mt][3] = *(const uint32_t*)(ap + 8 * PADH + 8);
            }
            uint32_t bfr[4][2];
            #pragma unroll
            for (int nt = 0; nt < 4; nt++) {
                const __half* bp = Bs + (wn * 32 + nt * 8 + g) * PADH + kb + 2 * tg;
                bfr[nt][0] = *(const uint32_t*)bp;
                bfr[nt][1] = *(const uint32_t*)(bp + 8);
            }
            #pragma unroll
            for (int mt = 0; mt < 2; mt++)
                #pragma unroll
                for (int nt = 0; nt < 4; nt++)
                    mma_f16(acc[mt][nt], afr[mt], bfr[nt]);
        }
        __syncthreads();
    }

    #pragma unroll
    for (int mt = 0; mt < 2; mt++) {
        #pragma unroll
        for (int nt = 0; nt < 4; nt++) {
            const int e = wm * 32 + mt * 16 + g;
            const float qb0 = g_qbv[n_idx[b * 64 + e]];
            const float qb1 = g_qbv[n_idx[b * 64 + e + 8]];
            const int l = l0 + wn * 32 + nt * 8 + 2 * tg;
            float* zr0 = g_z + ((size_t)b * 64 + e) * 2048 + l;
            float* zr1 = g_z + ((size_t)b * 64 + e + 8) * 2048 + l;
            *(float2*)zr0 = make_float2((acc[mt][nt][0] + qb0) * 0.03125f,
                                        (acc[mt][nt][1] + qb0) * 0.03125f);
            *(float2*)zr1 = make_float2((acc[mt][nt][2] + qb1) * 0.03125f,
                                        (acc[mt][nt][3] + qb1) * 0.03125f);
        }
    }
}

// ============================================================================
// Kernel 3/4: reduction sums
// ============================================================================
__global__ __launch_bounds__(256) void k_fwsums(const int* __restrict__ mask)
{
    const int be = blockIdx.x;
    const int b = be >> 6;
    const float* zr = g_z + (size_t)be * 2048;
    const int* mrow = mask + b * 2048;

    float sa = 0.f, sb = 0.f;
    for (int l = threadIdx.x; l < 2048; l += 256) {
        float v = zr[l];
        if (mrow[l] != 0) { sa += fmaxf(v, 0.f); sb += fmaxf(-v, 0.f); }
    }
    #pragma unroll
    for (int off = 16; off > 0; off >>= 1) {
        sa += __shfl_down_sync(0xffffffffu, sa, off);
        sb += __shfl_down_sync(0xffffffffu, sb, off);
    }
    __shared__ float ra[8], rb[8];
    int wrp = threadIdx.x >> 5, lane = threadIdx.x & 31;
    if (lane == 0) { ra[wrp] = sa; rb[wrp] = sb; }
    __syncthreads();
    if (threadIdx.x == 0) {
        float ta = 0.f, tb = 0.f;
        #pragma unroll
        for (int i = 0; i < 8; i++) { ta += ra[i]; tb += rb[i]; }
        g_afw[be] = ta; g_bfw[be] = tb;
    }
}

__global__ __launch_bounds__(256) void k_bwsums()
{
    const int idx = blockIdx.x * 256 + threadIdx.x;
    const int b = idx >> 11;
    const float* zp = g_z + (size_t)b * 64 * 2048 + (idx & 2047);
    float sa = 0.f, sb = 0.f;
    #pragma unroll 8
    for (int e = 0; e < 64; e++) {
        float v = zp[(size_t)e * 2048];
        sa += fmaxf(v, 0.f);
        sb += fmaxf(-v, 0.f);
    }
    g_abw[idx] = sa;
    g_bbw[idx] = sb;
}

// ============================================================================
// Kernel E: split-K P GEMM.  partials = A_{a,b} @ x over K half (no norm).
// grid (8, 16, 2): x=d-block, y=b, z=K half. M=64(e), N=128(d), K=1024.
// ============================================================================
#define PG_STG_H (2 * 64 * PADH + 64 * PADNH)
#define PG_SMEM (2 * PG_STG_H * 2)

__global__ __launch_bounds__(256) void k_pgemm2(const int* __restrict__ mask)
{
    extern __shared__ __half smh[];
    const int b  = blockIdx.y;
    const int n0 = blockIdx.x * 128;
    const int kh = blockIdx.z;                 // K half: 0 or 1
    float* outA = kh ? g_ppa1 : g_ppa0;
    float* outB = kh ? g_ppb1 : g_ppb0;

    const int tid = threadIdx.x;
    const int wid = tid >> 5, lane = tid & 31;
    const int wm = wid >> 2, wn = wid & 3;
    const int g = lane >> 2, tg = lane & 3;

    const uint32_t sb = smem_u32(smh);

    float accA[2][4][4], accB[2][4][4];
    #pragma unroll
    for (int mt = 0; mt < 2; mt++)
        #pragma unroll
        for (int nt = 0; nt < 4; nt++)
            #pragma unroll
            for (int r = 0; r < 4; r++) { accA[mt][nt][r] = 0.f; accB[mt][nt][r] = 0.f; }

    const int aE = tid >> 2;
    const int aC = (tid & 3) * 16;
    const float* zrow = g_z + ((size_t)b * 64 + aE) * 2048;
    const int* mrow = mask + b * 2048;
    const int kBase = kh * 1024;

    auto load_chunk = [&](int kc, int st) {
        __half* Aa = smh + st * PG_STG_H;
        __half* Ab = Aa + 64 * PADH;
        const uint32_t bB = sb + (uint32_t)(st * PG_STG_H + 2 * 64 * PADH) * 2u;
        const int kk = kBase + kc * 64;
        __half ha[16], hb[16];
        #pragma unroll
        for (int q = 0; q < 4; ++q) {
            float4 v = *(const float4*)(zrow + kk + aC + q * 4);
            int4 m = *(const int4*)(mrow + kk + aC + q * 4);
            float vv[4] = { v.x, v.y, v.z, v.w };
            int   mm[4] = { m.x, m.y, m.z, m.w };
            #pragma unroll
            for (int j = 0; j < 4; ++j) {
                ha[q * 4 + j] = __float2half_rn(mm[j] ? fmaxf(vv[j], 0.f) : 0.f);
                hb[q * 4 + j] = __float2half_rn(mm[j] ? fmaxf(-vv[j], 0.f) : 0.f);
            }
        }
        *(uint4*)(Aa + aE * PADH + aC)     = *(uint4*)ha;
        *(uint4*)(Aa + aE * PADH + aC + 8) = *(uint4*)(ha + 8);
        *(uint4*)(Ab + aE * PADH + aC)     = *(uint4*)hb;
        *(uint4*)(Ab + aE * PADH + aC + 8) = *(uint4*)(hb + 8);
        const __half* xs = g_xh + ((size_t)b * 2048 + kk) * 1024 + n0;
        #pragma unroll
        for (int s = 0; s < 4; ++s) {
            int slot = tid + s * 256;
            int row = slot >> 4, seg = slot & 15;
            cp_async16(bB + (uint32_t)(row * (PADNH * 2) + seg * 16),
                       xs + (size_t)row * 1024 + seg * 8);
        }
        asm volatile("cp.async.commit_group;" ::: "memory");
    };

    load_chunk(0, 0);

    for (int it = 0; it < 16; ++it) {
        const int buf = it & 1;
        if (it + 1 < 16) {
            load_chunk(it + 1, buf ^ 1);
            asm volatile("cp.async.wait_group 1;" ::: "memory");
        } else {
            asm volatile("cp.async.wait_group 0;" ::: "memory");
        }
        __syncthreads();

        const __half* Aa = smh + buf * PG_STG_H;
        const __half* Ab = Aa + 64 * PADH;
        const __half* Bs = Ab + 64 * PADH;

        #pragma unroll
        for (int ks = 0; ks < 4; ++ks) {
            const int kb = ks * 16;
            uint32_t afa[2][4], afb[2][4];
            #pragma unroll
            for (int mt = 0; mt < 2; mt++) {
                const __half* pa = Aa + (wm * 32 + mt * 16 + g) * PADH + kb + 2 * tg;
                const __half* pb = Ab + (wm * 32 + mt * 16 + g) * PADH + kb + 2 * tg;
                afa[mt][0] = *(const uint32_t*)pa;
                afa[mt][1] = *(const uint32_t*)(pa + 8 * PADH);
                afa[mt][2] = *(const uint32_t*)(pa + 8);
                afa[mt][3] = *(const uint32_t*)(pa + 8 * PADH + 8);
                afb[mt][0] = *(const uint32_t*)pb;
                afb[mt][1] = *(const uint32_t*)(pb + 8 * PADH);
                afb[mt][2] = *(const uint32_t*)(pb + 8);
                afb[mt][3] = *(const uint32_t*)(pb + 8 * PADH + 8);
            }
            uint32_t bfr[4][2];
            #pragma unroll
            for (int nt = 0; nt < 4; nt++) {
                const int n = wn * 32 + nt * 8 + g;
                bfr[nt][0] = ldpair(Bs, kb + 2 * tg, n, PADNH);
                bfr[nt][1] = ldpair(Bs, kb + 2 * tg + 8, n, PADNH);
            }
            #pragma unroll
            for (int mt = 0; mt < 2; mt++)
                #pragma unroll
                for (int nt = 0; nt < 4; nt++) {
                    mma_f16(accA[mt][nt], afa[mt], bfr[nt]);
                    mma_f16(accB[mt][nt], afb[mt], bfr[nt]);
                }
        }
        __syncthreads();
    }

    #pragma unroll
    for (int mt = 0; mt < 2; mt++) {
        const int e0 = wm * 32 + mt * 16 + g;
        #pragma unroll
        for (int nt = 0; nt < 4; nt++) {
            const int d = n0 + wn * 32 + nt * 8 + 2 * tg;
            *(float2*)(outA + ((size_t)b * 64 + e0) * 1024 + d) =
                make_float2(accA[mt][nt][0], accA[mt][nt][1]);
            *(float2*)(outA + ((size_t)b * 64 + e0 + 8) * 1024 + d) =
                make_float2(accA[mt][nt][2], accA[mt][nt][3]);
            *(float2*)(outB + ((size_t)b * 64 + e0) * 1024 + d) =
                make_float2(accB[mt][nt][0], accB[mt][nt][1]);
            *(float2*)(outB + ((size_t)b * 64 + e0 + 8) * 1024 + d) =
                make_float2(accB[mt][nt][2], accB[mt][nt][3]);
        }
    }
}

// Kernel E2: combine split-K partials + normalize -> fp16 g_pa/g_pb
__global__ __launch_bounds__(256) void k_psum()
{
    const int i = blockIdx.x * 256 + threadIdx.x;   // float4 index, 262144 total
    const int idx = i * 4;
    const int e = (idx >> 10) & 63;
    const int b = idx >> 16;
    const float ia = 1.f / (g_afw[b * 64 + e] + 1e-9f);
    const float ib = 1.f / (g_bfw[b * 64 + e] + 1e-9f);
    float4 a0 = ((const float4*)g_ppa0)[i];
    float4 a1 = ((const float4*)g_ppa1)[i];
    float4 b0 = ((const float4*)g_ppb0)[i];
    float4 b1 = ((const float4*)g_ppb1)[i];
    __half2 ha0 = __floats2half2_rn((a0.x + a1.x) * ia, (a0.y + a1.y) * ia);
    __half2 ha1 = __floats2half2_rn((a0.z + a1.z) * ia, (a0.w + a1.w) * ia);
    __half2 hb0 = __floats2half2_rn((b0.x + b1.x) * ib, (b0.y + b1.y) * ib);
    __half2 hb1 = __floats2half2_rn((b0.z + b1.z) * ib, (b0.w + b1.w) * ib);
    ((uint2*)g_pa)[i] = make_uint2(*(uint32_t*)&ha0, *(uint32_t*)&ha1);
    ((uint2*)g_pb)[i] = make_uint2(*(uint32_t*)&hb0, *(uint32_t*)&hb1);
}

// ============================================================================
// Kernel 6: final mix (fp16 mma). M=64(l), N=128(d), K=64(e). Single shot.
// ============================================================================
#define FN_SMEM ((2 * 64 * PADH + 2 * 64 * PADNH) * 2)

__global__ __launch_bounds__(256) void k_final(float* __restrict__ out)
{
    extern __shared__ __half smh[];
    __half* Aa = smh;
    __half* Ab = Aa + 64 * PADH;
    __half* Ba = Ab + 64 * PADH;
    __half* Bb = Ba + 64 * PADNH;

    const int b  = blockIdx.z;
    const int l0 = blockIdx.y * 64;
    const int d0 = blockIdx.x * 128;
    const int tid = threadIdx.x;
    const int wid = tid >> 5, lane = tid & 31;
    const int wm = wid >> 2, wn = wid & 3;
    const int g = lane >> 2, tg = lane & 3;

    {
        const int e  = tid & 63;
        const int lc = (tid >> 6) * 16;
        const float* zp = g_z + ((size_t)b * 64 + e) * 2048 + l0 + lc;
        #pragma unroll
        for (int j = 0; j < 4; ++j) {
            float4 v = *(const float4*)(zp + j * 4);
            float vv[4] = { v.x, v.y, v.z, v.w };
            #pragma unroll
            for (int t = 0; t < 4; ++t) {
                int l = lc + j * 4 + t;
                Aa[l * PADH + e] = __float2half_rn(fmaxf(vv[t], 0.f));
                Ab[l * PADH + e] = __float2half_rn(fmaxf(-vv[t], 0.f));
            }
        }
    }
    {
        const uint32_t baU = smem_u32(Ba);
        const uint32_t bbU = smem_u32(Bb);
        const __half* caP = g_ca + ((size_t)b * 64) * 1024 + d0;
        const __half* cbP = g_cb + ((size_t)b * 64) * 1024 + d0;
        #pragma unroll
        for (int s = 0; s < 4; ++s) {
            int slot = tid + s * 256;
            int row = slot >> 4, seg = slot & 15;
            uint32_t doff = (uint32_t)(row * (PADNH * 2) + seg * 16);
            cp_async16(baU + doff, caP + (size_t)row * 1024 + seg * 8);
            cp_async16(bbU + doff, cbP + (size_t)row * 1024 + seg * 8);
        }
        asm volatile("cp.async.commit_group;" ::: "memory");
        asm volatile("cp.async.wait_group 0;" ::: "memory");
    }
    __syncthreads();

    float aca[2][4][4], acb[2][4][4];
    #pragma unroll
    for (int mt = 0; mt < 2; mt++)
        #pragma unroll
        for (int nt = 0; nt < 4; nt++)
            #pragma unroll
            for (int r = 0; r < 4; r++) { aca[mt][nt][r] = 0.f; acb[mt][nt][r] = 0.f; }

    #pragma unroll
    for (int ks = 0; ks < 4; ++ks) {
        const int kb = ks * 16;
        uint32_t afa[2][4], afb[2][4];
        #pragma unroll
        for (int mt = 0; mt < 2; mt++) {
            const __half* pa = Aa + (wm * 32 + mt * 16 + g) * PADH + kb + 2 * tg;
            const __half* pb = Ab + (wm * 32 + mt * 16 + g) * PADH + kb + 2 * tg;
            afa[mt][0] = *(const uint32_t*)pa;
            afa[mt][1] = *(const uint32_t*)(pa + 8 * PADH);
            afa[mt][2] = *(const uint32_t*)(pa + 8);
            afa[mt][3] = *(const uint32_t*)(pa + 8 * PADH + 8);
            afb[mt][0] = *(const uint32_t*)pb;
            afb[mt][1] = *(const uint32_t*)(pb + 8 * PADH);
            afb[mt][2] = *(const uint32_t*)(pb + 8);
            afb[mt][3] = *(const uint32_t*)(pb + 8 * PADH + 8);
        }
        uint32_t bfa[4][2], bfb[4][2];
        #pragma unroll
        for (int nt = 0; nt < 4; nt++) {
            const int n = wn * 32 + nt * 8 + g;
            bfa[nt][0] = ldpair(Ba, kb + 2 * tg, n, PADNH);
            bfa[nt][1] = ldpair(Ba, kb + 2 * tg + 8, n, PADNH);
            bfb[nt][0] = ldpair(Bb, kb + 2 * tg, n, PADNH);
            bfb[nt][1] = ldpair(Bb, kb + 2 * tg + 8, n, PADNH);
        }
        #pragma unroll
        for (int mt = 0; mt < 2; mt++)
            #pragma unroll
            for (int nt = 0; nt < 4; nt++) {
                mma_f16(aca[mt][nt], afa[mt], bfa[nt]);
                mma_f16(acb[mt][nt], afb[mt], bfb[nt]);
            }
    }

    #pragma unroll
    for (int mt = 0; mt < 2; mt++) {
        const int l0r = l0 + wm * 32 + mt * 16 + g;
        const float ia0 = 1.f / (g_abw[b * 2048 + l0r] + 1e-9f);
        const float ib0 = 1.f / (g_bbw[b * 2048 + l0r] + 1e-9f);
        const float ia1 = 1.f / (g_abw[b * 2048 + l0r + 8] + 1e-9f);
        const float ib1 = 1.f / (g_bbw[b * 2048 + l0r + 8] + 1e-9f);
        #pragma unroll
        for (int nt = 0; nt < 4; nt++) {
            const int d = d0 + wn * 32 + nt * 8 + 2 * tg;
            float2 sg0 = __half22float2(*(const __half2*)(g_selh + ((size_t)b * 2048 + l0r) * 1024 + d));
            float2 sg1 = __half22float2(*(const __half2*)(g_selh + ((size_t)b * 2048 + l0r + 8) * 1024 + d));
            float2 o0 = make_float2(
                sg0.x * (aca[mt][nt][0] * ia0) + (1.f - sg0.x) * (acb[mt][nt][0] * ib0),
                sg0.y * (aca[mt][nt][1] * ia0) + (1.f - sg0.y) * (acb[mt][nt][1] * ib0));
            float2 o1 = make_float2(
                sg1.x * (aca[mt][nt][2] * ia1) + (1.f - sg1.x) * (acb[mt][nt][2] * ib1),
                sg1.y * (aca[mt][nt][3] * ia1) + (1.f - sg1.y) * (acb[mt][nt][3] * ib1));
            *(float2*)(out + ((size_t)b * 2048 + l0r) * 1024 + d)     = o0;
            *(float2*)(out + ((size_t)b * 2048 + l0r + 8) * 1024 + d) = o1;
        }
    }
}

// ============================================================================
extern "C" void kernel_launch(void* const* d_in, const int* in_sizes, int n_in,
                              void* d_out, int out_size)
{
    const float* x     = (const float*)d_in[0];
    const int*   n_idx = (const int*)  d_in[1];
    const int*   mask  = (const int*)  d_in[2];
    const float* q_emb = (const float*)d_in[3];
    const float* b_emb = (const float*)d_in[4];
    const float* Wk    = (const float*)d_in[5];
    const float* bk    = (const float*)d_in[6];
    const float* Wa    = (const float*)d_in[7];
    const float* ba    = (const float*)d_in[8];
    const float* Wb    = (const float*)d_in[9];
    const float* bb    = (const float*)d_in[10];
    const float* Ws    = (const float*)d_in[11];
    const float* bs    = (const float*)d_in[12];
    float* out = (float*)d_out;

    __half *xh_p, *qh_p;
    cudaGetSymbolAddress((void**)&xh_p, g_xh);
    cudaGetSymbolAddress((void**)&qh_p, g_qh);

    cudaFuncSetAttribute(k_selgemm, cudaFuncAttributeMaxDynamicSharedMemorySize, SG_SMEM);
    cudaFuncSetAttribute(k_cproj,   cudaFuncAttributeMaxDynamicSharedMemorySize, SG_SMEM);
    cudaFuncSetAttribute(k_qw,      cudaFuncAttributeMaxDynamicSharedMemorySize, QW_SMEM);
    cudaFuncSetAttribute(k_zgemm,   cudaFuncAttributeMaxDynamicSharedMemorySize, Z_SMEM);
    cudaFuncSetAttribute(k_pgemm2,  cudaFuncAttributeMaxDynamicSharedMemorySize, PG_SMEM);
    cudaFuncSetAttribute(k_final,   cudaFuncAttributeMaxDynamicSharedMemorySize, FN_SMEM);

    // side stream + events (created once; per-call GPU work is identical)
    static cudaStream_t s2 = nullptr;
    static cudaEvent_t evFork = nullptr, evSel = nullptr;
    if (s2 == nullptr) {
        cudaStreamCreateWithFlags(&s2, cudaStreamNonBlocking);
        cudaEventCreateWithFlags(&evFork, cudaEventDisableTiming);
        cudaEventCreateWithFlags(&evSel, cudaEventDisableTiming);
    }

    // prepass on main (capture) stream
    k_cvt_h <<<(NB * NL * ND / 4 + 255) / 256, 256>>>(x, xh_p, NB * NL * ND / 4);
    k_cvt4_h<<<dim3(ND * ND / 4 / 256, 4),     256>>>(Wk, Wa, Wb, Ws);
    k_cvt_h <<<(NE * ND / 4 + 255) / 256,      256>>>(q_emb, qh_p, NE * ND / 4);

    // fork: selgemm on side stream, concurrent with the z-chain
    cudaEventRecord(evFork, 0);
    cudaStreamWaitEvent(s2, evFork, 0);
    k_selgemm<<<dim3(8, 256), 256, SG_SMEM, s2>>>(bs);
    cudaEventRecord(evSel, s2);

    // z-chain on main stream
    k_qw     <<<8,                256, QW_SMEM>>>();
    k_qb     <<<1,                64>>>(q_emb, bk);
    k_zgemm  <<<dim3(16, 16),     256, Z_SMEM>>>(n_idx);
    k_pgemm2 <<<dim3(8, 16, 2),   256, PG_SMEM>>>(mask);
    k_fwsums <<<NB * NE,          256>>>(mask);
    k_bwsums <<<(NB * NL) / 256,  256>>>();
    k_psum   <<<NB * NE * ND / 4 / 256, 256>>>();
    k_cproj  <<<dim3(8, 8, 2),    256, SG_SMEM>>>(n_idx, b_emb, ba, bb);

    // join: final needs selh + ca/cb + z + bw sums
    cudaStreamWaitEvent(0, evSel, 0);
    k_final  <<<dim3(8, 32, 16),  256, FN_SMEM>>>(out);
}

// round 16
// speedup vs baseline: 1.0916x; 1.0193x over previous
#include <cuda_runtime.h>
#include <cuda_fp16.h>
#include <cstdint>
#include <math.h>

// Problem constants
#define NB 16
#define NL 2048
#define ND 1024
#define NE 64

// ---------------- scratch (device globals; no runtime allocation) ----------------
__device__ __half g_selh[(size_t)NB * NL * ND]; // sigmoid(x @ Ws^T + bs)
__device__ float  g_z   [(size_t)NB * NE * NL]; // attention logits (fp32)
__device__ __half g_pa  [(size_t)NB * NE * ND]; // normalized A_fw @ x
__device__ __half g_pb  [(size_t)NB * NE * ND];
__device__ float  g_ppa0[(size_t)NB * NE * ND]; // split-K partials (fp32)
__device__ float  g_ppa1[(size_t)NB * NE * ND];
__device__ float  g_ppb0[(size_t)NB * NE * ND];
__device__ float  g_ppb1[(size_t)NB * NE * ND];
__device__ __half g_ca  [(size_t)NB * NE * ND]; // class_a
__device__ __half g_cb  [(size_t)NB * NE * ND]; // class_b
__device__ float  g_afw [NB * NE];
__device__ float  g_bfw [NB * NE];
__device__ float  g_abw [NB * NL];
__device__ float  g_bbw [NB * NL];
__device__ __half g_xh  [(size_t)NB * NL * ND]; // x  (fp16)
__device__ __half g_wh  [(size_t)4 * ND * ND];  // Wk,Wa,Wb,Ws (fp16)
__device__ __half g_qh  [(size_t)NE * ND];      // q_emb (fp16)
__device__ __half g_qwh [(size_t)NE * ND];      // q_emb @ Wk (fp16)
__device__ float  g_qbv [NE];                   // q_emb . bk

// pads (in halves)
#define PADH  72    // [m/n][k] rows, BK=64 halves
#define PADNH 136   // [k][n] rows, 128 n-halves

// ============================================================================
// helpers
// ============================================================================
__device__ __forceinline__ uint32_t smem_u32(const void* p) {
    uint32_t a;
    asm("{ .reg .u64 t; cvta.to.shared.u64 t, %1; cvt.u32.u64 %0, t; }"
        : "=r"(a) : "l"(p));
    return a;
}

__device__ __forceinline__ void cp_async16(uint32_t dst, const void* src) {
    asm volatile("cp.async.cg.shared.global [%0], [%1], 16;" :: "r"(dst), "l"(src));
}

__device__ __forceinline__ void mma_f16(float* d, const uint32_t* a, const uint32_t* b) {
    asm volatile(
        "mma.sync.aligned.m16n8k16.row.col.f32.f16.f16.f32 "
        "{%0,%1,%2,%3}, {%4,%5,%6,%7}, {%8,%9}, {%0,%1,%2,%3};\n"
        : "+f"(d[0]), "+f"(d[1]), "+f"(d[2]), "+f"(d[3])
        : "r"(a[0]), "r"(a[1]), "r"(a[2]), "r"(a[3]), "r"(b[0]), "r"(b[1]));
}

// dual 16-bit load for [k][n] smem layouts: {B[k][n], B[k+1][n]}
__device__ __forceinline__ uint32_t ldpair(const __half* base, int k, int n, int strideH) {
    uint16_t lo = *(const uint16_t*)(base + (size_t)k * strideH + n);
    uint16_t hi = *(const uint16_t*)(base + (size_t)(k + 1) * strideH + n);
    return (uint32_t)lo | ((uint32_t)hi << 16);
}

// ============================================================================
// Kernel 0: fp32 -> fp16 conversion prepass
// ============================================================================
__global__ __launch_bounds__(256) void k_cvt_h(const float* __restrict__ src,
                                               __half* __restrict__ dst, int n4)
{
    int i = blockIdx.x * 256 + threadIdx.x;
    if (i >= n4) return;
    float4 v = ((const float4*)src)[i];
    __half2 h0 = __floats2half2_rn(v.x, v.y);
    __half2 h1 = __floats2half2_rn(v.z, v.w);
    ((uint2*)dst)[i] = make_uint2(*(uint32_t*)&h0, *(uint32_t*)&h1);
}

__global__ __launch_bounds__(256) void k_cvt4_h(
    const float* __restrict__ w0, const float* __restrict__ w1,
    const float* __restrict__ w2, const float* __restrict__ w3)
{
    const float* srcs[4] = { w0, w1, w2, w3 };
    const float* src = srcs[blockIdx.y];
    __half* dst = g_wh + (size_t)blockIdx.y * ND * ND;
    int i = blockIdx.x * 256 + threadIdx.x;
    float4 v = ((const float4*)src)[i];
    __half2 h0 = __floats2half2_rn(v.x, v.y);
    __half2 h1 = __floats2half2_rn(v.z, v.w);
    ((uint2*)dst)[i] = make_uint2(*(uint32_t*)&h0, *(uint32_t*)&h1);
}

// ============================================================================
// Kernel A: selector GEMM + sigmoid.  g_selh = sigmoid(x @ Ws^T + bs)
// fp16 mma. CTA 128x128, 8 warps (2x4), warp tile 64x32, BK=64 halves,
// 3-stage ring, 110.6 KB smem => 2 CTAs/SM.
// ============================================================================
#define SG_STG_H ((128 + 128) * PADH)
#define SG_SMEM (3 * SG_STG_H * 2)      // 110,592 B

__global__ __launch_bounds__(256, 2) void k_selgemm(const float* __restrict__ bs)
{
    extern __shared__ __half smh[];

    const int n0 = blockIdx.x * 128;
    const int m0 = blockIdx.y * 128;
    const __half* Wt = g_wh + (size_t)3 * ND * ND;

    const int tid = threadIdx.x;
    const int wid = tid >> 5, lane = tid & 31;
    const int wm = wid >> 2, wn = wid & 3;     // 2 x 4
    const int g = lane >> 2, tg = lane & 3;

    const uint32_t sb = smem_u32(smh);

    float acc[4][4][4];
    #pragma unroll
    for (int mt = 0; mt < 4; mt++)
        #pragma unroll
        for (int nt = 0; nt < 4; nt++)
            #pragma unroll
            for (int r = 0; r < 4; r++) acc[mt][nt][r] = 0.f;

    const int ldRow = tid >> 3;          // 0..31
    const int ldSeg = tid & 7;

    auto load_chunk = [&](int kc, int st) {
        const uint32_t s0 = sb + (uint32_t)(st * SG_STG_H) * 2u;
        const uint32_t bB = s0 + (uint32_t)(128 * PADH) * 2u;
        const __half* xs = g_xh + (size_t)m0 * 1024 + kc * 64;
        const __half* ws = Wt   + (size_t)n0 * 1024 + kc * 64;
        #pragma unroll
        for (int s = 0; s < 4; ++s) {
            int row = ldRow + s * 32;
            cp_async16(s0 + (uint32_t)(row * (PADH * 2) + ldSeg * 16),
                       xs + (size_t)row * 1024 + ldSeg * 8);
        }
        #pragma unroll
        for (int s = 0; s < 4; ++s) {
            int row = ldRow + s * 32;
            cp_async16(bB + (uint32_t)(row * (PADH * 2) + ldSeg * 16),
                       ws + (size_t)row * 1024 + ldSeg * 8);
        }
        asm volatile("cp.async.commit_group;" ::: "memory");
    };

    load_chunk(0, 0);
    load_chunk(1, 1);

    for (int it = 0; it < 16; ++it) {
        const int st = it % 3;
        if (it < 15) {
            asm volatile("cp.async.wait_group 1;" ::: "memory");
        } else {
            asm volatile("cp.async.wait_group 0;" ::: "memory");
        }
        __syncthreads();

        const __half* As = smh + st * SG_STG_H;
        const __half* Bs = As + 128 * PADH;

        #pragma unroll
        for (int ks = 0; ks < 4; ++ks) {
            const int kb = ks * 16;
            uint32_t afr[4][4];
            #pragma unroll
            for (int mt = 0; mt < 4; mt++) {
                const __half* ap = As + (wm * 64 + mt * 16 + g) * PADH + kb + 2 * tg;
                afr[mt][0] = *(const uint32_t*)ap;
                afr[mt][1] = *(const uint32_t*)(ap + 8 * PADH);
                afr[mt][2] = *(const uint32_t*)(ap + 8);
                afr[mt][3] = *(const uint32_t*)(ap + 8 * PADH + 8);
            }
            uint32_t bfr[4][2];
            #pragma unroll
            for (int nt = 0; nt < 4; nt++) {
                const __half* bp = Bs + (wn * 32 + nt * 8 + g) * PADH + kb + 2 * tg;
                bfr[nt][0] = *(const uint32_t*)bp;
                bfr[nt][1] = *(const uint32_t*)(bp + 8);
            }
            #pragma unroll
            for (int mt = 0; mt < 4; mt++)
                #pragma unroll
                for (int nt = 0; nt < 4; nt++)
                    mma_f16(acc[mt][nt], afr[mt], bfr[nt]);
        }

        if (it + 2 < 16) load_chunk(it + 2, (it + 2) % 3);
    }

    const int mBase = m0 + wm * 64;
    const int nBase = n0 + wn * 32;
    #pragma unroll
    for (int mt = 0; mt < 4; mt++) {
        #pragma unroll
        for (int nt = 0; nt < 4; nt++) {
            const int r0 = mBase + mt * 16 + g;
            const int c  = nBase + nt * 8 + 2 * tg;
            float2 bv = *(const float2*)(bs + c);
            float s00 = 1.f / (1.f + expf(-(acc[mt][nt][0] + bv.x)));
            float s01 = 1.f / (1.f + expf(-(acc[mt][nt][1] + bv.y)));
            float s10 = 1.f / (1.f + expf(-(acc[mt][nt][2] + bv.x)));
            float s11 = 1.f / (1.f + expf(-(acc[mt][nt][3] + bv.y)));
            *(__half2*)(g_selh + (size_t)r0 * 1024 + c)       = __floats2half2_rn(s00, s01);
            *(__half2*)(g_selh + (size_t)(r0 + 8) * 1024 + c) = __floats2half2_rn(s10, s11);
        }
    }
}

// ============================================================================
// Kernel B: class projections  g_c{a,b} = P @ W{a,b}^T + S*b{a,b} + b_emb[idx]
// ============================================================================
__global__ __launch_bounds__(256, 2) void k_cproj(
    const int* __restrict__ n_idx, const float* __restrict__ b_emb,
    const float* __restrict__ ba, const float* __restrict__ bb)
{
    extern __shared__ __half smh[];

    const int n0 = blockIdx.x * 128;
    const int m0 = blockIdx.y * 128;
    const int side = blockIdx.z;
    const __half* P   = side ? g_pb  : g_pa;
    const float* sums = side ? g_bfw : g_afw;
    const float* bias = side ? bb    : ba;
    __half*      out  = side ? g_cb  : g_ca;
    const __half* Wt  = g_wh + (size_t)(side ? 2 : 1) * ND * ND;

    const int tid = threadIdx.x;
    const int wid = tid >> 5, lane = tid & 31;
    const int wm = wid >> 2, wn = wid & 3;
    const int g = lane >> 2, tg = lane & 3;

    float acc[4][4][4];
    #pragma unroll
    for (int mt = 0; mt < 4; mt++)
        #pragma unroll
        for (int nt = 0; nt < 4; nt++)
            #pragma unroll
            for (int r = 0; r < 4; r++) acc[mt][nt][r] = 0.f;

    const uint32_t sb = smem_u32(smh);
    const int ldRow = tid >> 3;
    const int ldSeg = tid & 7;

    auto load_chunk = [&](int kc, int st) {
        const uint32_t s0 = sb + (uint32_t)(st * SG_STG_H) * 2u;
        const uint32_t bB = s0 + (uint32_t)(128 * PADH) * 2u;
        const __half* xs = P  + (size_t)m0 * 1024 + kc * 64;
        const __half* ws = Wt + (size_t)n0 * 1024 + kc * 64;
        #pragma unroll
        for (int s = 0; s < 4; ++s) {
            int row = ldRow + s * 32;
            cp_async16(s0 + (uint32_t)(row * (PADH * 2) + ldSeg * 16),
                       xs + (size_t)row * 1024 + ldSeg * 8);
        }
        #pragma unroll
        for (int s = 0; s < 4; ++s) {
            int row = ldRow + s * 32;
            cp_async16(bB + (uint32_t)(row * (PADH * 2) + ldSeg * 16),
                       ws + (size_t)row * 1024 + ldSeg * 8);
        }
        asm volatile("cp.async.commit_group;" ::: "memory");
    };

    load_chunk(0, 0);
    load_chunk(1, 1);

    for (int it = 0; it < 16; ++it) {
        const int st = it % 3;
        if (it < 15) {
            asm volatile("cp.async.wait_group 1;" ::: "memory");
        } else {
            asm volatile("cp.async.wait_group 0;" ::: "memory");
        }
        __syncthreads();

        const __half* As = smh + st * SG_STG_H;
        const __half* Bs = As + 128 * PADH;

        #pragma unroll
        for (int ks = 0; ks < 4; ++ks) {
            const int kb = ks * 16;
            uint32_t afr[4][4];
            #pragma unroll
            for (int mt = 0; mt < 4; mt++) {
                const __half* ap = As + (wm * 64 + mt * 16 + g) * PADH + kb + 2 * tg;
                afr[mt][0] = *(const uint32_t*)ap;
                afr[mt][1] = *(const uint32_t*)(ap + 8 * PADH);
                afr[mt][2] = *(const uint32_t*)(ap + 8);
                afr[mt][3] = *(const uint32_t*)(ap + 8 * PADH + 8);
            }
            uint32_t bfr[4][2];
            #pragma unroll
            for (int nt = 0; nt < 4; nt++) {
                const __half* bp = Bs + (wn * 32 + nt * 8 + g) * PADH + kb + 2 * tg;
                bfr[nt][0] = *(const uint32_t*)bp;
                bfr[nt][1] = *(const uint32_t*)(bp + 8);
            }
            #pragma unroll
            for (int mt = 0; mt < 4; mt++)
                #pragma unroll
                for (int nt = 0; nt < 4; nt++)
                    mma_f16(acc[mt][nt], afr[mt], bfr[nt]);
        }

        if (it + 2 < 16) load_chunk(it + 2, (it + 2) % 3);
    }

    const int mBase = m0 + wm * 64;
    const int nBase = n0 + wn * 32;
    #pragma unroll
    for (int mt = 0; mt < 4; mt++) {
        const int r0 = mBase + mt * 16 + g;
        const int b  = r0 >> 6;
        const int e0 = r0 & 63;
        float s0v = sums[b * 64 + e0];
        float s1v = sums[b * 64 + e0 + 8];
        float S0 = s0v / (s0v + 1e-9f);
        float S1 = s1v / (s1v + 1e-9f);
        const float* br0 = b_emb + (size_t)n_idx[b * 64 + e0] * 1024;
        const float* br1 = b_emb + (size_t)n_idx[b * 64 + e0 + 8] * 1024;
        #pragma unroll
        for (int nt = 0; nt < 4; nt++) {
            const int c = nBase + nt * 8 + 2 * tg;
            float2 bv = *(const float2*)(bias + c);
            float2 e0v = *(const float2*)(br0 + c);
            float2 e1v = *(const float2*)(br1 + c);
            *(__half2*)(out + (size_t)r0 * 1024 + c) = __floats2half2_rn(
                acc[mt][nt][0] + S0 * bv.x + e0v.x,
                acc[mt][nt][1] + S0 * bv.y + e0v.y);
            *(__half2*)(out + (size_t)(r0 + 8) * 1024 + c) = __floats2half2_rn(
                acc[mt][nt][2] + S1 * bv.x + e1v.x,
                acc[mt][nt][3] + S1 * bv.y + e1v.y);
        }
    }
}

// ============================================================================
// Kernel C: qw = q_emb @ Wk  (M=64(e), N=1024(d), K=1024(j)). B=[k][n]. grid(8).
// ============================================================================
#define QW_STG_H (64 * PADH + 64 * PADNH)
#define QW_SMEM (2 * QW_STG_H * 2)

__global__ __launch_bounds__(256) void k_qw()
{
    extern __shared__ __half smh[];
    const int n0 = blockIdx.x * 128;

    const int tid = threadIdx.x;
    const int wid = tid >> 5, lane = tid & 31;
    const int wm = wid >> 2, wn = wid & 3;
    const int g = lane >> 2, tg = lane & 3;

    const uint32_t sb = smem_u32(smh);

    float acc[2][4][4];
    #pragma unroll
    for (int mt = 0; mt < 2; mt++)
        #pragma unroll
        for (int nt = 0; nt < 4; nt++)
            #pragma unroll
            for (int r = 0; r < 4; r++) acc[mt][nt][r] = 0.f;

    const int aRow = tid >> 3;
    const int aSeg = tid & 7;

    auto load_chunk = [&](int kc, int st) {
        const uint32_t s0 = sb + (uint32_t)(st * QW_STG_H) * 2u;
        const uint32_t bB = s0 + (uint32_t)(64 * PADH) * 2u;
        cp_async16(s0 + (uint32_t)(aRow * (PADH * 2) + aSeg * 16),
                   g_qh + (size_t)aRow * 1024 + kc * 64 + aSeg * 8);
        cp_async16(s0 + (uint32_t)((aRow + 32) * (PADH * 2) + aSeg * 16),
                   g_qh + (size_t)(aRow + 32) * 1024 + kc * 64 + aSeg * 8);
        #pragma unroll
        for (int s = 0; s < 4; ++s) {
            int slot = tid + s * 256;
            int row = slot >> 4, seg = slot & 15;
            cp_async16(bB + (uint32_t)(row * (PADNH * 2) + seg * 16),
                       g_wh + (size_t)(kc * 64 + row) * 1024 + n0 + seg * 8);
        }
        asm volatile("cp.async.commit_group;" ::: "memory");
    };

    load_chunk(0, 0);

    for (int it = 0; it < 16; ++it) {
        const int buf = it & 1;
        if (it + 1 < 16) {
            load_chunk(it + 1, buf ^ 1);
            asm volatile("cp.async.wait_group 1;" ::: "memory");
        } else {
            asm volatile("cp.async.wait_group 0;" ::: "memory");
        }
        __syncthreads();

        const __half* As = smh + buf * QW_STG_H;
        const __half* Bs = As + 64 * PADH;

        #pragma unroll
        for (int ks = 0; ks < 4; ++ks) {
            const int kb = ks * 16;
            uint32_t afr[2][4];
            #pragma unroll
            for (int mt = 0; mt < 2; mt++) {
                const __half* ap = As + (wm * 32 + mt * 16 + g) * PADH + kb + 2 * tg;
                afr[mt][0] = *(const uint32_t*)ap;
                afr[mt][1] = *(const uint32_t*)(ap + 8 * PADH);
                afr[mt][2] = *(const uint32_t*)(ap + 8);
                afr[mt][3] = *(const uint32_t*)(ap + 8 * PADH + 8);
            }
            uint32_t bfr[4][2];
            #pragma unroll
            for (int nt = 0; nt < 4; nt++) {
                const int n = wn * 32 + nt * 8 + g;
                bfr[nt][0] = ldpair(Bs, kb + 2 * tg, n, PADNH);
                bfr[nt][1] = ldpair(Bs, kb + 2 * tg + 8, n, PADNH);
            }
            #pragma unroll
            for (int mt = 0; mt < 2; mt++)
                #pragma unroll
                for (int nt = 0; nt < 4; nt++)
                    mma_f16(acc[mt][nt], afr[mt], bfr[nt]);
        }
        __syncthreads();
    }

    #pragma unroll
    for (int mt = 0; mt < 2; mt++) {
        const int e0 = wm * 32 + mt * 16 + g;
        #pragma unroll
        for (int nt = 0; nt < 4; nt++) {
            const int c = n0 + wn * 32 + nt * 8 + 2 * tg;
            *(__half2*)(g_qwh + (size_t)e0 * 1024 + c) =
                __floats2half2_rn(acc[mt][nt][0], acc[mt][nt][1]);
            *(__half2*)(g_qwh + (size_t)(e0 + 8) * 1024 + c) =
                __floats2half2_rn(acc[mt][nt][2], acc[mt][nt][3]);
        }
    }
}

// Kernel C2: qb[e] = q_emb[e] . bk ; also zero fwsum accumulators
__global__ void k_qb(const float* __restrict__ q_emb, const float* __restrict__ bk)
{
    int t = threadIdx.x;                 // 1024 threads
    g_afw[t] = 0.f;
    g_bfw[t] = 0.f;
    if (t < 64) {
        float s = 0.f;
        const float* qr = q_emb + (size_t)t * 1024;
        for (int d = 0; d < 1024; ++d) s += qr[d] * bk[d];
        g_qbv[t] = s;
    }
}

// ============================================================================
// Kernel D: z[b,e,l] = (qwh[idx[b,e]] . xh[b,l] + qb[idx]) / 32
// Epilogue also computes fwsums (masked, atomicAdd) and bwsums (direct).
// ============================================================================
#define Z_STG_H ((64 + 128) * PADH)
#define Z_SMEM (2 * Z_STG_H * 2)

__global__ __launch_bounds__(256) void k_zgemm(const int* __restrict__ n_idx,
                                               const int* __restrict__ mask)
{
    extern __shared__ __half smh[];
    const int b  = blockIdx.y;
    const int l0 = blockIdx.x * 128;
    const int tid = threadIdx.x;
    const int wid = tid >> 5, lane = tid & 31;
    const int wm = wid >> 2, wn = wid & 3;
    const int g = lane >> 2, tg = lane & 3;

    const uint32_t sb = smem_u32(smh);

    float acc[2][4][4];
    #pragma unroll
    for (int mt = 0; mt < 2; mt++)
        #pragma unroll
        for (int nt = 0; nt < 4; nt++)
            #pragma unroll
            for (int r = 0; r < 4; r++) acc[mt][nt][r] = 0.f;

    const int aRow = tid >> 3;
    const int aSeg = tid & 7;
    const __half* aSrc0 = g_qwh + (size_t)n_idx[b * 64 + aRow] * 1024;
    const __half* aSrc1 = g_qwh + (size_t)n_idx[b * 64 + aRow + 32] * 1024;

    auto load_chunk = [&](int kc, int st) {
        const uint32_t s0 = sb + (uint32_t)(st * Z_STG_H) * 2u;
        const uint32_t bB = s0 + (uint32_t)(64 * PADH) * 2u;
        cp_async16(s0 + (uint32_t)(aRow * (PADH * 2) + aSeg * 16), aSrc0 + kc * 64 + aSeg * 8);
        cp_async16(s0 + (uint32_t)((aRow + 32) * (PADH * 2) + aSeg * 16), aSrc1 + kc * 64 + aSeg * 8);
        const __half* xs = g_xh + ((size_t)b * 2048 + l0) * 1024 + kc * 64;
        #pragma unroll
        for (int s = 0; s < 4; ++s) {
            int row = aRow + s * 32;
            cp_async16(bB + (uint32_t)(row * (PADH * 2) + aSeg * 16),
                       xs + (size_t)row * 1024 + aSeg * 8);
        }
        asm volatile("cp.async.commit_group;" ::: "memory");
    };

    load_chunk(0, 0);

    for (int it = 0; it < 16; ++it) {
        const int buf = it & 1;
        if (it + 1 < 16) {
            load_chunk(it + 1, buf ^ 1);
            asm volatile("cp.async.wait_group 1;" ::: "memory");
        } else {
            asm volatile("cp.async.wait_group 0;" ::: "memory");
        }
        __syncthreads();

        const __half* As = smh + buf * Z_STG_H;
        const __half* Bs = As + 64 * PADH;

        #pragma unroll
        for (int ks = 0; ks < 4; ++ks) {
            const int kb = ks * 16;
            uint32_t afr[2][4];
            #pragma unroll
            for (int mt = 0; mt < 2; mt++) {
                const __half* ap = As + (wm * 32 + mt * 16 + g) * PADH + kb + 2 * tg;
                afr[mt][0] = *(const uint32_t*)ap;
                afr[mt][1] = *(const uint32_t*)(ap + 8 * PADH);
                afr[mt][2] = *(const uint32_t*)(ap + 8);
                afr[mt][3] = *(const uint32_t*)(ap + 8 * PADH + 8);
            }
            uint32_t bfr[4][2];
            #pragma unroll
            for (int nt = 0; nt < 4; nt++) {
                const __half* bp = Bs + (wn * 32 + nt * 8 + g) * PADH + kb + 2 * tg;
                bfr[nt][0] = *(const uint32_t*)bp;
                bfr[nt][1] = *(const uint32_t*)(bp + 8);
            }
            #pragma unroll
            for (int mt = 0; mt < 2; mt++)
                #pragma unroll
                for (int nt = 0; nt < 4; nt++)
                    mma_f16(acc[mt][nt], afr[mt], bfr[nt]);
        }
        __syncthreads();
    }

    // ---- epilogue: z values + fused reductions ----
    float vz[2][4][4];
    #pragma unroll
    for (int mt = 0; mt < 2; mt++) {
        const int e = wm * 32 + mt * 16 + g;
        const float qb0 = g_qbv[n_idx[b * 64 + e]];
        const float qb1 = g_qbv[n_idx[b * 64 + e + 8]];
        #pragma unroll
        for (int nt = 0; nt < 4; nt++) {
            vz[mt][nt][0] = (acc[mt][nt][0] + qb0) * 0.03125f;
            vz[mt][nt][1] = (acc[mt][nt][1] + qb0) * 0.03125f;
            vz[mt][nt][2] = (acc[mt][nt][2] + qb1) * 0.03125f;
            vz[mt][nt][3] = (acc[mt][nt][3] + qb1) * 0.03125f;
            const int l = l0 + wn * 32 + nt * 8 + 2 * tg;
            *(float2*)(g_z + ((size_t)b * 64 + e) * 2048 + l) =
                make_float2(vz[mt][nt][0], vz[mt][nt][1]);
            *(float2*)(g_z + ((size_t)b * 64 + e + 8) * 2048 + l) =
                make_float2(vz[mt][nt][2], vz[mt][nt][3]);
        }
    }

    // load masks for this thread's 8 l positions
    int msk[4][2];
    #pragma unroll
    for (int nt = 0; nt < 4; nt++) {
        const int l = l0 + wn * 32 + nt * 8 + 2 * tg;
        msk[nt][0] = mask[b * 2048 + l];
        msk[nt][1] = mask[b * 2048 + l + 1];
    }

    // reduction buffers in smem (reuse tile memory; tile no longer needed)
    float* red = (float*)smh;   // [0:64) fwA, [64:128) fwB, [128:256) bwA, [256:384) bwB
    red[tid] = 0.f;                       // 0..255
    if (tid < 128) red[256 + tid] = 0.f;  // 256..383  (FIX: was if(tid<384) with 256 thr)
    __syncthreads();

    // fw: masked relu sums over l; per (mt, row-half) reduce over nt,j then tg
    #pragma unroll
    for (int mt = 0; mt < 2; mt++) {
        #pragma unroll
        for (int rr = 0; rr < 2; rr++) {     // row 0 / +8
            float fa = 0.f, fb = 0.f;
            #pragma unroll
            for (int nt = 0; nt < 4; nt++) {
                #pragma unroll
                for (int j = 0; j < 2; j++) {
                    float v = vz[mt][nt][rr * 2 + j];
                    if (msk[nt][j]) { fa += fmaxf(v, 0.f); fb += fmaxf(-v, 0.f); }
                }
            }
            fa += __shfl_xor_sync(0xffffffffu, fa, 1);
            fa += __shfl_xor_sync(0xffffffffu, fa, 2);
            fb += __shfl_xor_sync(0xffffffffu, fb, 1);
            fb += __shfl_xor_sync(0xffffffffu, fb, 2);
            if (tg == 0) {
                const int e = wm * 32 + mt * 16 + g + rr * 8;
                atomicAdd(&red[e], fa);
                atomicAdd(&red[64 + e], fb);
            }
        }
    }

    // bw: unmasked relu sums over e; per (nt, j) reduce over mt,rr then g
    #pragma unroll
    for (int nt = 0; nt < 4; nt++) {
        #pragma unroll
        for (int j = 0; j < 2; j++) {
            float ba_ = 0.f, bb_ = 0.f;
            #pragma unroll
            for (int mt = 0; mt < 2; mt++) {
                #pragma unroll
                for (int rr = 0; rr < 2; rr++) {
                    float v = vz[mt][nt][rr * 2 + j];
                    ba_ += fmaxf(v, 0.f);
                    bb_ += fmaxf(-v, 0.f);
                }
            }
            ba_ += __shfl_xor_sync(0xffffffffu, ba_, 4);
            ba_ += __shfl_xor_sync(0xffffffffu, ba_, 8);
            ba_ += __shfl_xor_sync(0xffffffffu, ba_, 16);
            bb_ += __shfl_xor_sync(0xffffffffu, bb_, 4);
            bb_ += __shfl_xor_sync(0xffffffffu, bb_, 8);
            bb_ += __shfl_xor_sync(0xffffffffu, bb_, 16);
            if (g == 0) {
                const int li = wn * 32 + nt * 8 + 2 * tg + j;
                atomicAdd(&red[128 + li], ba_);
                atomicAdd(&red[256 + li], bb_);
            }
        }
    }
    __syncthreads();

    if (tid < 64) {
        atomicAdd(&g_afw[b * 64 + tid], red[tid]);
        atomicAdd(&g_bfw[b * 64 + tid], red[64 + tid]);
    } else if (tid < 192) {
        const int li = tid - 64;
        g_abw[b * 2048 + l0 + li] = red[128 + li];
        g_bbw[b * 2048 + l0 + li] = red[256 + li];
    }
}

// ============================================================================
// Kernel E: split-K P GEMM.  partials = A_{a,b} @ x over K half (no norm).
// grid (8, 16, 2): x=d-block, y=b, z=K half. M=64(e), N=128(d), K=1024.
// ============================================================================
#define PG_STG_H (2 * 64 * PADH + 64 * PADNH)
#define PG_SMEM (2 * PG_STG_H * 2)

__global__ __launch_bounds__(256) void k_pgemm2(const int* __restrict__ mask)
{
    extern __shared__ __half smh[];
    const int b  = blockIdx.y;
    const int n0 = blockIdx.x * 128;
    const int kh = blockIdx.z;                 // K half: 0 or 1
    float* outA = kh ? g_ppa1 : g_ppa0;
    float* outB = kh ? g_ppb1 : g_ppb0;

    const int tid = threadIdx.x;
    const int wid = tid >> 5, lane = tid & 31;
    const int wm = wid >> 2, wn = wid & 3;
    const int g = lane >> 2, tg = lane & 3;

    const uint32_t sb = smem_u32(smh);

    float accA[2][4][4], accB[2][4][4];
    #pragma unroll
    for (int mt = 0; mt < 2; mt++)
        #pragma unroll
        for (int nt = 0; nt < 4; nt++)
            #pragma unroll
            for (int r = 0; r < 4; r++) { accA[mt][nt][r] = 0.f; accB[mt][nt][r] = 0.f; }

    const int aE = tid >> 2;
    const int aC = (tid & 3) * 16;
    const float* zrow = g_z + ((size_t)b * 64 + aE) * 2048;
    const int* mrow = mask + b * 2048;
    const int kBase = kh * 1024;

    auto load_chunk = [&](int kc, int st) {
        __half* Aa = smh + st * PG_STG_H;
        __half* Ab = Aa + 64 * PADH;
        const uint32_t bB = sb + (uint32_t)(st * PG_STG_H + 2 * 64 * PADH) * 2u;
        const int kk = kBase + kc * 64;
        __half ha[16], hb[16];
        #pragma unroll
        for (int q = 0; q < 4; ++q) {
            float4 v = *(const float4*)(zrow + kk + aC + q * 4);
            int4 m = *(const int4*)(mrow + kk + aC + q * 4);
            float vv[4] = { v.x, v.y, v.z, v.w };
            int   mm[4] = { m.x, m.y, m.z, m.w };
            #pragma unroll
            for (int j = 0; j < 4; ++j) {
                ha[q * 4 + j] = __float2half_rn(mm[j] ? fmaxf(vv[j], 0.f) : 0.f);
                hb[q * 4 + j] = __float2half_rn(mm[j] ? fmaxf(-vv[j], 0.f) : 0.f);
            }
        }
        *(uint4*)(Aa + aE * PADH + aC)     = *(uint4*)ha;
        *(uint4*)(Aa + aE * PADH + aC + 8) = *(uint4*)(ha + 8);
        *(uint4*)(Ab + aE * PADH + aC)     = *(uint4*)hb;
        *(uint4*)(Ab + aE * PADH + aC + 8) = *(uint4*)(hb + 8);
        const __half* xs = g_xh + ((size_t)b * 2048 + kk) * 1024 + n0;
        #pragma unroll
        for (int s = 0; s < 4; ++s) {
            int slot = tid + s * 256;
            int row = slot >> 4, seg = slot & 15;
            cp_async16(bB + (uint32_t)(row * (PADNH * 2) + seg * 16),
                       xs + (size_t)row * 1024 + seg * 8);
        }
        asm volatile("cp.async.commit_group;" ::: "memory");
    };

    load_chunk(0, 0);

    for (int it = 0; it < 16; ++it) {
        const int buf = it & 1;
        if (it + 1 < 16) {
            load_chunk(it + 1, buf ^ 1);
            asm volatile("cp.async.wait_group 1;" ::: "memory");
        } else {
            asm volatile("cp.async.wait_group 0;" ::: "memory");
        }
        __syncthreads();

        const __half* Aa = smh + buf * PG_STG_H;
        const __half* Ab = Aa + 64 * PADH;
        const __half* Bs = Ab + 64 * PADH;

        #pragma unroll
        for (int ks = 0; ks < 4; ++ks) {
            const int kb = ks * 16;
            uint32_t afa[2][4], afb[2][4];
            #pragma unroll
            for (int mt = 0; mt < 2; mt++) {
                const __half* pa = Aa + (wm * 32 + mt * 16 + g) * PADH + kb + 2 * tg;
                const __half* pb = Ab + (wm * 32 + mt * 16 + g) * PADH + kb + 2 * tg;
                afa[mt][0] = *(const uint32_t*)pa;
                afa[mt][1] = *(const uint32_t*)(pa + 8 * PADH);
                afa[mt][2] = *(const uint32_t*)(pa + 8);
                afa[mt][3] = *(const uint32_t*)(pa + 8 * PADH + 8);
                afb[mt][0] = *(const uint32_t*)pb;
                afb[mt][1] = *(const uint32_t*)(pb + 8 * PADH);
                afb[mt][2] = *(const uint32_t*)(pb + 8);
                afb[mt][3] = *(const uint32_t*)(pb + 8 * PADH + 8);
            }
            uint32_t bfr[4][2];
            #pragma unroll
            for (int nt = 0; nt < 4; nt++) {
                const int n = wn * 32 + nt * 8 + g;
                bfr[nt][0] = ldpair(Bs, kb + 2 * tg, n, PADNH);
                bfr[nt][1] = ldpair(Bs, kb + 2 * tg + 8, n, PADNH);
            }
            #pragma unroll
            for (int mt = 0; mt < 2; mt++)
                #pragma unroll
                for (int nt = 0; nt < 4; nt++) {
                    mma_f16(accA[mt][nt], afa[mt], bfr[nt]);
                    mma_f16(accB[mt][nt], afb[mt], bfr[nt]);
                }
        }
        __syncthreads();
    }

    #pragma unroll
    for (int mt = 0; mt < 2; mt++) {
        const int e0 = wm * 32 + mt * 16 + g;
        #pragma unroll
        for (int nt = 0; nt < 4; nt++) {
            const int d = n0 + wn * 32 + nt * 8 + 2 * tg;
            *(float2*)(outA + ((size_t)b * 64 + e0) * 1024 + d) =
                make_float2(accA[mt][nt][0], accA[mt][nt][1]);
            *(float2*)(outA + ((size_t)b * 64 + e0 + 8) * 1024 + d) =
                make_float2(accA[mt][nt][2], accA[mt][nt][3]);
            *(float2*)(outB + ((size_t)b * 64 + e0) * 1024 + d) =
                make_float2(accB[mt][nt][0], accB[mt][nt][1]);
            *(float2*)(outB + ((size_t)b * 64 + e0 + 8) * 1024 + d) =
                make_float2(accB[mt][nt][2], accB[mt][nt][3]);
        }
    }
}

// Kernel E2: combine split-K partials + normalize -> fp16 g_pa/g_pb
__global__ __launch_bounds__(256) void k_psum()
{
    const int i = blockIdx.x * 256 + threadIdx.x;   // float4 index
    const int idx = i * 4;
    const int e = (idx >> 10) & 63;
    const int b = idx >> 16;
    const float ia = 1.f / (g_afw[b * 64 + e] + 1e-9f);
    const float ib = 1.f / (g_bfw[b * 64 + e] + 1e-9f);
    float4 a0 = ((const float4*)g_ppa0)[i];
    float4 a1 = ((const float4*)g_ppa1)[i];
    float4 b0 = ((const float4*)g_ppb0)[i];
    float4 b1 = ((const float4*)g_ppb1)[i];
    __half2 ha0 = __floats2half2_rn((a0.x + a1.x) * ia, (a0.y + a1.y) * ia);
    __half2 ha1 = __floats2half2_rn((a0.z + a1.z) * ia, (a0.w + a1.w) * ia);
    __half2 hb0 = __floats2half2_rn((b0.x + b1.x) * ib, (b0.y + b1.y) * ib);
    __half2 hb1 = __floats2half2_rn((b0.z + b1.z) * ib, (b0.w + b1.w) * ib);
    ((uint2*)g_pa)[i] = make_uint2(*(uint32_t*)&ha0, *(uint32_t*)&ha1);
    ((uint2*)g_pb)[i] = make_uint2(*(uint32_t*)&hb0, *(uint32_t*)&hb1);
}

// ============================================================================
// Kernel 6: final mix (fp16 mma). M=64(l), N=128(d), K=64(e). Single shot.
// ============================================================================
#define FN_SMEM ((2 * 64 * PADH + 2 * 64 * PADNH) * 2)

__global__ __launch_bounds__(256) void k_final(float* __restrict__ out)
{
    extern __shared__ __half smh[];
    __half* Aa = smh;
    __half* Ab = Aa + 64 * PADH;
    __half* Ba = Ab + 64 * PADH;
    __half* Bb = Ba + 64 * PADNH;

    const int b  = blockIdx.z;
    const int l0 = blockIdx.y * 64;
    const int d0 = blockIdx.x * 128;
    const int tid = threadIdx.x;
    const int wid = tid >> 5, lane = tid & 31;
    const int wm = wid >> 2, wn = wid & 3;
    const int g = lane >> 2, tg = lane & 3;

    {
        const int e  = tid & 63;
        const int lc = (tid >> 6) * 16;
        const float* zp = g_z + ((size_t)b * 64 + e) * 2048 + l0 + lc;
        #pragma unroll
        for (int j = 0; j < 4; ++j) {
            float4 v = *(const float4*)(zp + j * 4);
            float vv[4] = { v.x, v.y, v.z, v.w };
            #pragma unroll
            for (int t = 0; t < 4; ++t) {
                int l = lc + j * 4 + t;
                Aa[l * PADH + e] = __float2half_rn(fmaxf(vv[t], 0.f));
                Ab[l * PADH + e] = __float2half_rn(fmaxf(-vv[t], 0.f));
            }
        }
    }
    {
        const uint32_t baU = smem_u32(Ba);
        const uint32_t bbU = smem_u32(Bb);
        const __half* caP = g_ca + ((size_t)b * 64) * 1024 + d0;
        const __half* cbP = g_cb + ((size_t)b * 64) * 1024 + d0;
        #pragma unroll
        for (int s = 0; s < 4; ++s) {
            int slot = tid + s * 256;
            int row = slot >> 4, seg = slot & 15;
            uint32_t doff = (uint32_t)(row * (PADNH * 2) + seg * 16);
            cp_async16(baU + doff, caP + (size_t)row * 1024 + seg * 8);
            cp_async16(bbU + doff, cbP + (size_t)row * 1024 + seg * 8);
        }
        asm volatile("cp.async.commit_group;" ::: "memory");
        asm volatile("cp.async.wait_group 0;" ::: "memory");
    }
    __syncthreads();

    float aca[2][4][4], acb[2][4][4];
    #pragma unroll
    for (int mt = 0; mt < 2; mt++)
        #pragma unroll
        for (int nt = 0; nt < 4; nt++)
            #pragma unroll
            for (int r = 0; r < 4; r++) { aca[mt][nt][r] = 0.f; acb[mt][nt][r] = 0.f; }

    #pragma unroll
    for (int ks = 0; ks < 4; ++ks) {
        const int kb = ks * 16;
        uint32_t afa[2][4], afb[2][4];
        #pragma unroll
        for (int mt = 0; mt < 2; mt++) {
            const __half* pa = Aa + (wm * 32 + mt * 16 + g) * PADH + kb + 2 * tg;
            const __half* pb = Ab + (wm * 32 + mt * 16 + g) * PADH + kb + 2 * tg;
            afa[mt][0] = *(const uint32_t*)pa;
            afa[mt][1] = *(const uint32_t*)(pa + 8 * PADH);
            afa[mt][2] = *(const uint32_t*)(pa + 8);
            afa[mt][3] = *(const uint32_t*)(pa + 8 * PADH + 8);
            afb[mt][0] = *(const uint32_t*)pb;
            afb[mt][1] = *(const uint32_t*)(pb + 8 * PADH);
            afb[mt][2] = *(const uint32_t*)(pb + 8);
            afb[mt][3] = *(const uint32_t*)(pb + 8 * PADH + 8);
        }
        uint32_t bfa[4][2], bfb[4][2];
        #pragma unroll
        for (int nt = 0; nt < 4; nt++) {
            const int n = wn * 32 + nt * 8 + g;
            bfa[nt][0] = ldpair(Ba, kb + 2 * tg, n, PADNH);
            bfa[nt][1] = ldpair(Ba, kb + 2 * tg + 8, n, PADNH);
            bfb[nt][0] = ldpair(Bb, kb + 2 * tg, n, PADNH);
            bfb[nt][1] = ldpair(Bb, kb + 2 * tg + 8, n, PADNH);
        }
        #pragma unroll
        for (int mt = 0; mt < 2; mt++)
            #pragma unroll
            for (int nt = 0; nt < 4; nt++) {
                mma_f16(aca[mt][nt], afa[mt], bfa[nt]);
                mma_f16(acb[mt][nt], afb[mt], bfb[nt]);
            }
    }

    #pragma unroll
    for (int mt = 0; mt < 2; mt++) {
        const int l0r = l0 + wm * 32 + mt * 16 + g;
        const float ia0 = 1.f / (g_abw[b * 2048 + l0r] + 1e-9f);
        const float ib0 = 1.f / (g_bbw[b * 2048 + l0r] + 1e-9f);
        const float ia1 = 1.f / (g_abw[b * 2048 + l0r + 8] + 1e-9f);
        const float ib1 = 1.f / (g_bbw[b * 2048 + l0r + 8] + 1e-9f);
        #pragma unroll
        for (int nt = 0; nt < 4; nt++) {
            const int d = d0 + wn * 32 + nt * 8 + 2 * tg;
            float2 sg0 = __half22float2(*(const __half2*)(g_selh + ((size_t)b * 2048 + l0r) * 1024 + d));
            float2 sg1 = __half22float2(*(const __half2*)(g_selh + ((size_t)b * 2048 + l0r + 8) * 1024 + d));
            float2 o0 = make_float2(
                sg0.x * (aca[mt][nt][0] * ia0) + (1.f - sg0.x) * (acb[mt][nt][0] * ib0),
                sg0.y * (aca[mt][nt][1] * ia0) + (1.f - sg0.y) * (acb[mt][nt][1] * ib0));
            float2 o1 = make_float2(
                sg1.x * (aca[mt][nt][2] * ia1) + (1.f - sg1.x) * (acb[mt][nt][2] * ib1),
                sg1.y * (aca[mt][nt][3] * ia1) + (1.f - sg1.y) * (acb[mt][nt][3] * ib1));
            *(float2*)(out + ((size_t)b * 2048 + l0r) * 1024 + d)     = o0;
            *(float2*)(out + ((size_t)b * 2048 + l0r + 8) * 1024 + d) = o1;
        }
    }
}

// ============================================================================
extern "C" void kernel_launch(void* const* d_in, const int* in_sizes, int n_in,
                              void* d_out, int out_size)
{
    const float* x     = (const float*)d_in[0];
    const int*   n_idx = (const int*)  d_in[1];
    const int*   mask  = (const int*)  d_in[2];
    const float* q_emb = (const float*)d_in[3];
    const float* b_emb = (const float*)d_in[4];
    const float* Wk    = (const float*)d_in[5];
    const float* bk    = (const float*)d_in[6];
    const float* Wa    = (const float*)d_in[7];
    const float* ba    = (const float*)d_in[8];
    const float* Wb    = (const float*)d_in[9];
    const float* bb    = (const float*)d_in[10];
    const float* Ws    = (const float*)d_in[11];
    const float* bs    = (const float*)d_in[12];
    float* out = (float*)d_out;

    __half *xh_p, *qh_p;
    cudaGetSymbolAddress((void**)&xh_p, g_xh);
    cudaGetSymbolAddress((void**)&qh_p, g_qh);

    cudaFuncSetAttribute(k_selgemm, cudaFuncAttributeMaxDynamicSharedMemorySize, SG_SMEM);
    cudaFuncSetAttribute(k_cproj,   cudaFuncAttributeMaxDynamicSharedMemorySize, SG_SMEM);
    cudaFuncSetAttribute(k_qw,      cudaFuncAttributeMaxDynamicSharedMemorySize, QW_SMEM);
    cudaFuncSetAttribute(k_zgemm,   cudaFuncAttributeMaxDynamicSharedMemorySize, Z_SMEM);
    cudaFuncSetAttribute(k_pgemm2,  cudaFuncAttributeMaxDynamicSharedMemorySize, PG_SMEM);
    cudaFuncSetAttribute(k_final,   cudaFuncAttributeMaxDynamicSharedMemorySize, FN_SMEM);

    // side stream + events (created once; per-call GPU work is identical)
    static cudaStream_t s2 = nullptr;
    static cudaEvent_t evFork = nullptr, evSel = nullptr;
    if (s2 == nullptr) {
        cudaStreamCreateWithFlags(&s2, cudaStreamNonBlocking);
        cudaEventCreateWithFlags(&evFork, cudaEventDisableTiming);
        cudaEventCreateWithFlags(&evSel, cudaEventDisableTiming);
    }

    // prepass on main (capture) stream
    k_cvt_h <<<(NB * NL * ND / 4 + 255) / 256, 256>>>(x, xh_p, NB * NL * ND / 4);
    k_cvt4_h<<<dim3(ND * ND / 4 / 256, 4),     256>>>(Wk, Wa, Wb, Ws);
    k_cvt_h <<<(NE * ND / 4 + 255) / 256,      256>>>(q_emb, qh_p, NE * ND / 4);

    // fork: selgemm on side stream, concurrent with the z-chain
    cudaEventRecord(evFork, 0);
    cudaStreamWaitEvent(s2, evFork, 0);
    k_selgemm<<<dim3(8, 256), 256, SG_SMEM, s2>>>(bs);
    cudaEventRecord(evSel, s2);

    // z-chain on main stream
    k_qw     <<<8,                256, QW_SMEM>>>();
    k_qb     <<<1,                1024>>>(q_emb, bk);
    k_zgemm  <<<dim3(16, 16),     256, Z_SMEM>>>(n_idx, mask);
    k_pgemm2 <<<dim3(8, 16, 2),   256, PG_SMEM>>>(mask);
    k_psum   <<<NB * NE * ND / 4 / 256, 256>>>();
    k_cproj  <<<dim3(8, 8, 2),    256, SG_SMEM>>>(n_idx, b_emb, ba, bb);

    // join: final needs selh + ca/cb + z + bw sums
    cudaStreamWaitEvent(0, evSel, 0);
    k_final  <<<dim3(8, 32, 16),  256, FN_SMEM>>>(out);
}

// round 17
// speedup vs baseline: 1.1432x; 1.0472x over previous
#include <cuda_runtime.h>
#include <cuda_fp16.h>
#include <cstdint>
#include <math.h>

// Problem constants
#define NB 16
#define NL 2048
#define ND 1024
#define NE 64

// ---------------- scratch (device globals; no runtime allocation) ----------------
__device__ __half g_selh[(size_t)NB * NL * ND]; // sigmoid(x @ Ws^T + bs)
__device__ float  g_z   [(size_t)NB * NE * NL]; // attention logits (fp32)
__device__ __half g_pa  [(size_t)NB * NE * ND]; // normalized A_fw @ x
__device__ __half g_pb  [(size_t)NB * NE * ND];
__device__ float  g_ppa0[(size_t)NB * NE * ND]; // split-K partials (fp32)
__device__ float  g_ppa1[(size_t)NB * NE * ND];
__device__ float  g_ppb0[(size_t)NB * NE * ND];
__device__ float  g_ppb1[(size_t)NB * NE * ND];
__device__ __half g_ca  [(size_t)NB * NE * ND]; // class_a
__device__ __half g_cb  [(size_t)NB * NE * ND]; // class_b
__device__ float  g_afw [NB * NE];
__device__ float  g_bfw [NB * NE];
__device__ float  g_abw [NB * NL];
__device__ float  g_bbw [NB * NL];
__device__ __half g_xh  [(size_t)NB * NL * ND]; // x  (fp16)
__device__ __half g_wh  [(size_t)4 * ND * ND];  // Wk,Wa,Wb,Ws (fp16)
__device__ __half g_qh  [(size_t)NE * ND];      // q_emb (fp16)
__device__ __half g_qwh [(size_t)NE * ND];      // q_emb @ Wk (fp16)
__device__ float  g_qbv [NE];                   // q_emb . bk

// pads (in halves)
#define PADH  72    // [m/n][k] rows, BK=64 halves
#define PADNH 136   // [k][n] rows, 128 n-halves

// ============================================================================
// helpers
// ============================================================================
__device__ __forceinline__ uint32_t smem_u32(const void* p) {
    uint32_t a;
    asm("{ .reg .u64 t; cvta.to.shared.u64 t, %1; cvt.u32.u64 %0, t; }"
        : "=r"(a) : "l"(p));
    return a;
}

__device__ __forceinline__ void cp_async16(uint32_t dst, const void* src) {
    asm volatile("cp.async.cg.shared.global [%0], [%1], 16;" :: "r"(dst), "l"(src));
}

__device__ __forceinline__ void mma_f16(float* d, const uint32_t* a, const uint32_t* b) {
    asm volatile(
        "mma.sync.aligned.m16n8k16.row.col.f32.f16.f16.f32 "
        "{%0,%1,%2,%3}, {%4,%5,%6,%7}, {%8,%9}, {%0,%1,%2,%3};\n"
        : "+f"(d[0]), "+f"(d[1]), "+f"(d[2]), "+f"(d[3])
        : "r"(a[0]), "r"(a[1]), "r"(a[2]), "r"(a[3]), "r"(b[0]), "r"(b[1]));
}

// dual 16-bit load for [k][n] smem layouts: {B[k][n], B[k+1][n]}
__device__ __forceinline__ uint32_t ldpair(const __half* base, int k, int n, int strideH) {
    uint16_t lo = *(const uint16_t*)(base + (size_t)k * strideH + n);
    uint16_t hi = *(const uint16_t*)(base + (size_t)(k + 1) * strideH + n);
    return (uint32_t)lo | ((uint32_t)hi << 16);
}

// ============================================================================
// Kernel 0: fp32 -> fp16 conversion prepass
// ============================================================================
__global__ __launch_bounds__(256) void k_cvt_h(const float* __restrict__ src,
                                               __half* __restrict__ dst, int n4)
{
    int i = blockIdx.x * 256 + threadIdx.x;
    if (i >= n4) return;
    float4 v = ((const float4*)src)[i];
    __half2 h0 = __floats2half2_rn(v.x, v.y);
    __half2 h1 = __floats2half2_rn(v.z, v.w);
    ((uint2*)dst)[i] = make_uint2(*(uint32_t*)&h0, *(uint32_t*)&h1);
}

__global__ __launch_bounds__(256) void k_cvt4_h(
    const float* __restrict__ w0, const float* __restrict__ w1,
    const float* __restrict__ w2, const float* __restrict__ w3)
{
    const float* srcs[4] = { w0, w1, w2, w3 };
    const float* src = srcs[blockIdx.y];
    __half* dst = g_wh + (size_t)blockIdx.y * ND * ND;
    int i = blockIdx.x * 256 + threadIdx.x;
    float4 v = ((const float4*)src)[i];
    __half2 h0 = __floats2half2_rn(v.x, v.y);
    __half2 h1 = __floats2half2_rn(v.z, v.w);
    ((uint2*)dst)[i] = make_uint2(*(uint32_t*)&h0, *(uint32_t*)&h1);
}

// ============================================================================
// Kernel A: selector GEMM + sigmoid.  g_selh = sigmoid(x @ Ws^T + bs)
// fp16 mma. CTA 128x128, 8 warps (2x4), warp tile 64x32, BK=64 halves,
// 3-stage ring, 110.6 KB smem => 2 CTAs/SM.
// ============================================================================
#define SG_STG_H ((128 + 128) * PADH)
#define SG_SMEM (3 * SG_STG_H * 2)      // 110,592 B

__global__ __launch_bounds__(256, 2) void k_selgemm(const float* __restrict__ bs)
{
    extern __shared__ __half smh[];

    const int n0 = blockIdx.x * 128;
    const int m0 = blockIdx.y * 128;
    const __half* Wt = g_wh + (size_t)3 * ND * ND;

    const int tid = threadIdx.x;
    const int wid = tid >> 5, lane = tid & 31;
    const int wm = wid >> 2, wn = wid & 3;     // 2 x 4
    const int g = lane >> 2, tg = lane & 3;

    const uint32_t sb = smem_u32(smh);

    float acc[4][4][4];
    #pragma unroll
    for (int mt = 0; mt < 4; mt++)
        #pragma unroll
        for (int nt = 0; nt < 4; nt++)
            #pragma unroll
            for (int r = 0; r < 4; r++) acc[mt][nt][r] = 0.f;

    const int ldRow = tid >> 3;          // 0..31
    const int ldSeg = tid & 7;

    auto load_chunk = [&](int kc, int st) {
        const uint32_t s0 = sb + (uint32_t)(st * SG_STG_H) * 2u;
        const uint32_t bB = s0 + (uint32_t)(128 * PADH) * 2u;
        const __half* xs = g_xh + (size_t)m0 * 1024 + kc * 64;
        const __half* ws = Wt   + (size_t)n0 * 1024 + kc * 64;
        #pragma unroll
        for (int s = 0; s < 4; ++s) {
            int row = ldRow + s * 32;
            cp_async16(s0 + (uint32_t)(row * (PADH * 2) + ldSeg * 16),
                       xs + (size_t)row * 1024 + ldSeg * 8);
        }
        #pragma unroll
        for (int s = 0; s < 4; ++s) {
            int row = ldRow + s * 32;
            cp_async16(bB + (uint32_t)(row * (PADH * 2) + ldSeg * 16),
                       ws + (size_t)row * 1024 + ldSeg * 8);
        }
        asm volatile("cp.async.commit_group;" ::: "memory");
    };

    load_chunk(0, 0);
    load_chunk(1, 1);

    for (int it = 0; it < 16; ++it) {
        const int st = it % 3;
        if (it < 15) {
            asm volatile("cp.async.wait_group 1;" ::: "memory");
        } else {
            asm volatile("cp.async.wait_group 0;" ::: "memory");
        }
        __syncthreads();

        const __half* As = smh + st * SG_STG_H;
        const __half* Bs = As + 128 * PADH;

        #pragma unroll
        for (int ks = 0; ks < 4; ++ks) {
            const int kb = ks * 16;
            uint32_t afr[4][4];
            #pragma unroll
            for (int mt = 0; mt < 4; mt++) {
                const __half* ap = As + (wm * 64 + mt * 16 + g) * PADH + kb + 2 * tg;
                afr[mt][0] = *(const uint32_t*)ap;
                afr[mt][1] = *(const uint32_t*)(ap + 8 * PADH);
                afr[mt][2] = *(const uint32_t*)(ap + 8);
                afr[mt][3] = *(const uint32_t*)(ap + 8 * PADH + 8);
            }
            uint32_t bfr[4][2];
            #pragma unroll
            for (int nt = 0; nt < 4; nt++) {
                const __half* bp = Bs + (wn * 32 + nt * 8 + g) * PADH + kb + 2 * tg;
                bfr[nt][0] = *(const uint32_t*)bp;
                bfr[nt][1] = *(const uint32_t*)(bp + 8);
            }
            #pragma unroll
            for (int mt = 0; mt < 4; mt++)
                #pragma unroll
                for (int nt = 0; nt < 4; nt++)
                    mma_f16(acc[mt][nt], afr[mt], bfr[nt]);
        }

        if (it + 2 < 16) load_chunk(it + 2, (it + 2) % 3);
    }

    const int mBase = m0 + wm * 64;
    const int nBase = n0 + wn * 32;
    #pragma unroll
    for (int mt = 0; mt < 4; mt++) {
        #pragma unroll
        for (int nt = 0; nt < 4; nt++) {
            const int r0 = mBase + mt * 16 + g;
            const int c  = nBase + nt * 8 + 2 * tg;
            float2 bv = *(const float2*)(bs + c);
            float s00 = 1.f / (1.f + expf(-(acc[mt][nt][0] + bv.x)));
            float s01 = 1.f / (1.f + expf(-(acc[mt][nt][1] + bv.y)));
            float s10 = 1.f / (1.f + expf(-(acc[mt][nt][2] + bv.x)));
            float s11 = 1.f / (1.f + expf(-(acc[mt][nt][3] + bv.y)));
            *(__half2*)(g_selh + (size_t)r0 * 1024 + c)       = __floats2half2_rn(s00, s01);
            *(__half2*)(g_selh + (size_t)(r0 + 8) * 1024 + c) = __floats2half2_rn(s10, s11);
        }
    }
}

// ============================================================================
// Kernel B: class projections  g_c{a,b} = P @ W{a,b}^T + S*b{a,b} + b_emb[idx]
// ============================================================================
__global__ __launch_bounds__(256, 2) void k_cproj(
    const int* __restrict__ n_idx, const float* __restrict__ b_emb,
    const float* __restrict__ ba, const float* __restrict__ bb)
{
    extern __shared__ __half smh[];

    const int n0 = blockIdx.x * 128;
    const int m0 = blockIdx.y * 128;
    const int side = blockIdx.z;
    const __half* P   = side ? g_pb  : g_pa;
    const float* sums = side ? g_bfw : g_afw;
    const float* bias = side ? bb    : ba;
    __half*      out  = side ? g_cb  : g_ca;
    const __half* Wt  = g_wh + (size_t)(side ? 2 : 1) * ND * ND;

    const int tid = threadIdx.x;
    const int wid = tid >> 5, lane = tid & 31;
    const int wm = wid >> 2, wn = wid & 3;
    const int g = lane >> 2, tg = lane & 3;

    float acc[4][4][4];
    #pragma unroll
    for (int mt = 0; mt < 4; mt++)
        #pragma unroll
        for (int nt = 0; nt < 4; nt++)
            #pragma unroll
            for (int r = 0; r < 4; r++) acc[mt][nt][r] = 0.f;

    const uint32_t sb = smem_u32(smh);
    const int ldRow = tid >> 3;
    const int ldSeg = tid & 7;

    auto load_chunk = [&](int kc, int st) {
        const uint32_t s0 = sb + (uint32_t)(st * SG_STG_H) * 2u;
        const uint32_t bB = s0 + (uint32_t)(128 * PADH) * 2u;
        const __half* xs = P  + (size_t)m0 * 1024 + kc * 64;
        const __half* ws = Wt + (size_t)n0 * 1024 + kc * 64;
        #pragma unroll
        for (int s = 0; s < 4; ++s) {
            int row = ldRow + s * 32;
            cp_async16(s0 + (uint32_t)(row * (PADH * 2) + ldSeg * 16),
                       xs + (size_t)row * 1024 + ldSeg * 8);
        }
        #pragma unroll
        for (int s = 0; s < 4; ++s) {
            int row = ldRow + s * 32;
            cp_async16(bB + (uint32_t)(row * (PADH * 2) + ldSeg * 16),
                       ws + (size_t)row * 1024 + ldSeg * 8);
        }
        asm volatile("cp.async.commit_group;" ::: "memory");
    };

    load_chunk(0, 0);
    load_chunk(1, 1);

    for (int it = 0; it < 16; ++it) {
        const int st = it % 3;
        if (it < 15) {
            asm volatile("cp.async.wait_group 1;" ::: "memory");
        } else {
            asm volatile("cp.async.wait_group 0;" ::: "memory");
        }
        __syncthreads();

        const __half* As = smh + st * SG_STG_H;
        const __half* Bs = As + 128 * PADH;

        #pragma unroll
        for (int ks = 0; ks < 4; ++ks) {
            const int kb = ks * 16;
            uint32_t afr[4][4];
            #pragma unroll
            for (int mt = 0; mt < 4; mt++) {
                const __half* ap = As + (wm * 64 + mt * 16 + g) * PADH + kb + 2 * tg;
                afr[mt][0] = *(const uint32_t*)ap;
                afr[mt][1] = *(const uint32_t*)(ap + 8 * PADH);
                afr[mt][2] = *(const uint32_t*)(ap + 8);
                afr[mt][3] = *(const uint32_t*)(ap + 8 * PADH + 8);
            }
            uint32_t bfr[4][2];
            #pragma unroll
            for (int nt = 0; nt < 4; nt++) {
                const __half* bp = Bs + (wn * 32 + nt * 8 + g) * PADH + kb + 2 * tg;
                bfr[nt][0] = *(const uint32_t*)bp;
                bfr[nt][1] = *(const uint32_t*)(bp + 8);
            }
            #pragma unroll
            for (int mt = 0; mt < 4; mt++)
                #pragma unroll
                for (int nt = 0; nt < 4; nt++)
                    mma_f16(acc[mt][nt], afr[mt], bfr[nt]);
        }

        if (it + 2 < 16) load_chunk(it + 2, (it + 2) % 3);
    }

    const int mBase = m0 + wm * 64;
    const int nBase = n0 + wn * 32;
    #pragma unroll
    for (int mt = 0; mt < 4; mt++) {
        const int r0 = mBase + mt * 16 + g;
        const int b  = r0 >> 6;
        const int e0 = r0 & 63;
        float s0v = sums[b * 64 + e0];
        float s1v = sums[b * 64 + e0 + 8];
        float S0 = s0v / (s0v + 1e-9f);
        float S1 = s1v / (s1v + 1e-9f);
        const float* br0 = b_emb + (size_t)n_idx[b * 64 + e0] * 1024;
        const float* br1 = b_emb + (size_t)n_idx[b * 64 + e0 + 8] * 1024;
        #pragma unroll
        for (int nt = 0; nt < 4; nt++) {
            const int c = nBase + nt * 8 + 2 * tg;
            float2 bv = *(const float2*)(bias + c);
            float2 e0v = *(const float2*)(br0 + c);
            float2 e1v = *(const float2*)(br1 + c);
            *(__half2*)(out + (size_t)r0 * 1024 + c) = __floats2half2_rn(
                acc[mt][nt][0] + S0 * bv.x + e0v.x,
                acc[mt][nt][1] + S0 * bv.y + e0v.y);
            *(__half2*)(out + (size_t)(r0 + 8) * 1024 + c) = __floats2half2_rn(
                acc[mt][nt][2] + S1 * bv.x + e1v.x,
                acc[mt][nt][3] + S1 * bv.y + e1v.y);
        }
    }
}

// ============================================================================
// Kernel C: qw = q_emb @ Wk  (M=64(e), N=1024(d), K=1024(j)). B=[k][n]. grid(8).
// ============================================================================
#define QW_STG_H (64 * PADH + 64 * PADNH)
#define QW_SMEM (2 * QW_STG_H * 2)

__global__ __launch_bounds__(256) void k_qw()
{
    extern __shared__ __half smh[];
    const int n0 = blockIdx.x * 128;

    const int tid = threadIdx.x;
    const int wid = tid >> 5, lane = tid & 31;
    const int wm = wid >> 2, wn = wid & 3;
    const int g = lane >> 2, tg = lane & 3;

    const uint32_t sb = smem_u32(smh);

    float acc[2][4][4];
    #pragma unroll
    for (int mt = 0; mt < 2; mt++)
        #pragma unroll
        for (int nt = 0; nt < 4; nt++)
            #pragma unroll
            for (int r = 0; r < 4; r++) acc[mt][nt][r] = 0.f;

    const int aRow = tid >> 3;
    const int aSeg = tid & 7;

    auto load_chunk = [&](int kc, int st) {
        const uint32_t s0 = sb + (uint32_t)(st * QW_STG_H) * 2u;
        const uint32_t bB = s0 + (uint32_t)(64 * PADH) * 2u;
        cp_async16(s0 + (uint32_t)(aRow * (PADH * 2) + aSeg * 16),
                   g_qh + (size_t)aRow * 1024 + kc * 64 + aSeg * 8);
        cp_async16(s0 + (uint32_t)((aRow + 32) * (PADH * 2) + aSeg * 16),
                   g_qh + (size_t)(aRow + 32) * 1024 + kc * 64 + aSeg * 8);
        #pragma unroll
        for (int s = 0; s < 4; ++s) {
            int slot = tid + s * 256;
            int row = slot >> 4, seg = slot & 15;
            cp_async16(bB + (uint32_t)(row * (PADNH * 2) + seg * 16),
                       g_wh + (size_t)(kc * 64 + row) * 1024 + n0 + seg * 8);
        }
        asm volatile("cp.async.commit_group;" ::: "memory");
    };

    load_chunk(0, 0);

    for (int it = 0; it < 16; ++it) {
        const int buf = it & 1;
        if (it + 1 < 16) {
            load_chunk(it + 1, buf ^ 1);
            asm volatile("cp.async.wait_group 1;" ::: "memory");
        } else {
            asm volatile("cp.async.wait_group 0;" ::: "memory");
        }
        __syncthreads();

        const __half* As = smh + buf * QW_STG_H;
        const __half* Bs = As + 64 * PADH;

        #pragma unroll
        for (int ks = 0; ks < 4; ++ks) {
            const int kb = ks * 16;
            uint32_t afr[2][4];
            #pragma unroll
            for (int mt = 0; mt < 2; mt++) {
                const __half* ap = As + (wm * 32 + mt * 16 + g) * PADH + kb + 2 * tg;
                afr[mt][0] = *(const uint32_t*)ap;
                afr[mt][1] = *(const uint32_t*)(ap + 8 * PADH);
                afr[mt][2] = *(const uint32_t*)(ap + 8);
                afr[mt][3] = *(const uint32_t*)(ap + 8 * PADH + 8);
            }
            uint32_t bfr[4][2];
            #pragma unroll
            for (int nt = 0; nt < 4; nt++) {
                const int n = wn * 32 + nt * 8 + g;
                bfr[nt][0] = ldpair(Bs, kb + 2 * tg, n, PADNH);
                bfr[nt][1] = ldpair(Bs, kb + 2 * tg + 8, n, PADNH);
            }
            #pragma unroll
            for (int mt = 0; mt < 2; mt++)
                #pragma unroll
                for (int nt = 0; nt < 4; nt++)
                    mma_f16(acc[mt][nt], afr[mt], bfr[nt]);
        }
        __syncthreads();
    }

    #pragma unroll
    for (int mt = 0; mt < 2; mt++) {
        const int e0 = wm * 32 + mt * 16 + g;
        #pragma unroll
        for (int nt = 0; nt < 4; nt++) {
            const int c = n0 + wn * 32 + nt * 8 + 2 * tg;
            *(__half2*)(g_qwh + (size_t)e0 * 1024 + c) =
                __floats2half2_rn(acc[mt][nt][0], acc[mt][nt][1]);
            *(__half2*)(g_qwh + (size_t)(e0 + 8) * 1024 + c) =
                __floats2half2_rn(acc[mt][nt][2], acc[mt][nt][3]);
        }
    }
}

// Kernel C2: qb[e] = q_emb[e] . bk ; also zero fwsum accumulators
__global__ void k_qb(const float* __restrict__ q_emb, const float* __restrict__ bk)
{
    int t = threadIdx.x;                 // 1024 threads
    g_afw[t] = 0.f;
    g_bfw[t] = 0.f;
    if (t < 64) {
        float s = 0.f;
        const float* qr = q_emb + (size_t)t * 1024;
        for (int d = 0; d < 1024; ++d) s += qr[d] * bk[d];
        g_qbv[t] = s;
    }
}

// ============================================================================
// Kernel D: z[b,e,l] = (qwh[idx[b,e]] . xh[b,l] + qb[idx]) / 32
// Epilogue also computes fwsums (masked, atomicAdd) and bwsums (direct).
// ============================================================================
#define Z_STG_H ((64 + 128) * PADH)
#define Z_SMEM (2 * Z_STG_H * 2)

__global__ __launch_bounds__(256) void k_zgemm(const int* __restrict__ n_idx,
                                               const int* __restrict__ mask)
{
    extern __shared__ __half smh[];
    const int b  = blockIdx.y;
    const int l0 = blockIdx.x * 128;
    const int tid = threadIdx.x;
    const int wid = tid >> 5, lane = tid & 31;
    const int wm = wid >> 2, wn = wid & 3;
    const int g = lane >> 2, tg = lane & 3;

    const uint32_t sb = smem_u32(smh);

    float acc[2][4][4];
    #pragma unroll
    for (int mt = 0; mt < 2; mt++)
        #pragma unroll
        for (int nt = 0; nt < 4; nt++)
            #pragma unroll
            for (int r = 0; r < 4; r++) acc[mt][nt][r] = 0.f;

    const int aRow = tid >> 3;
    const int aSeg = tid & 7;
    const __half* aSrc0 = g_qwh + (size_t)n_idx[b * 64 + aRow] * 1024;
    const __half* aSrc1 = g_qwh + (size_t)n_idx[b * 64 + aRow + 32] * 1024;

    auto load_chunk = [&](int kc, int st) {
        const uint32_t s0 = sb + (uint32_t)(st * Z_STG_H) * 2u;
        const uint32_t bB = s0 + (uint32_t)(64 * PADH) * 2u;
        cp_async16(s0 + (uint32_t)(aRow * (PADH * 2) + aSeg * 16), aSrc0 + kc * 64 + aSeg * 8);
        cp_async16(s0 + (uint32_t)((aRow + 32) * (PADH * 2) + aSeg * 16), aSrc1 + kc * 64 + aSeg * 8);
        const __half* xs = g_xh + ((size_t)b * 2048 + l0) * 1024 + kc * 64;
        #pragma unroll
        for (int s = 0; s < 4; ++s) {
            int row = aRow + s * 32;
            cp_async16(bB + (uint32_t)(row * (PADH * 2) + aSeg * 16),
                       xs + (size_t)row * 1024 + aSeg * 8);
        }
        asm volatile("cp.async.commit_group;" ::: "memory");
    };

    load_chunk(0, 0);

    for (int it = 0; it < 16; ++it) {
        const int buf = it & 1;
        if (it + 1 < 16) {
            load_chunk(it + 1, buf ^ 1);
            asm volatile("cp.async.wait_group 1;" ::: "memory");
        } else {
            asm volatile("cp.async.wait_group 0;" ::: "memory");
        }
        __syncthreads();

        const __half* As = smh + buf * Z_STG_H;
        const __half* Bs = As + 64 * PADH;

        #pragma unroll
        for (int ks = 0; ks < 4; ++ks) {
            const int kb = ks * 16;
            uint32_t afr[2][4];
            #pragma unroll
            for (int mt = 0; mt < 2; mt++) {
                const __half* ap = As + (wm * 32 + mt * 16 + g) * PADH + kb + 2 * tg;
                afr[mt][0] = *(const uint32_t*)ap;
                afr[mt][1] = *(const uint32_t*)(ap + 8 * PADH);
                afr[mt][2] = *(const uint32_t*)(ap + 8);
                afr[mt][3] = *(const uint32_t*)(ap + 8 * PADH + 8);
            }
            uint32_t bfr[4][2];
            #pragma unroll
            for (int nt = 0; nt < 4; nt++) {
                const __half* bp = Bs + (wn * 32 + nt * 8 + g) * PADH + kb + 2 * tg;
                bfr[nt][0] = *(const uint32_t*)bp;
                bfr[nt][1] = *(const uint32_t*)(bp + 8);
            }
            #pragma unroll
            for (int mt = 0; mt < 2; mt++)
                #pragma unroll
                for (int nt = 0; nt < 4; nt++)
                    mma_f16(acc[mt][nt], afr[mt], bfr[nt]);
        }
        __syncthreads();
    }

    // ---- epilogue: z values + fused reductions ----
    float vz[2][4][4];
    #pragma unroll
    for (int mt = 0; mt < 2; mt++) {
        const int e = wm * 32 + mt * 16 + g;
        const float qb0 = g_qbv[n_idx[b * 64 + e]];
        const float qb1 = g_qbv[n_idx[b * 64 + e + 8]];
        #pragma unroll
        for (int nt = 0; nt < 4; nt++) {
            vz[mt][nt][0] = (acc[mt][nt][0] + qb0) * 0.03125f;
            vz[mt][nt][1] = (acc[mt][nt][1] + qb0) * 0.03125f;
            vz[mt][nt][2] = (acc[mt][nt][2] + qb1) * 0.03125f;
            vz[mt][nt][3] = (acc[mt][nt][3] + qb1) * 0.03125f;
            const int l = l0 + wn * 32 + nt * 8 + 2 * tg;
            *(float2*)(g_z + ((size_t)b * 64 + e) * 2048 + l) =
                make_float2(vz[mt][nt][0], vz[mt][nt][1]);
            *(float2*)(g_z + ((size_t)b * 64 + e + 8) * 2048 + l) =
                make_float2(vz[mt][nt][2], vz[mt][nt][3]);
        }
    }

    // load masks for this thread's 8 l positions
    int msk[4][2];
    #pragma unroll
    for (int nt = 0; nt < 4; nt++) {
        const int l = l0 + wn * 32 + nt * 8 + 2 * tg;
        msk[nt][0] = mask[b * 2048 + l];
        msk[nt][1] = mask[b * 2048 + l + 1];
    }

    // reduction buffers in smem (reuse tile memory; tile no longer needed)
    float* red = (float*)smh;   // [0:64) fwA, [64:128) fwB, [128:256) bwA, [256:384) bwB
    red[tid] = 0.f;                       // 0..255
    if (tid < 128) red[256 + tid] = 0.f;  // 256..383
    __syncthreads();

    // fw: masked relu sums over l; per (mt, row-half) reduce over nt,j then tg
    #pragma unroll
    for (int mt = 0; mt < 2; mt++) {
        #pragma unroll
        for (int rr = 0; rr < 2; rr++) {     // row 0 / +8
            float fa = 0.f, fb = 0.f;
            #pragma unroll
            for (int nt = 0; nt < 4; nt++) {
                #pragma unroll
                for (int j = 0; j < 2; j++) {
                    float v = vz[mt][nt][rr * 2 + j];
                    if (msk[nt][j]) { fa += fmaxf(v, 0.f); fb += fmaxf(-v, 0.f); }
                }
            }
            fa += __shfl_xor_sync(0xffffffffu, fa, 1);
            fa += __shfl_xor_sync(0xffffffffu, fa, 2);
            fb += __shfl_xor_sync(0xffffffffu, fb, 1);
            fb += __shfl_xor_sync(0xffffffffu, fb, 2);
            if (tg == 0) {
                const int e = wm * 32 + mt * 16 + g + rr * 8;
                atomicAdd(&red[e], fa);
                atomicAdd(&red[64 + e], fb);
            }
        }
    }

    // bw: unmasked relu sums over e; per (nt, j) reduce over mt,rr then g
    #pragma unroll
    for (int nt = 0; nt < 4; nt++) {
        #pragma unroll
        for (int j = 0; j < 2; j++) {
            float ba_ = 0.f, bb_ = 0.f;
            #pragma unroll
            for (int mt = 0; mt < 2; mt++) {
                #pragma unroll
                for (int rr = 0; rr < 2; rr++) {
                    float v = vz[mt][nt][rr * 2 + j];
                    ba_ += fmaxf(v, 0.f);
                    bb_ += fmaxf(-v, 0.f);
                }
            }
            ba_ += __shfl_xor_sync(0xffffffffu, ba_, 4);
            ba_ += __shfl_xor_sync(0xffffffffu, ba_, 8);
            ba_ += __shfl_xor_sync(0xffffffffu, ba_, 16);
            bb_ += __shfl_xor_sync(0xffffffffu, bb_, 4);
            bb_ += __shfl_xor_sync(0xffffffffu, bb_, 8);
            bb_ += __shfl_xor_sync(0xffffffffu, bb_, 16);
            if (g == 0) {
                const int li = wn * 32 + nt * 8 + 2 * tg + j;
                atomicAdd(&red[128 + li], ba_);
                atomicAdd(&red[256 + li], bb_);
            }
        }
    }
    __syncthreads();

    if (tid < 64) {
        atomicAdd(&g_afw[b * 64 + tid], red[tid]);
        atomicAdd(&g_bfw[b * 64 + tid], red[64 + tid]);
    } else if (tid < 192) {
        const int li = tid - 64;
        g_abw[b * 2048 + l0 + li] = red[128 + li];
        g_bbw[b * 2048 + l0 + li] = red[256 + li];
    }
}

// ============================================================================
// Kernel E: split-K P GEMM.  partials = A_{a,b} @ x over K half (no norm).
// grid (8, 16, 2): x=d-block, y=b, z=K half. M=64(e), N=128(d), K=1024.
// ============================================================================
#define PG_STG_H (2 * 64 * PADH + 64 * PADNH)
#define PG_SMEM (2 * PG_STG_H * 2)

__global__ __launch_bounds__(256) void k_pgemm2(const int* __restrict__ mask)
{
    extern __shared__ __half smh[];
    const int b  = blockIdx.y;
    const int n0 = blockIdx.x * 128;
    const int kh = blockIdx.z;                 // K half: 0 or 1
    float* outA = kh ? g_ppa1 : g_ppa0;
    float* outB = kh ? g_ppb1 : g_ppb0;

    const int tid = threadIdx.x;
    const int wid = tid >> 5, lane = tid & 31;
    const int wm = wid >> 2, wn = wid & 3;
    const int g = lane >> 2, tg = lane & 3;

    const uint32_t sb = smem_u32(smh);

    float accA[2][4][4], accB[2][4][4];
    #pragma unroll
    for (int mt = 0; mt < 2; mt++)
        #pragma unroll
        for (int nt = 0; nt < 4; nt++)
            #pragma unroll
            for (int r = 0; r < 4; r++) { accA[mt][nt][r] = 0.f; accB[mt][nt][r] = 0.f; }

    const int aE = tid >> 2;
    const int aC = (tid & 3) * 16;
    const float* zrow = g_z + ((size_t)b * 64 + aE) * 2048;
    const int* mrow = mask + b * 2048;
    const int kBase = kh * 1024;

    auto load_chunk = [&](int kc, int st) {
        __half* Aa = smh + st * PG_STG_H;
        __half* Ab = Aa + 64 * PADH;
        const uint32_t bB = sb + (uint32_t)(st * PG_STG_H + 2 * 64 * PADH) * 2u;
        const int kk = kBase + kc * 64;
        __half ha[16], hb[16];
        #pragma unroll
        for (int q = 0; q < 4; ++q) {
            float4 v = *(const float4*)(zrow + kk + aC + q * 4);
            int4 m = *(const int4*)(mrow + kk + aC + q * 4);
            float vv[4] = { v.x, v.y, v.z, v.w };
            int   mm[4] = { m.x, m.y, m.z, m.w };
            #pragma unroll
            for (int j = 0; j < 4; ++j) {
                ha[q * 4 + j] = __float2half_rn(mm[j] ? fmaxf(vv[j], 0.f) : 0.f);
                hb[q * 4 + j] = __float2half_rn(mm[j] ? fmaxf(-vv[j], 0.f) : 0.f);
            }
        }
        *(uint4*)(Aa + aE * PADH + aC)     = *(uint4*)ha;
        *(uint4*)(Aa + aE * PADH + aC + 8) = *(uint4*)(ha + 8);
        *(uint4*)(Ab + aE * PADH + aC)     = *(uint4*)hb;
        *(uint4*)(Ab + aE * PADH + aC + 8) = *(uint4*)(hb + 8);
        const __half* xs = g_xh + ((size_t)b * 2048 + kk) * 1024 + n0;
        #pragma unroll
        for (int s = 0; s < 4; ++s) {
            int slot = tid + s * 256;
            int row = slot >> 4, seg = slot & 15;
            cp_async16(bB + (uint32_t)(row * (PADNH * 2) + seg * 16),
                       xs + (size_t)row * 1024 + seg * 8);
        }
        asm volatile("cp.async.commit_group;" ::: "memory");
    };

    load_chunk(0, 0);

    for (int it = 0; it < 16; ++it) {
        const int buf = it & 1;
        if (it + 1 < 16) {
            load_chunk(it + 1, buf ^ 1);
            asm volatile("cp.async.wait_group 1;" ::: "memory");
        } else {
            asm volatile("cp.async.wait_group 0;" ::: "memory");
        }
        __syncthreads();

        const __half* Aa = smh + buf * PG_STG_H;
        const __half* Ab = Aa + 64 * PADH;
        const __half* Bs = Ab + 64 * PADH;

        #pragma unroll
        for (int ks = 0; ks < 4; ++ks) {
            const int kb = ks * 16;
            uint32_t afa[2][4], afb[2][4];
            #pragma unroll
            for (int mt = 0; mt < 2; mt++) {
                const __half* pa = Aa + (wm * 32 + mt * 16 + g) * PADH + kb + 2 * tg;
                const __half* pb = Ab + (wm * 32 + mt * 16 + g) * PADH + kb + 2 * tg;
                afa[mt][0] = *(const uint32_t*)pa;
                afa[mt][1] = *(const uint32_t*)(pa + 8 * PADH);
                afa[mt][2] = *(const uint32_t*)(pa + 8);
                afa[mt][3] = *(const uint32_t*)(pa + 8 * PADH + 8);
                afb[mt][0] = *(const uint32_t*)pb;
                afb[mt][1] = *(const uint32_t*)(pb + 8 * PADH);
                afb[mt][2] = *(const uint32_t*)(pb + 8);
                afb[mt][3] = *(const uint32_t*)(pb + 8 * PADH + 8);
            }
            uint32_t bfr[4][2];
            #pragma unroll
            for (int nt = 0; nt < 4; nt++) {
                const int n = wn * 32 + nt * 8 + g;
                bfr[nt][0] = ldpair(Bs, kb + 2 * tg, n, PADNH);
                bfr[nt][1] = ldpair(Bs, kb + 2 * tg + 8, n, PADNH);
            }
            #pragma unroll
            for (int mt = 0; mt < 2; mt++)
                #pragma unroll
                for (int nt = 0; nt < 4; nt++) {
                    mma_f16(accA[mt][nt], afa[mt], bfr[nt]);
                    mma_f16(accB[mt][nt], afb[mt], bfr[nt]);
                }
        }
        __syncthreads();
    }

    #pragma unroll
    for (int mt = 0; mt < 2; mt++) {
        const int e0 = wm * 32 + mt * 16 + g;
        #pragma unroll
        for (int nt = 0; nt < 4; nt++) {
            const int d = n0 + wn * 32 + nt * 8 + 2 * tg;
            *(float2*)(outA + ((size_t)b * 64 + e0) * 1024 + d) =
                make_float2(accA[mt][nt][0], accA[mt][nt][1]);
            *(float2*)(outA + ((size_t)b * 64 + e0 + 8) * 1024 + d) =
                make_float2(accA[mt][nt][2], accA[mt][nt][3]);
            *(float2*)(outB + ((size_t)b * 64 + e0) * 1024 + d) =
                make_float2(accB[mt][nt][0], accB[mt][nt][1]);
            *(float2*)(outB + ((size_t)b * 64 + e0 + 8) * 1024 + d) =
                make_float2(accB[mt][nt][2], accB[mt][nt][3]);
        }
    }
}

// Kernel E2: combine split-K partials + normalize -> fp16 g_pa/g_pb
__global__ __launch_bounds__(256) void k_psum()
{
    const int i = blockIdx.x * 256 + threadIdx.x;   // float4 index
    const int idx = i * 4;
    const int e = (idx >> 10) & 63;
    const int b = idx >> 16;
    const float ia = 1.f / (g_afw[b * 64 + e] + 1e-9f);
    const float ib = 1.f / (g_bfw[b * 64 + e] + 1e-9f);
    float4 a0 = ((const float4*)g_ppa0)[i];
    float4 a1 = ((const float4*)g_ppa1)[i];
    float4 b0 = ((const float4*)g_ppb0)[i];
    float4 b1 = ((const float4*)g_ppb1)[i];
    __half2 ha0 = __floats2half2_rn((a0.x + a1.x) * ia, (a0.y + a1.y) * ia);
    __half2 ha1 = __floats2half2_rn((a0.z + a1.z) * ia, (a0.w + a1.w) * ia);
    __half2 hb0 = __floats2half2_rn((b0.x + b1.x) * ib, (b0.y + b1.y) * ib);
    __half2 hb1 = __floats2half2_rn((b0.z + b1.z) * ib, (b0.w + b1.w) * ib);
    ((uint2*)g_pa)[i] = make_uint2(*(uint32_t*)&ha0, *(uint32_t*)&ha1);
    ((uint2*)g_pb)[i] = make_uint2(*(uint32_t*)&hb0, *(uint32_t*)&hb1);
}

// ============================================================================
// Kernel 6: final mix (fp16 mma), persistent over d.
// grid (32, 16) = (l-block of 64, b). A (z tile) built ONCE; loop 8 d-blocks
// with double-buffered ca/cb tiles.
// ============================================================================
#define FN_B_H (2 * 64 * PADNH)                       // one d-stage (Ba+Bb)
#define FN_SMEM ((2 * 64 * PADH + 2 * FN_B_H) * 2)    // A + 2 stages

__global__ __launch_bounds__(256) void k_final(float* __restrict__ out)
{
    extern __shared__ __half smh[];
    __half* Aa = smh;
    __half* Ab = Aa + 64 * PADH;
    __half* Bst = Ab + 64 * PADH;          // 2 stages of (Ba, Bb)

    const int b  = blockIdx.y;
    const int l0 = blockIdx.x * 64;
    const int tid = threadIdx.x;
    const int wid = tid >> 5, lane = tid & 31;
    const int wm = wid >> 2, wn = wid & 3;
    const int g = lane >> 2, tg = lane & 3;

    // ---- build A tiles from z (once) ----
    {
        const int e  = tid & 63;
        const int lc = (tid >> 6) * 16;
        const float* zp = g_z + ((size_t)b * 64 + e) * 2048 + l0 + lc;
        #pragma unroll
        for (int j = 0; j < 4; ++j) {
            float4 v = *(const float4*)(zp + j * 4);
            float vv[4] = { v.x, v.y, v.z, v.w };
            #pragma unroll
            for (int t = 0; t < 4; ++t) {
                int l = lc + j * 4 + t;
                Aa[l * PADH + e] = __float2half_rn(fmaxf(vv[t], 0.f));
                Ab[l * PADH + e] = __float2half_rn(fmaxf(-vv[t], 0.f));
            }
        }
    }

    const uint32_t bstU = smem_u32(Bst);
    const __half* caP = g_ca + ((size_t)b * 64) * 1024;
    const __half* cbP = g_cb + ((size_t)b * 64) * 1024;

    auto load_B = [&](int dblk, int st) {
        const uint32_t baU = bstU + (uint32_t)(st * FN_B_H) * 2u;
        const uint32_t bbU = baU + (uint32_t)(64 * PADNH) * 2u;
        const int d0 = dblk * 128;
        #pragma unroll
        for (int s = 0; s < 4; ++s) {
            int slot = tid + s * 256;
            int row = slot >> 4, seg = slot & 15;
            uint32_t doff = (uint32_t)(row * (PADNH * 2) + seg * 16);
            cp_async16(baU + doff, caP + (size_t)row * 1024 + d0 + seg * 8);
            cp_async16(bbU + doff, cbP + (size_t)row * 1024 + d0 + seg * 8);
        }
        asm volatile("cp.async.commit_group;" ::: "memory");
    };

    load_B(0, 0);

    // per-row normalizers (constant across d)
    const int l0r0 = l0 + wm * 32 + g;
    const float ia0 = 1.f / (g_abw[b * 2048 + l0r0] + 1e-9f);
    const float ib0 = 1.f / (g_bbw[b * 2048 + l0r0] + 1e-9f);
    const float ia1 = 1.f / (g_abw[b * 2048 + l0r0 + 8] + 1e-9f);
    const float ib1 = 1.f / (g_bbw[b * 2048 + l0r0 + 8] + 1e-9f);
    const float ia2 = 1.f / (g_abw[b * 2048 + l0r0 + 16] + 1e-9f);
    const float ib2 = 1.f / (g_bbw[b * 2048 + l0r0 + 16] + 1e-9f);
    const float ia3 = 1.f / (g_abw[b * 2048 + l0r0 + 24] + 1e-9f);
    const float ib3 = 1.f / (g_bbw[b * 2048 + l0r0 + 24] + 1e-9f);
    const float iaT[2][2] = { { ia0, ia1 }, { ia2, ia3 } };
    const float ibT[2][2] = { { ib0, ib1 }, { ib2, ib3 } };

    for (int dblk = 0; dblk < 8; ++dblk) {
        const int buf = dblk & 1;
        if (dblk + 1 < 8) {
            load_B(dblk + 1, buf ^ 1);
            asm volatile("cp.async.wait_group 1;" ::: "memory");
        } else {
            asm volatile("cp.async.wait_group 0;" ::: "memory");
        }
        __syncthreads();

        const __half* Ba = Bst + buf * FN_B_H;
        const __half* Bb = Ba + 64 * PADNH;

        float aca[2][4][4], acb[2][4][4];
        #pragma unroll
        for (int mt = 0; mt < 2; mt++)
            #pragma unroll
            for (int nt = 0; nt < 4; nt++)
                #pragma unroll
                for (int r = 0; r < 4; r++) { aca[mt][nt][r] = 0.f; acb[mt][nt][r] = 0.f; }

        #pragma unroll
        for (int ks = 0; ks < 4; ++ks) {
            const int kb = ks * 16;
            uint32_t afa[2][4], afb[2][4];
            #pragma unroll
            for (int mt = 0; mt < 2; mt++) {
                const __half* pa = Aa + (wm * 32 + mt * 16 + g) * PADH + kb + 2 * tg;
                const __half* pb = Ab + (wm * 32 + mt * 16 + g) * PADH + kb + 2 * tg;
                afa[mt][0] = *(const uint32_t*)pa;
                afa[mt][1] = *(const uint32_t*)(pa + 8 * PADH);
                afa[mt][2] = *(const uint32_t*)(pa + 8);
                afa[mt][3] = *(const uint32_t*)(pa + 8 * PADH + 8);
                afb[mt][0] = *(const uint32_t*)pb;
                afb[mt][1] = *(const uint32_t*)(pb + 8 * PADH);
                afb[mt][2] = *(const uint32_t*)(pb + 8);
                afb[mt][3] = *(const uint32_t*)(pb + 8 * PADH + 8);
            }
            uint32_t bfa[4][2], bfb[4][2];
            #pragma unroll
            for (int nt = 0; nt < 4; nt++) {
                const int n = wn * 32 + nt * 8 + g;
                bfa[nt][0] = ldpair(Ba, kb + 2 * tg, n, PADNH);
                bfa[nt][1] = ldpair(Ba, kb + 2 * tg + 8, n, PADNH);
                bfb[nt][0] = ldpair(Bb, kb + 2 * tg, n, PADNH);
                bfb[nt][1] = ldpair(Bb, kb + 2 * tg + 8, n, PADNH);
            }
            #pragma unroll
            for (int mt = 0; mt < 2; mt++)
                #pragma unroll
                for (int nt = 0; nt < 4; nt++) {
                    mma_f16(aca[mt][nt], afa[mt], bfa[nt]);
                    mma_f16(acb[mt][nt], afb[mt], bfb[nt]);
                }
        }
        __syncthreads();   // stage reuse at dblk+2; all warps done with buf

        // epilogue for this d block
        #pragma unroll
        for (int mt = 0; mt < 2; mt++) {
            const int l0r = l0 + wm * 32 + mt * 16 + g;
            const float va0 = iaT[mt][0], vb0 = ibT[mt][0];
            const float va1 = iaT[mt][1], vb1 = ibT[mt][1];
            #pragma unroll
            for (int nt = 0; nt < 4; nt++) {
                const int d = dblk * 128 + wn * 32 + nt * 8 + 2 * tg;
                float2 sg0 = __half22float2(*(const __half2*)(g_selh + ((size_t)b * 2048 + l0r) * 1024 + d));
                float2 sg1 = __half22float2(*(const __half2*)(g_selh + ((size_t)b * 2048 + l0r + 8) * 1024 + d));
                float2 o0 = make_float2(
                    sg0.x * (aca[mt][nt][0] * va0) + (1.f - sg0.x) * (acb[mt][nt][0] * vb0),
                    sg0.y * (aca[mt][nt][1] * va0) + (1.f - sg0.y) * (acb[mt][nt][1] * vb0));
                float2 o1 = make_float2(
                    sg1.x * (aca[mt][nt][2] * va1) + (1.f - sg1.x) * (acb[mt][nt][2] * vb1),
                    sg1.y * (aca[mt][nt][3] * va1) + (1.f - sg1.y) * (acb[mt][nt][3] * vb1));
                *(float2*)(out + ((size_t)b * 2048 + l0r) * 1024 + d)     = o0;
                *(float2*)(out + ((size_t)b * 2048 + l0r + 8) * 1024 + d) = o1;
            }
        }
    }
}

// ============================================================================
extern "C" void kernel_launch(void* const* d_in, const int* in_sizes, int n_in,
                              void* d_out, int out_size)
{
    const float* x     = (const float*)d_in[0];
    const int*   n_idx = (const int*)  d_in[1];
    const int*   mask  = (const int*)  d_in[2];
    const float* q_emb = (const float*)d_in[3];
    const float* b_emb = (const float*)d_in[4];
    const float* Wk    = (const float*)d_in[5];
    const float* bk    = (const float*)d_in[6];
    const float* Wa    = (const float*)d_in[7];
    const float* ba    = (const float*)d_in[8];
    const float* Wb    = (const float*)d_in[9];
    const float* bb    = (const float*)d_in[10];
    const float* Ws    = (const float*)d_in[11];
    const float* bs    = (const float*)d_in[12];
    float* out = (float*)d_out;

    __half *xh_p, *qh_p;
    cudaGetSymbolAddress((void**)&xh_p, g_xh);
    cudaGetSymbolAddress((void**)&qh_p, g_qh);

    cudaFuncSetAttribute(k_selgemm, cudaFuncAttributeMaxDynamicSharedMemorySize, SG_SMEM);
    cudaFuncSetAttribute(k_cproj,   cudaFuncAttributeMaxDynamicSharedMemorySize, SG_SMEM);
    cudaFuncSetAttribute(k_qw,      cudaFuncAttributeMaxDynamicSharedMemorySize, QW_SMEM);
    cudaFuncSetAttribute(k_zgemm,   cudaFuncAttributeMaxDynamicSharedMemorySize, Z_SMEM);
    cudaFuncSetAttribute(k_pgemm2,  cudaFuncAttributeMaxDynamicSharedMemorySize, PG_SMEM);
    cudaFuncSetAttribute(k_final,   cudaFuncAttributeMaxDynamicSharedMemorySize, FN_SMEM);

    // side stream + events (created once; per-call GPU work is identical)
    static cudaStream_t s2 = nullptr;
    static cudaEvent_t evFork = nullptr, evSel = nullptr;
    if (s2 == nullptr) {
        cudaStreamCreateWithFlags(&s2, cudaStreamNonBlocking);
        cudaEventCreateWithFlags(&evFork, cudaEventDisableTiming);
        cudaEventCreateWithFlags(&evSel, cudaEventDisableTiming);
    }

    // prepass on main (capture) stream
    k_cvt_h <<<(NB * NL * ND / 4 + 255) / 256, 256>>>(x, xh_p, NB * NL * ND / 4);
    k_cvt4_h<<<dim3(ND * ND / 4 / 256, 4),     256>>>(Wk, Wa, Wb, Ws);
    k_cvt_h <<<(NE * ND / 4 + 255) / 256,      256>>>(q_emb, qh_p, NE * ND / 4);

    // fork: selgemm on side stream, concurrent with the z-chain
    cudaEventRecord(evFork, 0);
    cudaStreamWaitEvent(s2, evFork, 0);
    k_selgemm<<<dim3(8, 256), 256, SG_SMEM, s2>>>(bs);
    cudaEventRecord(evSel, s2);

    // z-chain on main stream
    k_qw     <<<8,                256, QW_SMEM>>>();
    k_qb     <<<1,                1024>>>(q_emb, bk);
    k_zgemm  <<<dim3(16, 16),     256, Z_SMEM>>>(n_idx, mask);
    k_pgemm2 <<<dim3(8, 16, 2),   256, PG_SMEM>>>(mask);
    k_psum   <<<NB * NE * ND / 4 / 256, 256>>>();
    k_cproj  <<<dim3(8, 8, 2),    256, SG_SMEM>>>(n_idx, b_emb, ba, bb);

    // join: final needs selh + ca/cb + z + bw sums
    cudaStreamWaitEvent(0, evSel, 0);
    k_final  <<<dim3(32, 16),     256, FN_SMEM>>>(out);
}